// round 1
// baseline (speedup 1.0000x reference)
#include <cuda_runtime.h>
#include <math.h>

#define NB    8
#define CCH   640
#define HW    1024
#define NH    8
#define DH    80
#define DCTX  512
#define GRP   32
#define CPG   20      // channels per group
#define SKCTX 77

// ---------------- scratch (static device globals; no allocation allowed) ----------------
__device__ float g_gn   [NB*HW*CCH];      // groupnorm output, [n, p, c]
__device__ float g_xseq [NB*HW*CCH];      // running residual stream [n*p, c]
__device__ float g_t    [NB*HW*CCH];      // layernorm temp
__device__ float g_qkv  [NB*HW*3*CCH];    // qkv for self-attn / q for cross-attn
__device__ float g_attn [NB*HW*CCH];      // attention output (pre out-proj)
__device__ float g_kctx [NB*SKCTX*CCH];
__device__ float g_vctx [NB*SKCTX*CCH];
__device__ float g_ff   [NB*HW*8*CCH];    // lin1 out (5120 wide)
__device__ float g_ffg  [NB*HW*4*CCH];    // geglu out (2560 wide)
__device__ float g_tmp  [NB*HW*CCH];      // final conv out, [n*p, c]
__device__ float g_gnstat[NB*GRP*2];      // mean, rstd per (n, group)

// ---------------- GroupNorm: stats ----------------
__global__ void gn_stats(const float* __restrict__ x) {
    int ng = blockIdx.x;               // n*GRP + g
    int n = ng / GRP, g = ng % GRP;
    const float* base = x + ((size_t)n*CCH + (size_t)g*CPG) * HW;
    float s = 0.f, s2 = 0.f;
    for (int i = threadIdx.x; i < CPG*HW; i += 256) {
        float v = base[i];
        s += v; s2 += v*v;
    }
    __shared__ float rs[256], rq[256];
    rs[threadIdx.x] = s; rq[threadIdx.x] = s2;
    __syncthreads();
    for (int o = 128; o > 0; o >>= 1) {
        if (threadIdx.x < o) { rs[threadIdx.x] += rs[threadIdx.x+o]; rq[threadIdx.x] += rq[threadIdx.x+o]; }
        __syncthreads();
    }
    if (threadIdx.x == 0) {
        float inv_n = 1.f / (float)(CPG*HW);
        float mu  = rs[0] * inv_n;
        float var = rq[0] * inv_n - mu*mu;
        g_gnstat[ng*2]   = mu;
        g_gnstat[ng*2+1] = rsqrtf(var + 1e-6f);
    }
}

// ---------------- GroupNorm apply + NCHW -> [n, p, c] transpose ----------------
__global__ void gn_apply(const float* __restrict__ x,
                         const float* __restrict__ s, const float* __restrict__ b) {
    int idx = blockIdx.x * 256 + threadIdx.x;
    if (idx >= NB*CCH*HW) return;
    int p = idx % HW;
    int c = (idx / HW) % CCH;
    int n = idx / (HW*CCH);
    int ng = n*GRP + c / CPG;
    float mu = g_gnstat[ng*2], is = g_gnstat[ng*2+1];
    float v = (x[idx] - mu) * is * s[c] + b[c];
    g_gn[((size_t)n*HW + p)*CCH + c] = v;
}

// ---------------- LayerNorm over last dim (CCH) ----------------
__global__ void layernorm(const float* __restrict__ in,
                          const float* __restrict__ s, const float* __restrict__ b,
                          float* __restrict__ out) {
    int row = blockIdx.x;
    const float* r = in + (size_t)row * CCH;
    float sum = 0.f, sq = 0.f;
    for (int i = threadIdx.x; i < CCH; i += 256) {
        float v = r[i]; sum += v; sq += v*v;
    }
    __shared__ float rs[256], rq[256];
    rs[threadIdx.x] = sum; rq[threadIdx.x] = sq;
    __syncthreads();
    for (int o = 128; o > 0; o >>= 1) {
        if (threadIdx.x < o) { rs[threadIdx.x] += rs[threadIdx.x+o]; rq[threadIdx.x] += rq[threadIdx.x+o]; }
        __syncthreads();
    }
    float mu  = rs[0] / (float)CCH;
    float inv = rsqrtf(rq[0] / (float)CCH - mu*mu + 1e-5f);
    for (int i = threadIdx.x; i < CCH; i += 256)
        out[(size_t)row*CCH + i] = (r[i] - mu) * inv * s[i] + b[i];
}

// ---------------- fp32 GEMM: C[M,N] = A[M,K] @ B (+bias) (+residual) ----------------
// TRANS_B=false: B is [K,N] row-major.  TRANS_B=true: B stored [N,K] (weights as (out,in)).
template<bool TRANS_B>
__global__ void gemm(const float* __restrict__ A, const float* __restrict__ B,
                     const float* __restrict__ bias, const float* __restrict__ res,
                     float* __restrict__ C, int M, int N, int K) {
    __shared__ float As[16][64];
    __shared__ float Bs[16][64];
    int tid = threadIdx.x;
    int tx = tid & 15, ty = tid >> 4;
    int bm = blockIdx.y * 64, bn = blockIdx.x * 64;

    float acc[4][4] = {};

    for (int k0 = 0; k0 < K; k0 += 16) {
        #pragma unroll
        for (int i = 0; i < 4; i++) {
            int t = tid + i*256;
            int m = t >> 4, k = t & 15;
            int gm = bm + m, gk = k0 + k;
            As[k][m] = (gm < M && gk < K) ? A[(size_t)gm*K + gk] : 0.f;
        }
        #pragma unroll
        for (int i = 0; i < 4; i++) {
            int t = tid + i*256;
            int k = t >> 6, n = t & 63;
            int gn = bn + n, gk = k0 + k;
            float v = 0.f;
            if (gn < N && gk < K)
                v = TRANS_B ? B[(size_t)gn*K + gk] : B[(size_t)gk*N + gn];
            Bs[k][n] = v;
        }
        __syncthreads();
        #pragma unroll
        for (int k = 0; k < 16; k++) {
            float4 a  = *(const float4*)&As[k][ty*4];
            float4 bv = *(const float4*)&Bs[k][tx*4];
            float av[4] = {a.x, a.y, a.z, a.w};
            float bb[4] = {bv.x, bv.y, bv.z, bv.w};
            #pragma unroll
            for (int i = 0; i < 4; i++)
                #pragma unroll
                for (int j = 0; j < 4; j++)
                    acc[i][j] += av[i] * bb[j];
        }
        __syncthreads();
    }

    #pragma unroll
    for (int i = 0; i < 4; i++) {
        int gm = bm + ty*4 + i;
        if (gm >= M) continue;
        #pragma unroll
        for (int j = 0; j < 4; j++) {
            int gn = bn + tx*4 + j;
            if (gn >= N) continue;
            float v = acc[i][j];
            if (bias) v += bias[gn];
            if (res)  v += res[(size_t)gm*N + gn];
            C[(size_t)gm*N + gn] = v;
        }
    }
}

// ---------------- attention: one block per (b, h, q) row ----------------
// Q rows: Q[(b*HW + q)*qs + h*DH + d]; K rows over SK; V same; O[(b*HW+q)*os + h*DH + d]
__global__ void attention(const float* __restrict__ Q, const float* __restrict__ Kp,
                          const float* __restrict__ V, float* __restrict__ O,
                          int SK, int qs, int ks, int vs, int os) {
    int q = blockIdx.x % HW;
    int h = (blockIdx.x / HW) % NH;
    int b = blockIdx.x / (HW*NH);
    int tid = threadIdx.x;

    __shared__ float sq[DH];
    __shared__ float sp[HW];     // scores (max SK = 1024)
    __shared__ float red[128];

    const float scale = rsqrtf((float)DH);
    const float* qrow = Q + ((size_t)(b*HW + q))*qs + h*DH;
    if (tid < DH) sq[tid] = qrow[tid];
    __syncthreads();

    float lmax = -1e30f;
    for (int j = tid; j < SK; j += 128) {
        const float* krow = Kp + ((size_t)(b*SK + j))*ks + h*DH;
        float s = 0.f;
        #pragma unroll 16
        for (int d = 0; d < DH; d++) s += sq[d] * krow[d];
        s *= scale;
        sp[j] = s;
        lmax = fmaxf(lmax, s);
    }
    red[tid] = lmax; __syncthreads();
    for (int o = 64; o > 0; o >>= 1) {
        if (tid < o) red[tid] = fmaxf(red[tid], red[tid+o]);
        __syncthreads();
    }
    float m = red[0];
    __syncthreads();

    float lsum = 0.f;
    for (int j = tid; j < SK; j += 128) {
        float e = expf(sp[j] - m);
        sp[j] = e;
        lsum += e;
    }
    red[tid] = lsum; __syncthreads();
    for (int o = 64; o > 0; o >>= 1) {
        if (tid < o) red[tid] += red[tid+o];
        __syncthreads();
    }
    float inv = 1.f / red[0];
    __syncthreads();

    for (int d = tid; d < DH; d += 128) {
        float o = 0.f;
        for (int j = 0; j < SK; j++)
            o += sp[j] * V[((size_t)(b*SK + j))*vs + h*DH + d];
        O[((size_t)(b*HW + q))*os + h*DH + d] = o * inv;
    }
}

// ---------------- GeGLU: a * gelu_exact(gate) ----------------
__global__ void geglu(const float* __restrict__ ff, float* __restrict__ out) {
    int idx = blockIdx.x * 256 + threadIdx.x;
    if (idx >= NB*HW*4*CCH) return;
    int m = idx / (4*CCH);
    int j = idx % (4*CCH);
    float a = ff[(size_t)m*8*CCH + j];
    float g = ff[(size_t)m*8*CCH + 4*CCH + j];
    float ge = 0.5f * g * (1.f + erff(g * 0.70710678118654752f));
    out[idx] = a * ge;
}

// ---------------- final: [n,p,c] -> [n,c,p] + residue_long ----------------
__global__ void final_add(const float* __restrict__ tmp, const float* __restrict__ xin,
                          float* __restrict__ out) {
    int idx = blockIdx.x * 256 + threadIdx.x;
    if (idx >= NB*CCH*HW) return;
    int p = idx % HW;
    int c = (idx / HW) % CCH;
    int n = idx / (HW*CCH);
    out[idx] = tmp[((size_t)n*HW + p)*CCH + c] + xin[idx];
}

// ---------------- host launch ----------------
extern "C" void kernel_launch(void* const* d_in, const int* in_sizes, int n_in,
                              void* d_out, int out_size) {
    const float* x        = (const float*)d_in[0];
    const float* context  = (const float*)d_in[1];
    const float* gn_s     = (const float*)d_in[2];
    const float* gn_b     = (const float*)d_in[3];
    const float* conv1_w  = (const float*)d_in[4];
    const float* conv1_b  = (const float*)d_in[5];
    const float* ln1_s    = (const float*)d_in[6];
    const float* ln1_b    = (const float*)d_in[7];
    const float* sa_in_w  = (const float*)d_in[8];
    const float* sa_out_w = (const float*)d_in[9];
    const float* sa_out_b = (const float*)d_in[10];
    const float* ln2_s    = (const float*)d_in[11];
    const float* ln2_b    = (const float*)d_in[12];
    const float* ca_q_w   = (const float*)d_in[13];
    const float* ca_k_w   = (const float*)d_in[14];
    const float* ca_v_w   = (const float*)d_in[15];
    const float* ca_out_w = (const float*)d_in[16];
    const float* ca_out_b = (const float*)d_in[17];
    const float* ln3_s    = (const float*)d_in[18];
    const float* ln3_b    = (const float*)d_in[19];
    const float* lin1_w   = (const float*)d_in[20];
    const float* lin1_b   = (const float*)d_in[21];
    const float* lin2_w   = (const float*)d_in[22];
    const float* lin2_b   = (const float*)d_in[23];
    const float* co_w     = (const float*)d_in[24];
    const float* co_b     = (const float*)d_in[25];
    float* out = (float*)d_out;

    float *gn, *xseq, *t, *qkv, *attn, *kctx, *vctx, *ff, *ffg, *tmp;
    cudaGetSymbolAddress((void**)&gn,   g_gn);
    cudaGetSymbolAddress((void**)&xseq, g_xseq);
    cudaGetSymbolAddress((void**)&t,    g_t);
    cudaGetSymbolAddress((void**)&qkv,  g_qkv);
    cudaGetSymbolAddress((void**)&attn, g_attn);
    cudaGetSymbolAddress((void**)&kctx, g_kctx);
    cudaGetSymbolAddress((void**)&vctx, g_vctx);
    cudaGetSymbolAddress((void**)&ff,   g_ff);
    cudaGetSymbolAddress((void**)&ffg,  g_ffg);
    cudaGetSymbolAddress((void**)&tmp,  g_tmp);

    const int M = NB * HW;   // 8192
    dim3 blk(256);

    // 1. GroupNorm + transpose to [n, p, c]
    gn_stats<<<NB*GRP, 256>>>(x);
    gn_apply<<<(NB*CCH*HW + 255)/256, 256>>>(x, gn_s, gn_b);

    // 2. conv1 (1x1): xseq = gn @ conv1_w^T + conv1_b
    gemm<true><<<dim3(CCH/64, M/64), blk>>>(gn, conv1_w, conv1_b, nullptr, xseq, M, CCH, CCH);

    // 3. self-attention
    layernorm<<<M, 256>>>(xseq, ln1_s, ln1_b, t);
    gemm<false><<<dim3(3*CCH/64, M/64), blk>>>(t, sa_in_w, nullptr, nullptr, qkv, M, 3*CCH, CCH);
    attention<<<NB*NH*HW, 128>>>(qkv, qkv + CCH, qkv + 2*CCH, attn,
                                 HW, 3*CCH, 3*CCH, 3*CCH, CCH);
    gemm<false><<<dim3(CCH/64, M/64), blk>>>(attn, sa_out_w, sa_out_b, xseq, xseq, M, CCH, CCH);

    // 4. cross-attention
    layernorm<<<M, 256>>>(xseq, ln2_s, ln2_b, t);
    gemm<false><<<dim3(CCH/64, M/64), blk>>>(t, ca_q_w, nullptr, nullptr, qkv, M, CCH, CCH);
    gemm<false><<<dim3(CCH/64, (NB*SKCTX + 63)/64), blk>>>(context, ca_k_w, nullptr, nullptr, kctx, NB*SKCTX, CCH, DCTX);
    gemm<false><<<dim3(CCH/64, (NB*SKCTX + 63)/64), blk>>>(context, ca_v_w, nullptr, nullptr, vctx, NB*SKCTX, CCH, DCTX);
    attention<<<NB*NH*HW, 128>>>(qkv, kctx, vctx, attn,
                                 SKCTX, CCH, CCH, CCH, CCH);
    gemm<false><<<dim3(CCH/64, M/64), blk>>>(attn, ca_out_w, ca_out_b, xseq, xseq, M, CCH, CCH);

    // 5. GeGLU FFN
    layernorm<<<M, 256>>>(xseq, ln3_s, ln3_b, t);
    gemm<false><<<dim3(8*CCH/64, M/64), blk>>>(t, lin1_w, lin1_b, nullptr, ff, M, 8*CCH, CCH);
    geglu<<<(NB*HW*4*CCH + 255)/256, 256>>>(ff, ffg);
    gemm<false><<<dim3(CCH/64, M/64), blk>>>(ffg, lin2_w, lin2_b, xseq, xseq, M, CCH, 4*CCH);

    // 6. final 1x1 conv + long residual, back to NCHW
    gemm<true><<<dim3(CCH/64, M/64), blk>>>(xseq, co_w, co_b, nullptr, tmp, M, CCH, CCH);
    final_add<<<(NB*CCH*HW + 255)/256, 256>>>(tmp, x, out);
}

// round 2
// speedup vs baseline: 6.5662x; 6.5662x over previous
#include <cuda_runtime.h>
#include <math.h>
#include <stdint.h>

#define NB    8
#define CCH   640
#define HW    1024
#define NH    8
#define DH    80
#define DCTX  512
#define GRP   32
#define CPG   20
#define SKCTX 77

// ---------------- scratch ----------------
__device__ float g_gn    [NB*HW*CCH];
__device__ float g_xseq  [NB*HW*CCH];
__device__ float g_t     [NB*HW*CCH];
__device__ float g_qkv   [NB*HW*3*CCH];
__device__ float g_attn  [NB*HW*CCH];
__device__ float g_kctx  [NB*SKCTX*CCH];
__device__ float g_vctx  [NB*SKCTX*CCH];
__device__ float g_ff    [NB*HW*8*CCH];
__device__ float g_ffg   [NB*HW*4*CCH];
__device__ float g_tmp   [NB*HW*CCH];
__device__ float g_scores[NB*NH*HW*HW];     // 256 MB self-attn scores
__device__ float g_gnstat[NB*GRP*2];

// ---------------- GroupNorm stats ----------------
__global__ void gn_stats(const float* __restrict__ x) {
    int ng = blockIdx.x;
    int n = ng / GRP, g = ng % GRP;
    const float* base = x + ((size_t)n*CCH + (size_t)g*CPG) * HW;
    float s = 0.f, s2 = 0.f;
    for (int i = threadIdx.x; i < CPG*HW; i += 256) {
        float v = base[i]; s += v; s2 += v*v;
    }
    __shared__ float rs[256], rq[256];
    rs[threadIdx.x] = s; rq[threadIdx.x] = s2;
    __syncthreads();
    for (int o = 128; o > 0; o >>= 1) {
        if (threadIdx.x < o) { rs[threadIdx.x] += rs[threadIdx.x+o]; rq[threadIdx.x] += rq[threadIdx.x+o]; }
        __syncthreads();
    }
    if (threadIdx.x == 0) {
        float inv_n = 1.f / (float)(CPG*HW);
        float mu  = rs[0] * inv_n;
        float var = rq[0] * inv_n - mu*mu;
        g_gnstat[ng*2]   = mu;
        g_gnstat[ng*2+1] = rsqrtf(var + 1e-6f);
    }
}

__global__ void gn_apply(const float* __restrict__ x,
                         const float* __restrict__ s, const float* __restrict__ b) {
    int idx = blockIdx.x * 256 + threadIdx.x;
    if (idx >= NB*CCH*HW) return;
    int p = idx % HW;
    int c = (idx / HW) % CCH;
    int n = idx / (HW*CCH);
    int ng = n*GRP + c / CPG;
    float mu = g_gnstat[ng*2], is = g_gnstat[ng*2+1];
    g_gn[((size_t)n*HW + p)*CCH + c] = (x[idx] - mu) * is * s[c] + b[c];
}

// ---------------- LayerNorm ----------------
__global__ void layernorm(const float* __restrict__ in,
                          const float* __restrict__ s, const float* __restrict__ b,
                          float* __restrict__ out) {
    int row = blockIdx.x;
    const float* r = in + (size_t)row * CCH;
    float sum = 0.f, sq = 0.f;
    for (int i = threadIdx.x; i < CCH; i += 256) {
        float v = r[i]; sum += v; sq += v*v;
    }
    __shared__ float rs[256], rq[256];
    rs[threadIdx.x] = sum; rq[threadIdx.x] = sq;
    __syncthreads();
    for (int o = 128; o > 0; o >>= 1) {
        if (threadIdx.x < o) { rs[threadIdx.x] += rs[threadIdx.x+o]; rq[threadIdx.x] += rq[threadIdx.x+o]; }
        __syncthreads();
    }
    float mu  = rs[0] / (float)CCH;
    float inv = rsqrtf(rq[0] / (float)CCH - mu*mu + 1e-5f);
    for (int i = threadIdx.x; i < CCH; i += 256)
        out[(size_t)row*CCH + i] = (r[i] - mu) * inv * s[i] + b[i];
}

// ---------------- tf32 helpers ----------------
__device__ __forceinline__ uint32_t f2tf(float f) {
    uint32_t u; asm("cvt.rna.tf32.f32 %0, %1;" : "=r"(u) : "f"(f)); return u;
}
__device__ __forceinline__ void mma8(float c[4], uint32_t a0, uint32_t a1, uint32_t a2, uint32_t a3,
                                     uint32_t b0, uint32_t b1) {
    asm volatile("mma.sync.aligned.m16n8k8.row.col.f32.tf32.tf32.f32 "
        "{%0,%1,%2,%3}, {%4,%5,%6,%7}, {%8,%9}, {%0,%1,%2,%3};"
        : "+f"(c[0]), "+f"(c[1]), "+f"(c[2]), "+f"(c[3])
        : "r"(a0), "r"(a1), "r"(a2), "r"(a3), "r"(b0), "r"(b1));
}

// ---------------- tf32 GEMM, 128x128x16 block tile, batched ----------------
// C[z][m,n] = A[z][m,:K] @ B  (+bias) (+res)
// TRANS_B: B stored [N,K] (row n holds K values), else [K,N].
#define SMS 136
template<bool TRANS_B>
__global__ __launch_bounds__(256)
void gemm_tf32(const float* __restrict__ A, int lda, long sAb, long sAh,
               const float* __restrict__ B, int ldb, long sBb, long sBh,
               const float* __restrict__ bias,
               const float* __restrict__ res,
               float* __restrict__ C, int ldc, long sCb, long sCh,
               int M, int N, int K) {
    __shared__ uint32_t As[16*SMS];
    __shared__ uint32_t Bs[16*SMS];

    int tid = threadIdx.x;
    int lane = tid & 31, warp = tid >> 5;
    int wm = (warp >> 2) * 64, wn = (warp & 3) * 32;
    int bm = blockIdx.y * 128, bn = blockIdx.x * 128;
    int zb = blockIdx.z >> 3, zh = blockIdx.z & 7;   // only used when batched

    const float* Ab = A + (long)zb*sAb + (long)zh*sAh;
    const float* Bb = B + (long)zb*sBb + (long)zh*sBh;
    const float* Rb = res ? res + (long)zb*sCb + (long)zh*sCh : nullptr;
    float*       Cb = C + (long)zb*sCb + (long)zh*sCh;

    float acc[4][4][4];
    #pragma unroll
    for (int i = 0; i < 4; i++)
        #pragma unroll
        for (int j = 0; j < 4; j++)
            #pragma unroll
            for (int r = 0; r < 4; r++) acc[i][j][r] = 0.f;

    const int ar = tid >> 2, ac4 = (tid & 3) << 2;     // A/B-trans loader coords
    const int bk = tid >> 5, bn4 = (tid & 31) << 2;    // B-notrans loader coords

    for (int k0 = 0; k0 < K; k0 += 16) {
        // --- stage A (128 x 16) ---
        #pragma unroll
        for (int rr = ar; rr < 128; rr += 64) {
            int gm = bm + rr;
            float4 v = make_float4(0.f,0.f,0.f,0.f);
            if (gm < M) v = *(const float4*)(Ab + (size_t)gm*lda + k0 + ac4);
            As[(ac4+0)*SMS + rr] = f2tf(v.x);
            As[(ac4+1)*SMS + rr] = f2tf(v.y);
            As[(ac4+2)*SMS + rr] = f2tf(v.z);
            As[(ac4+3)*SMS + rr] = f2tf(v.w);
        }
        // --- stage B (16 x 128 as [k][n]) ---
        if (TRANS_B) {
            #pragma unroll
            for (int rr = ar; rr < 128; rr += 64) {
                int gn = bn + rr;
                float4 v = make_float4(0.f,0.f,0.f,0.f);
                if (gn < N) v = *(const float4*)(Bb + (size_t)gn*ldb + k0 + ac4);
                Bs[(ac4+0)*SMS + rr] = f2tf(v.x);
                Bs[(ac4+1)*SMS + rr] = f2tf(v.y);
                Bs[(ac4+2)*SMS + rr] = f2tf(v.z);
                Bs[(ac4+3)*SMS + rr] = f2tf(v.w);
            }
        } else {
            #pragma unroll
            for (int kk = bk; kk < 16; kk += 8) {
                int gn = bn + bn4;
                float4 v = make_float4(0.f,0.f,0.f,0.f);
                if (gn + 3 < N) v = *(const float4*)(Bb + (size_t)(k0+kk)*ldb + gn);
                Bs[kk*SMS + bn4 + 0] = f2tf(v.x);
                Bs[kk*SMS + bn4 + 1] = f2tf(v.y);
                Bs[kk*SMS + bn4 + 2] = f2tf(v.z);
                Bs[kk*SMS + bn4 + 3] = f2tf(v.w);
            }
        }
        __syncthreads();

        #pragma unroll
        for (int kk = 0; kk < 16; kk += 8) {
            int kb = kk + (lane & 3);
            uint32_t af[4][4], bf[4][2];
            #pragma unroll
            for (int mi = 0; mi < 4; mi++) {
                int m0 = wm + mi*16 + (lane >> 2);
                af[mi][0] = As[kb*SMS + m0];
                af[mi][1] = As[kb*SMS + m0 + 8];
                af[mi][2] = As[(kb+4)*SMS + m0];
                af[mi][3] = As[(kb+4)*SMS + m0 + 8];
            }
            #pragma unroll
            for (int ni = 0; ni < 4; ni++) {
                int n0 = wn + ni*8 + (lane >> 2);
                bf[ni][0] = Bs[kb*SMS + n0];
                bf[ni][1] = Bs[(kb+4)*SMS + n0];
            }
            #pragma unroll
            for (int mi = 0; mi < 4; mi++)
                #pragma unroll
                for (int ni = 0; ni < 4; ni++)
                    mma8(acc[mi][ni], af[mi][0], af[mi][1], af[mi][2], af[mi][3],
                         bf[ni][0], bf[ni][1]);
        }
        __syncthreads();
    }

    // --- epilogue ---
    #pragma unroll
    for (int mi = 0; mi < 4; mi++) {
        #pragma unroll
        for (int ni = 0; ni < 4; ni++) {
            int row0 = bm + wm + mi*16 + (lane >> 2);
            int col0 = bn + wn + ni*8 + (lane & 3)*2;
            #pragma unroll
            for (int r = 0; r < 4; r++) {
                int row = row0 + (r >> 1)*8;
                int col = col0 + (r & 1);
                if (row < M && col < N) {
                    float v = acc[mi][ni][r];
                    if (bias) v += bias[col];
                    if (Rb)   v += Rb[(size_t)row*ldc + col];
                    Cb[(size_t)row*ldc + col] = v;
                }
            }
        }
    }
}

// ---------------- softmax over contiguous rows of length SK (scaled) ----------------
__global__ void softmax_rows(float* __restrict__ S, int SK, float scale) {
    int row = blockIdx.x;
    float* r = S + (size_t)row * SK;
    int tid = threadIdx.x;
    float lmax = -1e30f;
    for (int i = tid; i < SK; i += 256) lmax = fmaxf(lmax, r[i]);
    __shared__ float red[256];
    red[tid] = lmax; __syncthreads();
    for (int o = 128; o > 0; o >>= 1) {
        if (tid < o) red[tid] = fmaxf(red[tid], red[tid+o]);
        __syncthreads();
    }
    float m = red[0];
    __syncthreads();
    float lsum = 0.f;
    for (int i = tid; i < SK; i += 256) {
        float e = __expf((r[i] - m) * scale);
        r[i] = e; lsum += e;
    }
    red[tid] = lsum; __syncthreads();
    for (int o = 128; o > 0; o >>= 1) {
        if (tid < o) red[tid] += red[tid+o];
        __syncthreads();
    }
    float inv = 1.f / red[0];
    __syncthreads();
    for (int i = tid; i < SK; i += 256) r[i] *= inv;
}

// ---------------- small-SK attention (cross-attn, SK=77) ----------------
__global__ void attention(const float* __restrict__ Q, const float* __restrict__ Kp,
                          const float* __restrict__ V, float* __restrict__ O,
                          int SK, int qs, int ks, int vs, int os) {
    int q = blockIdx.x % HW;
    int h = (blockIdx.x / HW) % NH;
    int b = blockIdx.x / (HW*NH);
    int tid = threadIdx.x;

    __shared__ float sq[DH];
    __shared__ float sp[128];
    __shared__ float red[128];

    const float scale = rsqrtf((float)DH);
    const float* qrow = Q + ((size_t)(b*HW + q))*qs + h*DH;
    if (tid < DH) sq[tid] = qrow[tid];
    __syncthreads();

    float lmax = -1e30f;
    if (tid < SK) {
        const float* krow = Kp + ((size_t)(b*SK + tid))*ks + h*DH;
        float s = 0.f;
        #pragma unroll 16
        for (int d = 0; d < DH; d++) s += sq[d] * krow[d];
        s *= scale;
        sp[tid] = s;
        lmax = s;
    }
    red[tid] = lmax; __syncthreads();
    for (int o = 64; o > 0; o >>= 1) {
        if (tid < o) red[tid] = fmaxf(red[tid], red[tid+o]);
        __syncthreads();
    }
    float m = red[0];
    __syncthreads();
    float lsum = 0.f;
    if (tid < SK) {
        float e = __expf(sp[tid] - m);
        sp[tid] = e; lsum = e;
    }
    red[tid] = lsum; __syncthreads();
    for (int o = 64; o > 0; o >>= 1) {
        if (tid < o) red[tid] += red[tid+o];
        __syncthreads();
    }
    float inv = 1.f / red[0];
    __syncthreads();

    if (tid < DH) {
        float o = 0.f;
        for (int j = 0; j < SK; j++)
            o += sp[j] * V[((size_t)(b*SK + j))*vs + h*DH + tid];
        O[((size_t)(b*HW + q))*os + h*DH + tid] = o * inv;
    }
}

// ---------------- GeGLU ----------------
__global__ void geglu(const float* __restrict__ ff, float* __restrict__ out) {
    int idx = blockIdx.x * 256 + threadIdx.x;
    if (idx >= NB*HW*4*CCH) return;
    int m = idx / (4*CCH);
    int j = idx % (4*CCH);
    float a = ff[(size_t)m*8*CCH + j];
    float g = ff[(size_t)m*8*CCH + 4*CCH + j];
    float ge = 0.5f * g * (1.f + erff(g * 0.70710678118654752f));
    out[idx] = a * ge;
}

__global__ void final_add(const float* __restrict__ tmp, const float* __restrict__ xin,
                          float* __restrict__ out) {
    int idx = blockIdx.x * 256 + threadIdx.x;
    if (idx >= NB*CCH*HW) return;
    int p = idx % HW;
    int c = (idx / HW) % CCH;
    int n = idx / (HW*CCH);
    out[idx] = tmp[((size_t)n*HW + p)*CCH + c] + xin[idx];
}

// ---------------- host launch ----------------
extern "C" void kernel_launch(void* const* d_in, const int* in_sizes, int n_in,
                              void* d_out, int out_size) {
    const float* x        = (const float*)d_in[0];
    const float* context  = (const float*)d_in[1];
    const float* gn_s     = (const float*)d_in[2];
    const float* gn_b     = (const float*)d_in[3];
    const float* conv1_w  = (const float*)d_in[4];
    const float* conv1_b  = (const float*)d_in[5];
    const float* ln1_s    = (const float*)d_in[6];
    const float* ln1_b    = (const float*)d_in[7];
    const float* sa_in_w  = (const float*)d_in[8];
    const float* sa_out_w = (const float*)d_in[9];
    const float* sa_out_b = (const float*)d_in[10];
    const float* ln2_s    = (const float*)d_in[11];
    const float* ln2_b    = (const float*)d_in[12];
    const float* ca_q_w   = (const float*)d_in[13];
    const float* ca_k_w   = (const float*)d_in[14];
    const float* ca_v_w   = (const float*)d_in[15];
    const float* ca_out_w = (const float*)d_in[16];
    const float* ca_out_b = (const float*)d_in[17];
    const float* ln3_s    = (const float*)d_in[18];
    const float* ln3_b    = (const float*)d_in[19];
    const float* lin1_w   = (const float*)d_in[20];
    const float* lin1_b   = (const float*)d_in[21];
    const float* lin2_w   = (const float*)d_in[22];
    const float* lin2_b   = (const float*)d_in[23];
    const float* co_w     = (const float*)d_in[24];
    const float* co_b     = (const float*)d_in[25];
    float* out = (float*)d_out;

    float *gn, *xseq, *t, *qkv, *attn, *kctx, *vctx, *ff, *ffg, *tmp, *sc;
    cudaGetSymbolAddress((void**)&gn,   g_gn);
    cudaGetSymbolAddress((void**)&xseq, g_xseq);
    cudaGetSymbolAddress((void**)&t,    g_t);
    cudaGetSymbolAddress((void**)&qkv,  g_qkv);
    cudaGetSymbolAddress((void**)&attn, g_attn);
    cudaGetSymbolAddress((void**)&kctx, g_kctx);
    cudaGetSymbolAddress((void**)&vctx, g_vctx);
    cudaGetSymbolAddress((void**)&ff,   g_ff);
    cudaGetSymbolAddress((void**)&ffg,  g_ffg);
    cudaGetSymbolAddress((void**)&tmp,  g_tmp);
    cudaGetSymbolAddress((void**)&sc,   g_scores);

    const int M = NB * HW;   // 8192
    dim3 blk(256);
    auto gxy = [](int N_, int M_) { return dim3((N_+127)/128, (M_+127)/128, 1); };

    // 1. GroupNorm + transpose
    gn_stats<<<NB*GRP, 256>>>(x);
    gn_apply<<<(NB*CCH*HW + 255)/256, 256>>>(x, gn_s, gn_b);

    // 2. conv1
    gemm_tf32<true><<<gxy(CCH, M), blk>>>(gn, CCH, 0,0, conv1_w, CCH, 0,0,
                                          conv1_b, nullptr, xseq, CCH, 0,0, M, CCH, CCH);

    // 3. self-attention
    layernorm<<<M, 256>>>(xseq, ln1_s, ln1_b, t);
    gemm_tf32<false><<<gxy(3*CCH, M), blk>>>(t, CCH, 0,0, sa_in_w, 3*CCH, 0,0,
                                             nullptr, nullptr, qkv, 3*CCH, 0,0, M, 3*CCH, CCH);
    // scores[z=b*8+h] = Q @ K^T  (M=1024, N=1024, K=80)
    {
        dim3 g(8, 8, NB*NH);
        gemm_tf32<true><<<g, blk>>>(qkv,        3*CCH, (long)HW*3*CCH, DH,
                                    qkv + CCH,  3*CCH, (long)HW*3*CCH, DH,
                                    nullptr, nullptr,
                                    sc, HW, (long)NH*HW*HW, (long)HW*HW,
                                    HW, HW, DH);
    }
    softmax_rows<<<NB*NH*HW, 256>>>(sc, HW, rsqrtf((float)DH));
    // attn = P @ V   (M=1024, N=80, K=1024)
    {
        dim3 g(1, 8, NB*NH);
        gemm_tf32<false><<<g, blk>>>(sc, HW, (long)NH*HW*HW, (long)HW*HW,
                                     qkv + 2*CCH, 3*CCH, (long)HW*3*CCH, DH,
                                     nullptr, nullptr,
                                     attn, CCH, (long)HW*CCH, DH,
                                     HW, DH, HW);
    }
    gemm_tf32<false><<<gxy(CCH, M), blk>>>(attn, CCH, 0,0, sa_out_w, CCH, 0,0,
                                           sa_out_b, xseq, xseq, CCH, 0,0, M, CCH, CCH);

    // 4. cross-attention
    layernorm<<<M, 256>>>(xseq, ln2_s, ln2_b, t);
    gemm_tf32<false><<<gxy(CCH, M), blk>>>(t, CCH, 0,0, ca_q_w, CCH, 0,0,
                                           nullptr, nullptr, qkv, CCH, 0,0, M, CCH, CCH);
    gemm_tf32<false><<<gxy(CCH, NB*SKCTX), blk>>>(context, DCTX, 0,0, ca_k_w, CCH, 0,0,
                                                  nullptr, nullptr, kctx, CCH, 0,0, NB*SKCTX, CCH, DCTX);
    gemm_tf32<false><<<gxy(CCH, NB*SKCTX), blk>>>(context, DCTX, 0,0, ca_v_w, CCH, 0,0,
                                                  nullptr, nullptr, vctx, CCH, 0,0, NB*SKCTX, CCH, DCTX);
    attention<<<NB*NH*HW, 128>>>(qkv, kctx, vctx, attn, SKCTX, CCH, CCH, CCH, CCH);
    gemm_tf32<false><<<gxy(CCH, M), blk>>>(attn, CCH, 0,0, ca_out_w, CCH, 0,0,
                                           ca_out_b, xseq, xseq, CCH, 0,0, M, CCH, CCH);

    // 5. GeGLU FFN
    layernorm<<<M, 256>>>(xseq, ln3_s, ln3_b, t);
    gemm_tf32<false><<<gxy(8*CCH, M), blk>>>(t, CCH, 0,0, lin1_w, 8*CCH, 0,0,
                                             lin1_b, nullptr, ff, 8*CCH, 0,0, M, 8*CCH, CCH);
    geglu<<<(NB*HW*4*CCH + 255)/256, 256>>>(ff, ffg);
    gemm_tf32<false><<<gxy(CCH, M), blk>>>(ffg, 4*CCH, 0,0, lin2_w, CCH, 0,0,
                                           lin2_b, xseq, xseq, CCH, 0,0, M, CCH, 4*CCH);

    // 6. final conv + long residual
    gemm_tf32<true><<<gxy(CCH, M), blk>>>(xseq, CCH, 0,0, co_w, CCH, 0,0,
                                          co_b, nullptr, tmp, CCH, 0,0, M, CCH, CCH);
    final_add<<<(NB*CCH*HW + 255)/256, 256>>>(tmp, x, out);
}

// round 3
// speedup vs baseline: 7.8668x; 1.1981x over previous
#include <cuda_runtime.h>
#include <math.h>
#include <stdint.h>

#define NB    8
#define CCH   640
#define HW    1024
#define NH    8
#define DH    80
#define DCTX  512
#define GRP   32
#define CPG   20
#define SKCTX 77

// ---------------- scratch ----------------
__device__ float g_gn    [NB*HW*CCH];
__device__ float g_xseq  [NB*HW*CCH];
__device__ float g_t     [NB*HW*CCH];
__device__ float g_qkv   [NB*HW*3*CCH];
__device__ float g_attn  [NB*HW*CCH];
__device__ float g_kctx  [NB*SKCTX*CCH];
__device__ float g_vctx  [NB*SKCTX*CCH];
__device__ float g_ff    [NB*HW*8*CCH];
__device__ float g_ffg   [NB*HW*4*CCH];
__device__ float g_tmp   [NB*HW*CCH];
__device__ float g_scores[NB*NH*HW*HW];
__device__ float g_rowinv[NB*NH*HW];
__device__ float g_gnstat[NB*GRP*2];

// ---------------- GroupNorm ----------------
__global__ void gn_stats(const float* __restrict__ x) {
    int ng = blockIdx.x;
    int n = ng / GRP, g = ng % GRP;
    const float* base = x + ((size_t)n*CCH + (size_t)g*CPG) * HW;
    float s = 0.f, s2 = 0.f;
    for (int i = threadIdx.x; i < CPG*HW; i += 256) {
        float v = base[i]; s += v; s2 += v*v;
    }
    __shared__ float rs[256], rq[256];
    rs[threadIdx.x] = s; rq[threadIdx.x] = s2;
    __syncthreads();
    for (int o = 128; o > 0; o >>= 1) {
        if (threadIdx.x < o) { rs[threadIdx.x] += rs[threadIdx.x+o]; rq[threadIdx.x] += rq[threadIdx.x+o]; }
        __syncthreads();
    }
    if (threadIdx.x == 0) {
        float inv_n = 1.f / (float)(CPG*HW);
        float mu  = rs[0] * inv_n;
        float var = rq[0] * inv_n - mu*mu;
        g_gnstat[ng*2]   = mu;
        g_gnstat[ng*2+1] = rsqrtf(var + 1e-6f);
    }
}

__global__ void gn_apply(const float* __restrict__ x,
                         const float* __restrict__ s, const float* __restrict__ b) {
    int idx = blockIdx.x * 256 + threadIdx.x;
    if (idx >= NB*CCH*HW) return;
    int p = idx % HW;
    int c = (idx / HW) % CCH;
    int n = idx / (HW*CCH);
    int ng = n*GRP + c / CPG;
    float mu = g_gnstat[ng*2], is = g_gnstat[ng*2+1];
    g_gn[((size_t)n*HW + p)*CCH + c] = (x[idx] - mu) * is * s[c] + b[c];
}

// ---------------- LayerNorm ----------------
__global__ void layernorm(const float* __restrict__ in,
                          const float* __restrict__ s, const float* __restrict__ b,
                          float* __restrict__ out) {
    int row = blockIdx.x;
    const float* r = in + (size_t)row * CCH;
    float sum = 0.f, sq = 0.f;
    for (int i = threadIdx.x; i < CCH; i += 256) {
        float v = r[i]; sum += v; sq += v*v;
    }
    __shared__ float rs[256], rq[256];
    rs[threadIdx.x] = sum; rq[threadIdx.x] = sq;
    __syncthreads();
    for (int o = 128; o > 0; o >>= 1) {
        if (threadIdx.x < o) { rs[threadIdx.x] += rs[threadIdx.x+o]; rq[threadIdx.x] += rq[threadIdx.x+o]; }
        __syncthreads();
    }
    float mu  = rs[0] / (float)CCH;
    float inv = rsqrtf(rq[0] / (float)CCH - mu*mu + 1e-5f);
    for (int i = threadIdx.x; i < CCH; i += 256)
        out[(size_t)row*CCH + i] = (r[i] - mu) * inv * s[i] + b[i];
}

// ---------------- mma / cp.async helpers ----------------
__device__ __forceinline__ void mma8(float c[4], uint32_t a0, uint32_t a1, uint32_t a2, uint32_t a3,
                                     uint32_t b0, uint32_t b1) {
    asm volatile("mma.sync.aligned.m16n8k8.row.col.f32.tf32.tf32.f32 "
        "{%0,%1,%2,%3}, {%4,%5,%6,%7}, {%8,%9}, {%0,%1,%2,%3};"
        : "+f"(c[0]), "+f"(c[1]), "+f"(c[2]), "+f"(c[3])
        : "r"(a0), "r"(a1), "r"(a2), "r"(a3), "r"(b0), "r"(b1));
}
__device__ __forceinline__ void cpa16(float* dst, const float* src, bool valid) {
    uint32_t d = (uint32_t)__cvta_generic_to_shared(dst);
    int sz = valid ? 16 : 0;
    asm volatile("cp.async.cg.shared.global [%0], [%1], 16, %2;" :: "r"(d), "l"(src), "r"(sz));
}
#define CP_COMMIT() asm volatile("cp.async.commit_group;")
#define CP_WAIT1()  asm volatile("cp.async.wait_group 1;")

// ---------------- tf32 GEMM, 128x128x32, double-buffered cp.async ----------------
// C[z][m,n] = A[z] @ B[z] (*rowscale) (+bias) (+res)
// TRANS_B: B stored [N,K] row-major; else [K,N] row-major.
#define SMEM_BYTES 73728
template<bool TRANS_B>
__global__ __launch_bounds__(256)
void gemm_tf32(const float* __restrict__ A, int lda, long sAb, long sAh,
               const float* __restrict__ B, int ldb, long sBb, long sBh,
               const float* __restrict__ bias,
               const float* __restrict__ res,
               const float* __restrict__ rowscale,
               float* __restrict__ C, int ldc, long sCb, long sCh,
               int M, int N, int K) {
    extern __shared__ float smem[];
    constexpr int SA  = 36;          // padded row stride for [r][k] tiles
    constexpr int ASZ = 128 * 36;
    constexpr int BSZ = TRANS_B ? 128 * 36 : 32 * 132;
    float* As = smem;                // [2][ASZ]
    float* Bs = smem + 2 * ASZ;      // [2][BSZ]

    int tid = threadIdx.x;
    int lane = tid & 31, warp = tid >> 5;
    int wm = (warp >> 2) * 64, wn = (warp & 3) * 32;
    int bm = blockIdx.y * 128, bn = blockIdx.x * 128;
    int zb = blockIdx.z >> 3, zh = blockIdx.z & 7;

    const float* Ab = A + (long)zb*sAb + (long)zh*sAh;
    const float* Bb = B + (long)zb*sBb + (long)zh*sBh;
    const float* Rb = res ? res + (long)zb*sCb + (long)zh*sCh : nullptr;
    const float* RS = rowscale ? rowscale + (size_t)blockIdx.z * M : nullptr;
    float*       Cb = C + (long)zb*sCb + (long)zh*sCh;

    auto stage = [&](int k0, int buf) {
        #pragma unroll
        for (int i = 0; i < 4; i++) {
            int c = tid + i*256;
            int m = c >> 3, kc = (c & 7) << 2;
            int gm = bm + m, gk = k0 + kc;
            bool v = (gm < M) && (gk < K);
            cpa16(As + buf*ASZ + m*SA + kc, v ? Ab + (size_t)gm*lda + gk : Ab, v);
        }
        if (TRANS_B) {
            #pragma unroll
            for (int i = 0; i < 4; i++) {
                int c = tid + i*256;
                int n = c >> 3, kc = (c & 7) << 2;
                int gn = bn + n, gk = k0 + kc;
                bool v = (gn < N) && (gk < K);
                cpa16(Bs + buf*BSZ + n*SA + kc, v ? Bb + (size_t)gn*ldb + gk : Bb, v);
            }
        } else {
            #pragma unroll
            for (int i = 0; i < 4; i++) {
                int c = tid + i*256;
                int k = c >> 5, nc = (c & 31) << 2;
                int gk = k0 + k, gn = bn + nc;
                bool v = (gk < K) && (gn < N);
                cpa16(Bs + buf*BSZ + k*132 + nc, v ? Bb + (size_t)gk*ldb + gn : Bb, v);
            }
        }
    };

    float acc[4][4][4];
    #pragma unroll
    for (int i = 0; i < 4; i++)
        #pragma unroll
        for (int j = 0; j < 4; j++)
            #pragma unroll
            for (int r = 0; r < 4; r++) acc[i][j][r] = 0.f;

    int nk = (K + 31) >> 5;
    stage(0, 0);
    CP_COMMIT();

    for (int t = 0; t < nk; t++) {
        if (t + 1 < nk) stage((t+1) << 5, (t+1) & 1);
        CP_COMMIT();
        CP_WAIT1();
        __syncthreads();

        int p = t & 1;
        const uint32_t* A_s = (const uint32_t*)(As + p*ASZ);
        const uint32_t* B_s = (const uint32_t*)(Bs + p*BSZ);

        #pragma unroll
        for (int kk = 0; kk < 32; kk += 8) {
            int kb = kk + (lane & 3);
            uint32_t af[4][4], bf[4][2];
            #pragma unroll
            for (int mi = 0; mi < 4; mi++) {
                int m0 = wm + mi*16 + (lane >> 2);
                af[mi][0] = A_s[m0*SA + kb];
                af[mi][1] = A_s[(m0+8)*SA + kb];
                af[mi][2] = A_s[m0*SA + kb + 4];
                af[mi][3] = A_s[(m0+8)*SA + kb + 4];
            }
            #pragma unroll
            for (int ni = 0; ni < 4; ni++) {
                int n0 = wn + ni*8 + (lane >> 2);
                if (TRANS_B) {
                    bf[ni][0] = B_s[n0*SA + kb];
                    bf[ni][1] = B_s[n0*SA + kb + 4];
                } else {
                    bf[ni][0] = B_s[kb*132 + n0];
                    bf[ni][1] = B_s[(kb+4)*132 + n0];
                }
            }
            #pragma unroll
            for (int mi = 0; mi < 4; mi++)
                #pragma unroll
                for (int ni = 0; ni < 4; ni++)
                    mma8(acc[mi][ni], af[mi][0], af[mi][1], af[mi][2], af[mi][3],
                         bf[ni][0], bf[ni][1]);
        }
        __syncthreads();
    }

    #pragma unroll
    for (int mi = 0; mi < 4; mi++) {
        #pragma unroll
        for (int ni = 0; ni < 4; ni++) {
            int row0 = bm + wm + mi*16 + (lane >> 2);
            int col0 = bn + wn + ni*8 + (lane & 3)*2;
            #pragma unroll
            for (int r = 0; r < 4; r++) {
                int row = row0 + (r >> 1)*8;
                int col = col0 + (r & 1);
                if (row < M && col < N) {
                    float v = acc[mi][ni][r];
                    if (RS)   v *= RS[row];
                    if (bias) v += bias[col];
                    if (Rb)   v += Rb[(size_t)row*ldc + col];
                    Cb[(size_t)row*ldc + col] = v;
                }
            }
        }
    }
}

// ---------------- softmax (2-pass, writes 1/sum; normalization folded into PV) ----------------
__global__ void softmax_rows(float* __restrict__ S, float* __restrict__ rowinv, float scale) {
    int row = blockIdx.x;
    float4* r4 = (float4*)(S + (size_t)row * HW);
    int tid = threadIdx.x;           // 256 threads x float4 = 1024
    float4 v = r4[tid];
    float m = fmaxf(fmaxf(v.x, v.y), fmaxf(v.z, v.w));
    __shared__ float red[256];
    red[tid] = m; __syncthreads();
    for (int o = 128; o > 0; o >>= 1) {
        if (tid < o) red[tid] = fmaxf(red[tid], red[tid+o]);
        __syncthreads();
    }
    m = red[0];
    __syncthreads();
    float4 e;
    e.x = __expf((v.x - m) * scale);
    e.y = __expf((v.y - m) * scale);
    e.z = __expf((v.z - m) * scale);
    e.w = __expf((v.w - m) * scale);
    r4[tid] = e;
    red[tid] = e.x + e.y + e.z + e.w;
    __syncthreads();
    for (int o = 128; o > 0; o >>= 1) {
        if (tid < o) red[tid] += red[tid+o];
        __syncthreads();
    }
    if (tid == 0) rowinv[row] = 1.f / red[0];
}

// NOTE: softmax max is computed over raw scores; exp applies scale to (x-m),
// identical to softmax(scale*x) since scale>0 (max position invariant under
// monotone map; exp((x-m)*s) / sum = softmax(s*x)).

// ---------------- small-SK attention (cross-attn, SK=77) ----------------
__global__ void attention(const float* __restrict__ Q, const float* __restrict__ Kp,
                          const float* __restrict__ V, float* __restrict__ O,
                          int SK, int qs, int ks, int vs, int os) {
    int q = blockIdx.x % HW;
    int h = (blockIdx.x / HW) % NH;
    int b = blockIdx.x / (HW*NH);
    int tid = threadIdx.x;

    __shared__ float sq[DH];
    __shared__ float sp[128];
    __shared__ float red[128];

    const float scale = rsqrtf((float)DH);
    const float* qrow = Q + ((size_t)(b*HW + q))*qs + h*DH;
    if (tid < DH) sq[tid] = qrow[tid];
    __syncthreads();

    float lmax = -1e30f;
    if (tid < SK) {
        const float* krow = Kp + ((size_t)(b*SK + tid))*ks + h*DH;
        float s = 0.f;
        #pragma unroll 16
        for (int d = 0; d < DH; d++) s += sq[d] * krow[d];
        s *= scale;
        sp[tid] = s;
        lmax = s;
    }
    red[tid] = lmax; __syncthreads();
    for (int o = 64; o > 0; o >>= 1) {
        if (tid < o) red[tid] = fmaxf(red[tid], red[tid+o]);
        __syncthreads();
    }
    float m = red[0];
    __syncthreads();
    float lsum = 0.f;
    if (tid < SK) {
        float e = __expf(sp[tid] - m);
        sp[tid] = e; lsum = e;
    }
    red[tid] = lsum; __syncthreads();
    for (int o = 64; o > 0; o >>= 1) {
        if (tid < o) red[tid] += red[tid+o];
        __syncthreads();
    }
    float inv = 1.f / red[0];
    __syncthreads();

    if (tid < DH) {
        float o = 0.f;
        for (int j = 0; j < SK; j++)
            o += sp[j] * V[((size_t)(b*SK + j))*vs + h*DH + tid];
        O[((size_t)(b*HW + q))*os + h*DH + tid] = o * inv;
    }
}

// ---------------- GeGLU ----------------
__global__ void geglu(const float* __restrict__ ff, float* __restrict__ out) {
    int idx = blockIdx.x * 256 + threadIdx.x;
    if (idx >= NB*HW*4*CCH) return;
    int m = idx / (4*CCH);
    int j = idx % (4*CCH);
    float a = ff[(size_t)m*8*CCH + j];
    float g = ff[(size_t)m*8*CCH + 4*CCH + j];
    float ge = 0.5f * g * (1.f + erff(g * 0.70710678118654752f));
    out[idx] = a * ge;
}

__global__ void final_add(const float* __restrict__ tmp, const float* __restrict__ xin,
                          float* __restrict__ out) {
    int idx = blockIdx.x * 256 + threadIdx.x;
    if (idx >= NB*CCH*HW) return;
    int p = idx % HW;
    int c = (idx / HW) % CCH;
    int n = idx / (HW*CCH);
    out[idx] = tmp[((size_t)n*HW + p)*CCH + c] + xin[idx];
}

// ---------------- host launch ----------------
extern "C" void kernel_launch(void* const* d_in, const int* in_sizes, int n_in,
                              void* d_out, int out_size) {
    const float* x        = (const float*)d_in[0];
    const float* context  = (const float*)d_in[1];
    const float* gn_s     = (const float*)d_in[2];
    const float* gn_b     = (const float*)d_in[3];
    const float* conv1_w  = (const float*)d_in[4];
    const float* conv1_b  = (const float*)d_in[5];
    const float* ln1_s    = (const float*)d_in[6];
    const float* ln1_b    = (const float*)d_in[7];
    const float* sa_in_w  = (const float*)d_in[8];
    const float* sa_out_w = (const float*)d_in[9];
    const float* sa_out_b = (const float*)d_in[10];
    const float* ln2_s    = (const float*)d_in[11];
    const float* ln2_b    = (const float*)d_in[12];
    const float* ca_q_w   = (const float*)d_in[13];
    const float* ca_k_w   = (const float*)d_in[14];
    const float* ca_v_w   = (const float*)d_in[15];
    const float* ca_out_w = (const float*)d_in[16];
    const float* ca_out_b = (const float*)d_in[17];
    const float* ln3_s    = (const float*)d_in[18];
    const float* ln3_b    = (const float*)d_in[19];
    const float* lin1_w   = (const float*)d_in[20];
    const float* lin1_b   = (const float*)d_in[21];
    const float* lin2_w   = (const float*)d_in[22];
    const float* lin2_b   = (const float*)d_in[23];
    const float* co_w     = (const float*)d_in[24];
    const float* co_b     = (const float*)d_in[25];
    float* out = (float*)d_out;

    float *gn, *xseq, *t, *qkv, *attn, *kctx, *vctx, *ff, *ffg, *tmp, *sc, *rinv;
    cudaGetSymbolAddress((void**)&gn,   g_gn);
    cudaGetSymbolAddress((void**)&xseq, g_xseq);
    cudaGetSymbolAddress((void**)&t,    g_t);
    cudaGetSymbolAddress((void**)&qkv,  g_qkv);
    cudaGetSymbolAddress((void**)&attn, g_attn);
    cudaGetSymbolAddress((void**)&kctx, g_kctx);
    cudaGetSymbolAddress((void**)&vctx, g_vctx);
    cudaGetSymbolAddress((void**)&ff,   g_ff);
    cudaGetSymbolAddress((void**)&ffg,  g_ffg);
    cudaGetSymbolAddress((void**)&tmp,  g_tmp);
    cudaGetSymbolAddress((void**)&sc,   g_scores);
    cudaGetSymbolAddress((void**)&rinv, g_rowinv);

    cudaFuncSetAttribute(gemm_tf32<true>,  cudaFuncAttributeMaxDynamicSharedMemorySize, SMEM_BYTES);
    cudaFuncSetAttribute(gemm_tf32<false>, cudaFuncAttributeMaxDynamicSharedMemorySize, SMEM_BYTES);

    const int M = NB * HW;   // 8192
    dim3 blk(256);
    auto gxy = [](int N_, int M_) { return dim3((N_+127)/128, (M_+127)/128, 1); };

    // 1. GroupNorm + transpose
    gn_stats<<<NB*GRP, 256>>>(x);
    gn_apply<<<(NB*CCH*HW + 255)/256, 256>>>(x, gn_s, gn_b);

    // 2. conv1
    gemm_tf32<true><<<gxy(CCH, M), blk, SMEM_BYTES>>>(gn, CCH, 0,0, conv1_w, CCH, 0,0,
                                          conv1_b, nullptr, nullptr, xseq, CCH, 0,0, M, CCH, CCH);

    // 3. self-attention
    layernorm<<<M, 256>>>(xseq, ln1_s, ln1_b, t);
    gemm_tf32<false><<<gxy(3*CCH, M), blk, SMEM_BYTES>>>(t, CCH, 0,0, sa_in_w, 3*CCH, 0,0,
                                             nullptr, nullptr, nullptr, qkv, 3*CCH, 0,0, M, 3*CCH, CCH);
    {   // scores[z] = Q @ K^T
        dim3 g(8, 8, NB*NH);
        gemm_tf32<true><<<g, blk, SMEM_BYTES>>>(qkv,       3*CCH, (long)HW*3*CCH, DH,
                                    qkv + CCH, 3*CCH, (long)HW*3*CCH, DH,
                                    nullptr, nullptr, nullptr,
                                    sc, HW, (long)NH*HW*HW, (long)HW*HW,
                                    HW, HW, DH);
    }
    softmax_rows<<<NB*NH*HW, 256>>>(sc, rinv, rsqrtf((float)DH));
    {   // attn = P @ V, normalized by rowinv in epilogue
        dim3 g(1, 8, NB*NH);
        gemm_tf32<false><<<g, blk, SMEM_BYTES>>>(sc, HW, (long)NH*HW*HW, (long)HW*HW,
                                     qkv + 2*CCH, 3*CCH, (long)HW*3*CCH, DH,
                                     nullptr, nullptr, rinv,
                                     attn, CCH, (long)HW*CCH, DH,
                                     HW, DH, HW);
    }
    gemm_tf32<false><<<gxy(CCH, M), blk, SMEM_BYTES>>>(attn, CCH, 0,0, sa_out_w, CCH, 0,0,
                                           sa_out_b, xseq, nullptr, xseq, CCH, 0,0, M, CCH, CCH);

    // 4. cross-attention
    layernorm<<<M, 256>>>(xseq, ln2_s, ln2_b, t);
    gemm_tf32<false><<<gxy(CCH, M), blk, SMEM_BYTES>>>(t, CCH, 0,0, ca_q_w, CCH, 0,0,
                                           nullptr, nullptr, nullptr, qkv, CCH, 0,0, M, CCH, CCH);
    gemm_tf32<false><<<gxy(CCH, NB*SKCTX), blk, SMEM_BYTES>>>(context, DCTX, 0,0, ca_k_w, CCH, 0,0,
                                                  nullptr, nullptr, nullptr, kctx, CCH, 0,0, NB*SKCTX, CCH, DCTX);
    gemm_tf32<false><<<gxy(CCH, NB*SKCTX), blk, SMEM_BYTES>>>(context, DCTX, 0,0, ca_v_w, CCH, 0,0,
                                                  nullptr, nullptr, nullptr, vctx, CCH, 0,0, NB*SKCTX, CCH, DCTX);
    attention<<<NB*NH*HW, 128>>>(qkv, kctx, vctx, attn, SKCTX, CCH, CCH, CCH, CCH);
    gemm_tf32<false><<<gxy(CCH, M), blk, SMEM_BYTES>>>(attn, CCH, 0,0, ca_out_w, CCH, 0,0,
                                           ca_out_b, xseq, nullptr, xseq, CCH, 0,0, M, CCH, CCH);

    // 5. GeGLU FFN
    layernorm<<<M, 256>>>(xseq, ln3_s, ln3_b, t);
    gemm_tf32<false><<<gxy(8*CCH, M), blk, SMEM_BYTES>>>(t, CCH, 0,0, lin1_w, 8*CCH, 0,0,
                                             lin1_b, nullptr, nullptr, ff, 8*CCH, 0,0, M, 8*CCH, CCH);
    geglu<<<(NB*HW*4*CCH + 255)/256, 256>>>(ff, ffg);
    gemm_tf32<false><<<gxy(CCH, M), blk, SMEM_BYTES>>>(ffg, 4*CCH, 0,0, lin2_w, CCH, 0,0,
                                           lin2_b, xseq, nullptr, xseq, CCH, 0,0, M, CCH, 4*CCH);

    // 6. final conv + long residual
    gemm_tf32<true><<<gxy(CCH, M), blk, SMEM_BYTES>>>(xseq, CCH, 0,0, co_w, CCH, 0,0,
                                          co_b, nullptr, nullptr, tmp, CCH, 0,0, M, CCH, CCH);
    final_add<<<(NB*CCH*HW + 255)/256, 256>>>(tmp, x, out);
}

// round 4
// speedup vs baseline: 8.5804x; 1.0907x over previous
#include <cuda_runtime.h>
#include <math.h>
#include <stdint.h>

#define NB    8
#define CCH   640
#define HW    1024
#define NH    8
#define DH    80
#define DCTX  512
#define GRP   32
#define CPG   20
#define SKCTX 77

// ---------------- scratch ----------------
__device__ float g_gn    [NB*HW*CCH];
__device__ float g_xseq  [NB*HW*CCH];
__device__ float g_t     [NB*HW*CCH];
__device__ float g_qkv   [NB*HW*3*CCH];
__device__ float g_attn  [NB*HW*CCH];
__device__ float g_kctx  [NB*SKCTX*CCH];
__device__ float g_vctx  [NB*SKCTX*CCH];
__device__ float g_ff    [NB*HW*8*CCH];
__device__ float g_ffg   [NB*HW*4*CCH];
__device__ float g_tmp   [NB*HW*CCH];
__device__ float g_gnstat[NB*GRP*2];

// ---------------- GroupNorm stats (float4) ----------------
__global__ void gn_stats(const float* __restrict__ x) {
    int ng = blockIdx.x;
    int n = ng / GRP, g = ng % GRP;
    const float4* base = (const float4*)(x + ((size_t)n*CCH + (size_t)g*CPG) * HW);
    float s = 0.f, s2 = 0.f;
    for (int i = threadIdx.x; i < CPG*HW/4; i += 256) {
        float4 v = base[i];
        s  += v.x + v.y + v.z + v.w;
        s2 += v.x*v.x + v.y*v.y + v.z*v.z + v.w*v.w;
    }
    __shared__ float rs[256], rq[256];
    rs[threadIdx.x] = s; rq[threadIdx.x] = s2;
    __syncthreads();
    for (int o = 128; o > 0; o >>= 1) {
        if (threadIdx.x < o) { rs[threadIdx.x] += rs[threadIdx.x+o]; rq[threadIdx.x] += rq[threadIdx.x+o]; }
        __syncthreads();
    }
    if (threadIdx.x == 0) {
        float inv_n = 1.f / (float)(CPG*HW);
        float mu  = rs[0] * inv_n;
        float var = rq[0] * inv_n - mu*mu;
        g_gnstat[ng*2]   = mu;
        g_gnstat[ng*2+1] = rsqrtf(var + 1e-6f);
    }
}

// ---------------- GroupNorm apply + transpose (32x32 smem tile) ----------------
__global__ void gn_apply(const float* __restrict__ x,
                         const float* __restrict__ s, const float* __restrict__ b) {
    __shared__ float tile[32][33];
    int n = blockIdx.z;
    int p0 = blockIdx.x*32, c0 = blockIdx.y*32;
    int tx = threadIdx.x, ty = threadIdx.y;   // 32 x 8
    #pragma unroll
    for (int i = 0; i < 4; i++) {
        int c = c0 + ty + i*8;
        int ng = n*GRP + c / CPG;
        float mu = g_gnstat[ng*2], is = g_gnstat[ng*2+1];
        float v = x[((size_t)n*CCH + c)*HW + p0 + tx];
        tile[ty + i*8][tx] = (v - mu) * is * s[c] + b[c];
    }
    __syncthreads();
    #pragma unroll
    for (int i = 0; i < 4; i++) {
        int p = p0 + ty + i*8;
        g_gn[((size_t)n*HW + p)*CCH + c0 + tx] = tile[tx][ty + i*8];
    }
}

// ---------------- LayerNorm (float4, single read pass) ----------------
__global__ __launch_bounds__(160)
void layernorm(const float* __restrict__ in,
               const float* __restrict__ s, const float* __restrict__ b,
               float* __restrict__ out) {
    int row = blockIdx.x;
    int tid = threadIdx.x;       // 160 threads * float4 = 640
    const float4* r4 = (const float4*)(in + (size_t)row * CCH);
    float4 v = r4[tid];
    float sum = v.x + v.y + v.z + v.w;
    float sq  = v.x*v.x + v.y*v.y + v.z*v.z + v.w*v.w;
    #pragma unroll
    for (int o = 16; o > 0; o >>= 1) {
        sum += __shfl_xor_sync(~0u, sum, o);
        sq  += __shfl_xor_sync(~0u, sq,  o);
    }
    __shared__ float ws[5], wq[5];
    int w = tid >> 5;
    if ((tid & 31) == 0) { ws[w] = sum; wq[w] = sq; }
    __syncthreads();
    sum = ws[0] + ws[1] + ws[2] + ws[3] + ws[4];
    sq  = wq[0] + wq[1] + wq[2] + wq[3] + wq[4];
    float mu  = sum / (float)CCH;
    float inv = rsqrtf(sq / (float)CCH - mu*mu + 1e-5f);
    float4 sc = ((const float4*)s)[tid];
    float4 bb = ((const float4*)b)[tid];
    float4 o;
    o.x = (v.x - mu) * inv * sc.x + bb.x;
    o.y = (v.y - mu) * inv * sc.y + bb.y;
    o.z = (v.z - mu) * inv * sc.z + bb.z;
    o.w = (v.w - mu) * inv * sc.w + bb.w;
    ((float4*)(out + (size_t)row * CCH))[tid] = o;
}

// ---------------- mma / cp.async helpers ----------------
__device__ __forceinline__ void mma8(float c[4], uint32_t a0, uint32_t a1, uint32_t a2, uint32_t a3,
                                     uint32_t b0, uint32_t b1) {
    asm volatile("mma.sync.aligned.m16n8k8.row.col.f32.tf32.tf32.f32 "
        "{%0,%1,%2,%3}, {%4,%5,%6,%7}, {%8,%9}, {%0,%1,%2,%3};"
        : "+f"(c[0]), "+f"(c[1]), "+f"(c[2]), "+f"(c[3])
        : "r"(a0), "r"(a1), "r"(a2), "r"(a3), "r"(b0), "r"(b1));
}
__device__ __forceinline__ void cpa16(float* dst, const float* src, bool valid) {
    uint32_t d = (uint32_t)__cvta_generic_to_shared(dst);
    int sz = valid ? 16 : 0;
    asm volatile("cp.async.cg.shared.global [%0], [%1], 16, %2;" :: "r"(d), "l"(src), "r"(sz));
}
#define CP_COMMIT() asm volatile("cp.async.commit_group;")
#define CP_WAIT1()  asm volatile("cp.async.wait_group 1;")
__device__ __forceinline__ uint32_t fu(float f) { return __float_as_uint(f); }

// ---------------- tf32 GEMM, 128x128x32, double-buffered cp.async ----------------
#define SMEM_BYTES 73728
template<bool TRANS_B>
__global__ __launch_bounds__(256)
void gemm_tf32(const float* __restrict__ A, int lda, long sAb, long sAh,
               const float* __restrict__ B, int ldb, long sBb, long sBh,
               const float* __restrict__ bias,
               const float* __restrict__ res,
               float* __restrict__ C, int ldc, long sCb, long sCh,
               int M, int N, int K) {
    extern __shared__ float smem[];
    constexpr int SA  = 36;
    constexpr int ASZ = 128 * 36;
    constexpr int BSZ = TRANS_B ? 128 * 36 : 32 * 132;
    float* As = smem;
    float* Bs = smem + 2 * ASZ;

    int tid = threadIdx.x;
    int lane = tid & 31, warp = tid >> 5;
    int wm = (warp >> 2) * 64, wn = (warp & 3) * 32;
    int bm = blockIdx.y * 128, bn = blockIdx.x * 128;
    int zb = blockIdx.z >> 3, zh = blockIdx.z & 7;

    const float* Ab = A + (long)zb*sAb + (long)zh*sAh;
    const float* Bb = B + (long)zb*sBb + (long)zh*sBh;
    const float* Rb = res ? res + (long)zb*sCb + (long)zh*sCh : nullptr;
    float*       Cb = C + (long)zb*sCb + (long)zh*sCh;

    auto stage = [&](int k0, int buf) {
        #pragma unroll
        for (int i = 0; i < 4; i++) {
            int c = tid + i*256;
            int m = c >> 3, kc = (c & 7) << 2;
            int gm = bm + m, gk = k0 + kc;
            bool v = (gm < M) && (gk < K);
            cpa16(As + buf*ASZ + m*SA + kc, v ? Ab + (size_t)gm*lda + gk : Ab, v);
        }
        if (TRANS_B) {
            #pragma unroll
            for (int i = 0; i < 4; i++) {
                int c = tid + i*256;
                int n = c >> 3, kc = (c & 7) << 2;
                int gn = bn + n, gk = k0 + kc;
                bool v = (gn < N) && (gk < K);
                cpa16(Bs + buf*BSZ + n*SA + kc, v ? Bb + (size_t)gn*ldb + gk : Bb, v);
            }
        } else {
            #pragma unroll
            for (int i = 0; i < 4; i++) {
                int c = tid + i*256;
                int k = c >> 5, nc = (c & 31) << 2;
                int gk = k0 + k, gn = bn + nc;
                bool v = (gk < K) && (gn < N);
                cpa16(Bs + buf*BSZ + k*132 + nc, v ? Bb + (size_t)gk*ldb + gn : Bb, v);
            }
        }
    };

    float acc[4][4][4];
    #pragma unroll
    for (int i = 0; i < 4; i++)
        #pragma unroll
        for (int j = 0; j < 4; j++)
            #pragma unroll
            for (int r = 0; r < 4; r++) acc[i][j][r] = 0.f;

    int nk = (K + 31) >> 5;
    stage(0, 0);
    CP_COMMIT();

    for (int t = 0; t < nk; t++) {
        if (t + 1 < nk) stage((t+1) << 5, (t+1) & 1);
        CP_COMMIT();
        CP_WAIT1();
        __syncthreads();

        int p = t & 1;
        const uint32_t* A_s = (const uint32_t*)(As + p*ASZ);
        const uint32_t* B_s = (const uint32_t*)(Bs + p*BSZ);

        #pragma unroll
        for (int kk = 0; kk < 32; kk += 8) {
            int kb = kk + (lane & 3);
            uint32_t af[4][4], bf[4][2];
            #pragma unroll
            for (int mi = 0; mi < 4; mi++) {
                int m0 = wm + mi*16 + (lane >> 2);
                af[mi][0] = A_s[m0*SA + kb];
                af[mi][1] = A_s[(m0+8)*SA + kb];
                af[mi][2] = A_s[m0*SA + kb + 4];
                af[mi][3] = A_s[(m0+8)*SA + kb + 4];
            }
            #pragma unroll
            for (int ni = 0; ni < 4; ni++) {
                int n0 = wn + ni*8 + (lane >> 2);
                if (TRANS_B) {
                    bf[ni][0] = B_s[n0*SA + kb];
                    bf[ni][1] = B_s[n0*SA + kb + 4];
                } else {
                    bf[ni][0] = B_s[kb*132 + n0];
                    bf[ni][1] = B_s[(kb+4)*132 + n0];
                }
            }
            #pragma unroll
            for (int mi = 0; mi < 4; mi++)
                #pragma unroll
                for (int ni = 0; ni < 4; ni++)
                    mma8(acc[mi][ni], af[mi][0], af[mi][1], af[mi][2], af[mi][3],
                         bf[ni][0], bf[ni][1]);
        }
        __syncthreads();
    }

    #pragma unroll
    for (int mi = 0; mi < 4; mi++) {
        #pragma unroll
        for (int ni = 0; ni < 4; ni++) {
            int row0 = bm + wm + mi*16 + (lane >> 2);
            int col0 = bn + wn + ni*8 + (lane & 3)*2;
            #pragma unroll
            for (int r = 0; r < 4; r++) {
                int row = row0 + (r >> 1)*8;
                int col = col0 + (r & 1);
                if (row < M && col < N) {
                    float v = acc[mi][ni][r];
                    if (bias) v += bias[col];
                    if (Rb)   v += Rb[(size_t)row*ldc + col];
                    Cb[(size_t)row*ldc + col] = v;
                }
            }
        }
    }
}

// ---------------- fused flash self-attention (tf32 mma) ----------------
// grid (HW/128, NB*NH), 256 threads (8 warps x 16 q-rows). K/V double-buffered.
#define KP 84
#define VP 88
#define FLASH_SMEM ((2*64*KP + 2*64*VP)*4)
__global__ __launch_bounds__(256)
void flash_attn(const float* __restrict__ QKV, float* __restrict__ O) {
    constexpr int LD = 3*CCH;
    extern __shared__ float sm[];
    float* Ks = sm;                  // [2][64*KP]
    float* Vs = sm + 2*64*KP;        // [2][64*VP]

    int tid = threadIdx.x, lane = tid & 31, w = tid >> 5;
    int z = blockIdx.y;
    int b = z >> 3, h = z & 7;
    int q0 = blockIdx.x * 128;
    int gr = lane >> 2, t4 = lane & 3;

    const float* Qb = QKV + ((size_t)b*HW)*LD + h*DH;
    const float* Kb = QKV + ((size_t)b*HW)*LD + CCH + h*DH;
    const float* Vb = QKV + ((size_t)b*HW)*LD + 2*CCH + h*DH;

    auto stage = [&](int kt, int buf) {
        int row = tid >> 2;
        int cc  = (tid & 3) * 20;
        const float* kg = Kb + (size_t)(kt*64 + row)*LD + cc;
        const float* vg = Vb + (size_t)(kt*64 + row)*LD + cc;
        float* ksm = Ks + buf*64*KP + row*KP + cc;
        float* vsm = Vs + buf*64*VP + row*VP + cc;
        #pragma unroll
        for (int i = 0; i < 5; i++) {
            cpa16(ksm + i*4, kg + i*4, true);
            cpa16(vsm + i*4, vg + i*4, true);
        }
    };

    stage(0, 0);
    CP_COMMIT();

    // Q fragments in registers (scaled by 1/sqrt(DH))
    const float qscale = 0.1118033988749895f;   // 1/sqrt(80)
    float qf[10][4];
    {
        const float* qp  = Qb + (size_t)(q0 + w*16 + gr)*LD;
        const float* qp8 = qp + 8*LD;
        #pragma unroll
        for (int ks = 0; ks < 10; ks++) {
            qf[ks][0] = qp [ks*8 + t4]     * qscale;
            qf[ks][1] = qp8[ks*8 + t4]     * qscale;
            qf[ks][2] = qp [ks*8 + t4 + 4] * qscale;
            qf[ks][3] = qp8[ks*8 + t4 + 4] * qscale;
        }
    }

    float m0v = -1e30f, m1v = -1e30f, l0 = 0.f, l1 = 0.f;
    float oa[10][4];
    #pragma unroll
    for (int ni = 0; ni < 10; ni++) { oa[ni][0]=oa[ni][1]=oa[ni][2]=oa[ni][3]=0.f; }

    for (int kt = 0; kt < 16; kt++) {
        if (kt + 1 < 16) stage(kt+1, (kt+1) & 1);
        CP_COMMIT();
        CP_WAIT1();
        __syncthreads();
        const float* Kc = Ks + (kt & 1)*64*KP;
        const float* Vc = Vs + (kt & 1)*64*VP;

        // S = Q @ K^T  (16 x 64 per warp)
        float s[8][4];
        #pragma unroll
        for (int ni = 0; ni < 8; ni++) { s[ni][0]=s[ni][1]=s[ni][2]=s[ni][3]=0.f; }
        #pragma unroll
        for (int ks = 0; ks < 10; ks++) {
            #pragma unroll
            for (int ni = 0; ni < 8; ni++) {
                uint32_t b0 = fu(Kc[(gr + 8*ni)*KP + ks*8 + t4]);
                uint32_t b1 = fu(Kc[(gr + 8*ni)*KP + ks*8 + t4 + 4]);
                mma8(s[ni], fu(qf[ks][0]), fu(qf[ks][1]), fu(qf[ks][2]), fu(qf[ks][3]), b0, b1);
            }
        }

        // online softmax
        float tm0 = -1e30f, tm1 = -1e30f;
        #pragma unroll
        for (int ni = 0; ni < 8; ni++) {
            tm0 = fmaxf(tm0, fmaxf(s[ni][0], s[ni][1]));
            tm1 = fmaxf(tm1, fmaxf(s[ni][2], s[ni][3]));
        }
        tm0 = fmaxf(tm0, __shfl_xor_sync(~0u, tm0, 1));
        tm0 = fmaxf(tm0, __shfl_xor_sync(~0u, tm0, 2));
        tm1 = fmaxf(tm1, __shfl_xor_sync(~0u, tm1, 1));
        tm1 = fmaxf(tm1, __shfl_xor_sync(~0u, tm1, 2));
        float mn0 = fmaxf(m0v, tm0), mn1 = fmaxf(m1v, tm1);
        float al0 = __expf(m0v - mn0), al1 = __expf(m1v - mn1);
        m0v = mn0; m1v = mn1;
        float ts0 = 0.f, ts1 = 0.f;
        #pragma unroll
        for (int ni = 0; ni < 8; ni++) {
            s[ni][0] = __expf(s[ni][0] - mn0);
            s[ni][1] = __expf(s[ni][1] - mn0);
            s[ni][2] = __expf(s[ni][2] - mn1);
            s[ni][3] = __expf(s[ni][3] - mn1);
            ts0 += s[ni][0] + s[ni][1];
            ts1 += s[ni][2] + s[ni][3];
        }
        ts0 += __shfl_xor_sync(~0u, ts0, 1); ts0 += __shfl_xor_sync(~0u, ts0, 2);
        ts1 += __shfl_xor_sync(~0u, ts1, 1); ts1 += __shfl_xor_sync(~0u, ts1, 2);
        l0 = l0*al0 + ts0;
        l1 = l1*al1 + ts1;
        #pragma unroll
        for (int ni = 0; ni < 10; ni++) {
            oa[ni][0] *= al0; oa[ni][1] *= al0;
            oa[ni][2] *= al1; oa[ni][3] *= al1;
        }

        // O += P @ V  (P fragments via intra-quad shuffles)
        #pragma unroll
        for (int ks = 0; ks < 8; ks++) {
            int src = (lane & ~3) | (t4 >> 1);
            float v0 = __shfl_sync(~0u, s[ks][0], src);
            float v1 = __shfl_sync(~0u, s[ks][1], src);
            float v2 = __shfl_sync(~0u, s[ks][2], src);
            float v3 = __shfl_sync(~0u, s[ks][3], src);
            float w0 = __shfl_sync(~0u, s[ks][0], src + 2);
            float w1 = __shfl_sync(~0u, s[ks][1], src + 2);
            float w2 = __shfl_sync(~0u, s[ks][2], src + 2);
            float w3 = __shfl_sync(~0u, s[ks][3], src + 2);
            bool odd = t4 & 1;
            uint32_t a0 = fu(odd ? v1 : v0);
            uint32_t a1 = fu(odd ? v3 : v2);
            uint32_t a2 = fu(odd ? w1 : w0);
            uint32_t a3 = fu(odd ? w3 : w2);
            #pragma unroll
            for (int ni = 0; ni < 10; ni++) {
                uint32_t b0 = fu(Vc[(t4 + 8*ks)*VP + gr + 8*ni]);
                uint32_t b1 = fu(Vc[(t4 + 4 + 8*ks)*VP + gr + 8*ni]);
                mma8(oa[ni], a0, a1, a2, a3, b0, b1);
            }
        }
        __syncthreads();
    }

    float inv0 = 1.f / l0, inv1 = 1.f / l1;
    float* Ob = O + ((size_t)(b*HW + q0 + w*16))*CCH + h*DH;
    #pragma unroll
    for (int ni = 0; ni < 10; ni++) {
        float2 lo = make_float2(oa[ni][0]*inv0, oa[ni][1]*inv0);
        float2 hi = make_float2(oa[ni][2]*inv1, oa[ni][3]*inv1);
        *(float2*)(Ob + (size_t)gr*CCH + 8*ni + 2*t4) = lo;
        *(float2*)(Ob + (size_t)(gr+8)*CCH + 8*ni + 2*t4) = hi;
    }
}

// ---------------- small-SK attention (cross-attn, SK=77) ----------------
__global__ void attention(const float* __restrict__ Q, const float* __restrict__ Kp,
                          const float* __restrict__ V, float* __restrict__ O,
                          int SK, int qs, int ks, int vs, int os) {
    int q = blockIdx.x % HW;
    int h = (blockIdx.x / HW) % NH;
    int b = blockIdx.x / (HW*NH);
    int tid = threadIdx.x;

    __shared__ float sq[DH];
    __shared__ float sp[128];
    __shared__ float red[128];

    const float scale = rsqrtf((float)DH);
    const float* qrow = Q + ((size_t)(b*HW + q))*qs + h*DH;
    if (tid < DH) sq[tid] = qrow[tid];
    __syncthreads();

    float lmax = -1e30f;
    if (tid < SK) {
        const float* krow = Kp + ((size_t)(b*SK + tid))*ks + h*DH;
        float s = 0.f;
        #pragma unroll 16
        for (int d = 0; d < DH; d++) s += sq[d] * krow[d];
        s *= scale;
        sp[tid] = s;
        lmax = s;
    }
    red[tid] = lmax; __syncthreads();
    for (int o = 64; o > 0; o >>= 1) {
        if (tid < o) red[tid] = fmaxf(red[tid], red[tid+o]);
        __syncthreads();
    }
    float m = red[0];
    __syncthreads();
    float lsum = 0.f;
    if (tid < SK) {
        float e = __expf(sp[tid] - m);
        sp[tid] = e; lsum = e;
    }
    red[tid] = lsum; __syncthreads();
    for (int o = 64; o > 0; o >>= 1) {
        if (tid < o) red[tid] += red[tid+o];
        __syncthreads();
    }
    float inv = 1.f / red[0];
    __syncthreads();

    if (tid < DH) {
        float o = 0.f;
        for (int j = 0; j < SK; j++)
            o += sp[j] * V[((size_t)(b*SK + j))*vs + h*DH + tid];
        O[((size_t)(b*HW + q))*os + h*DH + tid] = o * inv;
    }
}

// ---------------- GeGLU (float4) ----------------
__global__ void geglu(const float* __restrict__ ff, float* __restrict__ out) {
    int idx = blockIdx.x * 256 + threadIdx.x;
    if (idx >= NB*HW*CCH) return;    // NB*HW*4*CCH/4
    int m = idx / CCH;
    int j = idx % CCH;
    float4 a = *(const float4*)(ff + (size_t)m*8*CCH + j*4);
    float4 g = *(const float4*)(ff + (size_t)m*8*CCH + 4*CCH + j*4);
    float4 r;
    r.x = a.x * 0.5f * g.x * (1.f + erff(g.x * 0.70710678118654752f));
    r.y = a.y * 0.5f * g.y * (1.f + erff(g.y * 0.70710678118654752f));
    r.z = a.z * 0.5f * g.z * (1.f + erff(g.z * 0.70710678118654752f));
    r.w = a.w * 0.5f * g.w * (1.f + erff(g.w * 0.70710678118654752f));
    *(float4*)(out + (size_t)m*4*CCH + j*4) = r;
}

// ---------------- final transpose + residual (32x32 smem tile) ----------------
__global__ void final_add(const float* __restrict__ tmp, const float* __restrict__ xin,
                          float* __restrict__ out) {
    __shared__ float tile[32][33];
    int n = blockIdx.z;
    int p0 = blockIdx.x*32, c0 = blockIdx.y*32;
    int tx = threadIdx.x, ty = threadIdx.y;
    #pragma unroll
    for (int i = 0; i < 4; i++) {
        int p = p0 + ty + i*8;
        tile[ty + i*8][tx] = tmp[((size_t)n*HW + p)*CCH + c0 + tx];
    }
    __syncthreads();
    #pragma unroll
    for (int i = 0; i < 4; i++) {
        int c = c0 + ty + i*8;
        size_t o = ((size_t)n*CCH + c)*HW + p0 + tx;
        out[o] = tile[tx][ty + i*8] + xin[o];
    }
}

// ---------------- host launch ----------------
extern "C" void kernel_launch(void* const* d_in, const int* in_sizes, int n_in,
                              void* d_out, int out_size) {
    const float* x        = (const float*)d_in[0];
    const float* context  = (const float*)d_in[1];
    const float* gn_s     = (const float*)d_in[2];
    const float* gn_b     = (const float*)d_in[3];
    const float* conv1_w  = (const float*)d_in[4];
    const float* conv1_b  = (const float*)d_in[5];
    const float* ln1_s    = (const float*)d_in[6];
    const float* ln1_b    = (const float*)d_in[7];
    const float* sa_in_w  = (const float*)d_in[8];
    const float* sa_out_w = (const float*)d_in[9];
    const float* sa_out_b = (const float*)d_in[10];
    const float* ln2_s    = (const float*)d_in[11];
    const float* ln2_b    = (const float*)d_in[12];
    const float* ca_q_w   = (const float*)d_in[13];
    const float* ca_k_w   = (const float*)d_in[14];
    const float* ca_v_w   = (const float*)d_in[15];
    const float* ca_out_w = (const float*)d_in[16];
    const float* ca_out_b = (const float*)d_in[17];
    const float* ln3_s    = (const float*)d_in[18];
    const float* ln3_b    = (const float*)d_in[19];
    const float* lin1_w   = (const float*)d_in[20];
    const float* lin1_b   = (const float*)d_in[21];
    const float* lin2_w   = (const float*)d_in[22];
    const float* lin2_b   = (const float*)d_in[23];
    const float* co_w     = (const float*)d_in[24];
    const float* co_b     = (const float*)d_in[25];
    float* out = (float*)d_out;

    float *gn, *xseq, *t, *qkv, *attn, *kctx, *vctx, *ff, *ffg, *tmp;
    cudaGetSymbolAddress((void**)&gn,   g_gn);
    cudaGetSymbolAddress((void**)&xseq, g_xseq);
    cudaGetSymbolAddress((void**)&t,    g_t);
    cudaGetSymbolAddress((void**)&qkv,  g_qkv);
    cudaGetSymbolAddress((void**)&attn, g_attn);
    cudaGetSymbolAddress((void**)&kctx, g_kctx);
    cudaGetSymbolAddress((void**)&vctx, g_vctx);
    cudaGetSymbolAddress((void**)&ff,   g_ff);
    cudaGetSymbolAddress((void**)&ffg,  g_ffg);
    cudaGetSymbolAddress((void**)&tmp,  g_tmp);

    cudaFuncSetAttribute(gemm_tf32<true>,  cudaFuncAttributeMaxDynamicSharedMemorySize, SMEM_BYTES);
    cudaFuncSetAttribute(gemm_tf32<false>, cudaFuncAttributeMaxDynamicSharedMemorySize, SMEM_BYTES);
    cudaFuncSetAttribute(flash_attn, cudaFuncAttributeMaxDynamicSharedMemorySize, FLASH_SMEM);

    const int M = NB * HW;   // 8192
    dim3 blk(256);
    dim3 tblk(32, 8);
    dim3 tgrid(HW/32, CCH/32, NB);
    auto gxy = [](int N_, int M_) { return dim3((N_+127)/128, (M_+127)/128, 1); };

    // 1. GroupNorm + transpose
    gn_stats<<<NB*GRP, 256>>>(x);
    gn_apply<<<tgrid, tblk>>>(x, gn_s, gn_b);

    // 2. conv1
    gemm_tf32<true><<<gxy(CCH, M), blk, SMEM_BYTES>>>(gn, CCH, 0,0, conv1_w, CCH, 0,0,
                                          conv1_b, nullptr, xseq, CCH, 0,0, M, CCH, CCH);

    // 3. self-attention (fused flash)
    layernorm<<<M, 160>>>(xseq, ln1_s, ln1_b, t);
    gemm_tf32<false><<<gxy(3*CCH, M), blk, SMEM_BYTES>>>(t, CCH, 0,0, sa_in_w, 3*CCH, 0,0,
                                             nullptr, nullptr, qkv, 3*CCH, 0,0, M, 3*CCH, CCH);
    flash_attn<<<dim3(HW/128, NB*NH), 256, FLASH_SMEM>>>(qkv, attn);
    gemm_tf32<false><<<gxy(CCH, M), blk, SMEM_BYTES>>>(attn, CCH, 0,0, sa_out_w, CCH, 0,0,
                                           sa_out_b, xseq, xseq, CCH, 0,0, M, CCH, CCH);

    // 4. cross-attention
    layernorm<<<M, 160>>>(xseq, ln2_s, ln2_b, t);
    gemm_tf32<false><<<gxy(CCH, M), blk, SMEM_BYTES>>>(t, CCH, 0,0, ca_q_w, CCH, 0,0,
                                           nullptr, nullptr, qkv, CCH, 0,0, M, CCH, CCH);
    gemm_tf32<false><<<gxy(CCH, NB*SKCTX), blk, SMEM_BYTES>>>(context, DCTX, 0,0, ca_k_w, CCH, 0,0,
                                                  nullptr, nullptr, kctx, CCH, 0,0, NB*SKCTX, CCH, DCTX);
    gemm_tf32<false><<<gxy(CCH, NB*SKCTX), blk, SMEM_BYTES>>>(context, DCTX, 0,0, ca_v_w, CCH, 0,0,
                                                  nullptr, nullptr, vctx, CCH, 0,0, NB*SKCTX, CCH, DCTX);
    attention<<<NB*NH*HW, 128>>>(qkv, kctx, vctx, attn, SKCTX, CCH, CCH, CCH, CCH);
    gemm_tf32<false><<<gxy(CCH, M), blk, SMEM_BYTES>>>(attn, CCH, 0,0, ca_out_w, CCH, 0,0,
                                           ca_out_b, xseq, xseq, CCH, 0,0, M, CCH, CCH);

    // 5. GeGLU FFN
    layernorm<<<M, 160>>>(xseq, ln3_s, ln3_b, t);
    gemm_tf32<false><<<gxy(8*CCH, M), blk, SMEM_BYTES>>>(t, CCH, 0,0, lin1_w, 8*CCH, 0,0,
                                             lin1_b, nullptr, ff, 8*CCH, 0,0, M, 8*CCH, CCH);
    geglu<<<(NB*HW*CCH + 255)/256, 256>>>(ff, ffg);
    gemm_tf32<false><<<gxy(CCH, M), blk, SMEM_BYTES>>>(ffg, 4*CCH, 0,0, lin2_w, CCH, 0,0,
                                           lin2_b, xseq, xseq, CCH, 0,0, M, CCH, 4*CCH);

    // 6. final conv + long residual (transposed epilogue)
    gemm_tf32<true><<<gxy(CCH, M), blk, SMEM_BYTES>>>(xseq, CCH, 0,0, co_w, CCH, 0,0,
                                          co_b, nullptr, tmp, CCH, 0,0, M, CCH, CCH);
    final_add<<<tgrid, tblk>>>(tmp, x, out);
}

// round 6
// speedup vs baseline: 10.0481x; 1.1711x over previous
#include <cuda_runtime.h>
#include <cuda_fp16.h>
#include <math.h>
#include <stdint.h>

#define NB    8
#define CCH   640
#define HW    1024
#define NH    8
#define DH    80
#define DCTX  512
#define GRP   32
#define CPG   20
#define SKCTX 77

// ---------------- fp32 scratch ----------------
__device__ float  g_xseq [NB*HW*CCH];
__device__ float  g_qkv  [NB*HW*3*CCH];
__device__ float  g_kctx [NB*SKCTX*CCH];
__device__ float  g_vctx [NB*SKCTX*CCH];
__device__ float  g_tmp  [NB*HW*CCH];
__device__ float  g_gnstat[NB*GRP*2];
// ---------------- fp16 scratch ----------------
__device__ __half h_gn  [NB*HW*CCH];
__device__ __half h_t   [NB*HW*CCH];
__device__ __half h_attn[NB*HW*CCH];
__device__ __half h_ctx [NB*SKCTX*DCTX];
__device__ __half h_ff  [NB*HW*8*CCH];
__device__ __half h_ffg [NB*HW*4*CCH];
__device__ __half h_x   [NB*HW*CCH];
__device__ __half h_w   [8847360];       // all weights, fp16, [N,K]

// ---------------- GroupNorm stats ----------------
__global__ void gn_stats(const float* __restrict__ x) {
    int ng = blockIdx.x;
    int n = ng / GRP, g = ng % GRP;
    const float4* base = (const float4*)(x + ((size_t)n*CCH + (size_t)g*CPG) * HW);
    float s = 0.f, s2 = 0.f;
    for (int i = threadIdx.x; i < CPG*HW/4; i += 256) {
        float4 v = base[i];
        s  += v.x + v.y + v.z + v.w;
        s2 += v.x*v.x + v.y*v.y + v.z*v.z + v.w*v.w;
    }
    __shared__ float rs[256], rq[256];
    rs[threadIdx.x] = s; rq[threadIdx.x] = s2;
    __syncthreads();
    for (int o = 128; o > 0; o >>= 1) {
        if (threadIdx.x < o) { rs[threadIdx.x] += rs[threadIdx.x+o]; rq[threadIdx.x] += rq[threadIdx.x+o]; }
        __syncthreads();
    }
    if (threadIdx.x == 0) {
        float inv_n = 1.f / (float)(CPG*HW);
        float mu  = rs[0] * inv_n;
        float var = rq[0] * inv_n - mu*mu;
        g_gnstat[ng*2]   = mu;
        g_gnstat[ng*2+1] = rsqrtf(var + 1e-6f);
    }
}

// ---------------- GroupNorm apply + transpose -> fp16 [n,p,c] ----------------
__global__ void gn_apply(const float* __restrict__ x,
                         const float* __restrict__ s, const float* __restrict__ b) {
    __shared__ float tile[32][33];
    int n = blockIdx.z;
    int p0 = blockIdx.x*32, c0 = blockIdx.y*32;
    int tx = threadIdx.x, ty = threadIdx.y;
    #pragma unroll
    for (int i = 0; i < 4; i++) {
        int c = c0 + ty + i*8;
        int ng = n*GRP + c / CPG;
        float mu = g_gnstat[ng*2], is = g_gnstat[ng*2+1];
        float v = x[((size_t)n*CCH + c)*HW + p0 + tx];
        tile[ty + i*8][tx] = (v - mu) * is * s[c] + b[c];
    }
    __syncthreads();
    #pragma unroll
    for (int i = 0; i < 4; i++) {
        int p = p0 + ty + i*8;
        h_gn[((size_t)n*HW + p)*CCH + c0 + tx] = __float2half(tile[tx][ty + i*8]);
    }
}

// ---------------- weight transpose+convert fp32 [K,N] -> fp16 [N,K] ----------------
__global__ void wtrans_h(const float* __restrict__ src, __half* __restrict__ dst, int K, int N) {
    __shared__ float t[32][33];
    int k0 = blockIdx.y*32, n0 = blockIdx.x*32;
    int tx = threadIdx.x, ty = threadIdx.y;
    #pragma unroll
    for (int i = 0; i < 4; i++)
        t[ty + i*8][tx] = src[(size_t)(k0 + ty + i*8)*N + n0 + tx];
    __syncthreads();
    #pragma unroll
    for (int i = 0; i < 4; i++)
        dst[(size_t)(n0 + ty + i*8)*K + k0 + tx] = __float2half(t[tx][ty + i*8]);
}

// ---------------- straight convert fp32 -> fp16 ----------------
__global__ void cvt_h(const float* __restrict__ src, __half* __restrict__ dst, int n4) {
    int i = blockIdx.x * 256 + threadIdx.x;
    if (i >= n4) return;
    float4 v = ((const float4*)src)[i];
    __half2 p0 = __floats2half2_rn(v.x, v.y);
    __half2 p1 = __floats2half2_rn(v.z, v.w);
    union { uint2 u; __half2 h[2]; } pk; pk.h[0] = p0; pk.h[1] = p1;
    ((uint2*)dst)[i] = pk.u;
}

// ---------------- LayerNorm fp32 in -> fp16 out ----------------
__global__ __launch_bounds__(160)
void layernorm(const float* __restrict__ in,
               const float* __restrict__ s, const float* __restrict__ b,
               __half* __restrict__ out) {
    int row = blockIdx.x;
    int tid = threadIdx.x;
    const float4* r4 = (const float4*)(in + (size_t)row * CCH);
    float4 v = r4[tid];
    float sum = v.x + v.y + v.z + v.w;
    float sq  = v.x*v.x + v.y*v.y + v.z*v.z + v.w*v.w;
    #pragma unroll
    for (int o = 16; o > 0; o >>= 1) {
        sum += __shfl_xor_sync(~0u, sum, o);
        sq  += __shfl_xor_sync(~0u, sq,  o);
    }
    __shared__ float ws[5], wq[5];
    int w = tid >> 5;
    if ((tid & 31) == 0) { ws[w] = sum; wq[w] = sq; }
    __syncthreads();
    sum = ws[0] + ws[1] + ws[2] + ws[3] + ws[4];
    sq  = wq[0] + wq[1] + wq[2] + wq[3] + wq[4];
    float mu  = sum / (float)CCH;
    float inv = rsqrtf(sq / (float)CCH - mu*mu + 1e-5f);
    float4 sc = ((const float4*)s)[tid];
    float4 bb = ((const float4*)b)[tid];
    union { uint2 u; __half2 h[2]; } pk;
    pk.h[0] = __floats2half2_rn((v.x - mu) * inv * sc.x + bb.x, (v.y - mu) * inv * sc.y + bb.y);
    pk.h[1] = __floats2half2_rn((v.z - mu) * inv * sc.z + bb.z, (v.w - mu) * inv * sc.w + bb.w);
    ((uint2*)(out + (size_t)row * CCH))[tid] = pk.u;
}

// ---------------- mma / cp.async helpers ----------------
__device__ __forceinline__ void mma16h(float c[4], uint32_t a0, uint32_t a1, uint32_t a2, uint32_t a3,
                                       uint32_t b0, uint32_t b1) {
    asm volatile("mma.sync.aligned.m16n8k16.row.col.f32.f16.f16.f32 "
        "{%0,%1,%2,%3}, {%4,%5,%6,%7}, {%8,%9}, {%0,%1,%2,%3};"
        : "+f"(c[0]), "+f"(c[1]), "+f"(c[2]), "+f"(c[3])
        : "r"(a0), "r"(a1), "r"(a2), "r"(a3), "r"(b0), "r"(b1));
}
__device__ __forceinline__ void mma8(float c[4], uint32_t a0, uint32_t a1, uint32_t a2, uint32_t a3,
                                     uint32_t b0, uint32_t b1) {
    asm volatile("mma.sync.aligned.m16n8k8.row.col.f32.tf32.tf32.f32 "
        "{%0,%1,%2,%3}, {%4,%5,%6,%7}, {%8,%9}, {%0,%1,%2,%3};"
        : "+f"(c[0]), "+f"(c[1]), "+f"(c[2]), "+f"(c[3])
        : "r"(a0), "r"(a1), "r"(a2), "r"(a3), "r"(b0), "r"(b1));
}
__device__ __forceinline__ void cpa16(void* dst, const void* src, bool valid) {
    uint32_t d = (uint32_t)__cvta_generic_to_shared(dst);
    int sz = valid ? 16 : 0;
    asm volatile("cp.async.cg.shared.global [%0], [%1], 16, %2;" :: "r"(d), "l"(src), "r"(sz));
}
#define CP_COMMIT() asm volatile("cp.async.commit_group;")
#define CP_WAIT1()  asm volatile("cp.async.wait_group 1;")
__device__ __forceinline__ uint32_t fu(float f) { return __float_as_uint(f); }

// ---------------- fp16 GEMM: 128x128x64, double-buffered cp.async ----------------
// A [M,K] fp16 row-major, B [N,K] fp16 row-major. C = A@B^T (+bias)(+res), fp32 and/or fp16 out.
#define RS36 36                     // row stride in u32 (64 halves data + 4 u32 pad)
#define BUFU (128*RS36)             // u32 per buffer
#define GEMM_SMEM (4*BUFU*4)        // 73728 B
__global__ __launch_bounds__(256)
void gemm_h(const __half* __restrict__ A, int lda,
            const __half* __restrict__ B,
            const float* __restrict__ bias,
            const float* __restrict__ res,
            float* __restrict__ C, __half* __restrict__ Ch, int ldc,
            int M, int N, int K) {
    extern __shared__ uint32_t sm[];
    uint32_t* As = sm;              // [2][BUFU]
    uint32_t* Bs = sm + 2*BUFU;

    int tid = threadIdx.x;
    int lane = tid & 31, warp = tid >> 5;
    int gr = lane >> 2, t4 = lane & 3;
    int wm = (warp >> 2) * 64, wn = (warp & 3) * 32;
    int bm = blockIdx.y * 128, bn = blockIdx.x * 128;

    auto stage = [&](int kt, int buf) {
        #pragma unroll
        for (int i = 0; i < 4; i++) {           // A: 128 rows x 128B
            int c = tid + i*256;
            int row = c >> 3, seg = c & 7;
            int gm = bm + row;
            cpa16(As + buf*BUFU + row*RS36 + seg*4,
                  A + ((size_t)(gm < M ? gm : 0))*lda + kt*64 + seg*8, gm < M);
        }
        #pragma unroll
        for (int i = 0; i < 4; i++) {           // B: 128 rows x 128B
            int c = tid + i*256;
            int row = c >> 3, seg = c & 7;
            int gn = bn + row;
            cpa16(Bs + buf*BUFU + row*RS36 + seg*4,
                  B + ((size_t)(gn < N ? gn : 0))*K + kt*64 + seg*8, gn < N);
        }
    };

    float acc[4][4][4];
    #pragma unroll
    for (int i = 0; i < 4; i++)
        #pragma unroll
        for (int j = 0; j < 4; j++)
            #pragma unroll
            for (int r = 0; r < 4; r++) acc[i][j][r] = 0.f;

    int nk = K >> 6;
    stage(0, 0);
    CP_COMMIT();

    for (int t = 0; t < nk; t++) {
        if (t + 1 < nk) stage(t+1, (t+1) & 1);
        CP_COMMIT();
        CP_WAIT1();
        __syncthreads();

        const uint32_t* A_s = As + (t & 1)*BUFU;
        const uint32_t* B_s = Bs + (t & 1)*BUFU;

        #pragma unroll
        for (int ks = 0; ks < 4; ks++) {        // 4 x k16
            uint32_t af[4][4], bf[4][2];
            #pragma unroll
            for (int mi = 0; mi < 4; mi++) {
                int m0 = wm + mi*16 + gr;
                af[mi][0] = A_s[m0*RS36 + ks*8 + t4];
                af[mi][1] = A_s[(m0+8)*RS36 + ks*8 + t4];
                af[mi][2] = A_s[m0*RS36 + ks*8 + t4 + 4];
                af[mi][3] = A_s[(m0+8)*RS36 + ks*8 + t4 + 4];
            }
            #pragma unroll
            for (int ni = 0; ni < 4; ni++) {
                int n0 = wn + ni*8 + gr;
                bf[ni][0] = B_s[n0*RS36 + ks*8 + t4];
                bf[ni][1] = B_s[n0*RS36 + ks*8 + t4 + 4];
            }
            #pragma unroll
            for (int mi = 0; mi < 4; mi++)
                #pragma unroll
                for (int ni = 0; ni < 4; ni++)
                    mma16h(acc[mi][ni], af[mi][0], af[mi][1], af[mi][2], af[mi][3],
                           bf[ni][0], bf[ni][1]);
        }
        __syncthreads();
    }

    #pragma unroll
    for (int mi = 0; mi < 4; mi++) {
        #pragma unroll
        for (int ni = 0; ni < 4; ni++) {
            int col0 = bn + wn + ni*8 + t4*2;
            #pragma unroll
            for (int half_r = 0; half_r < 2; half_r++) {
                int row = bm + wm + mi*16 + gr + half_r*8;
                if (row >= M) continue;
                float v0 = acc[mi][ni][half_r*2 + 0];
                float v1 = acc[mi][ni][half_r*2 + 1];
                if (bias) { v0 += bias[col0]; v1 += bias[col0+1]; }
                if (res) {
                    const float* rp = res + (size_t)row*ldc + col0;
                    v0 += rp[0]; v1 += rp[1];
                }
                if (C) *(float2*)(C + (size_t)row*ldc + col0) = make_float2(v0, v1);
                if (Ch) *(__half2*)(Ch + (size_t)row*ldc + col0) = __floats2half2_rn(v0, v1);
            }
        }
    }
}

// ---------------- fused flash self-attention (tf32 mma, fp32 qkv in, fp16 out) ----------------
#define KP 84
#define VP 88
#define FLASH_SMEM ((2*64*KP + 2*64*VP)*4)
__global__ __launch_bounds__(256)
void flash_attn(const float* __restrict__ QKV, __half* __restrict__ O) {
    constexpr int LD = 3*CCH;
    extern __shared__ float smf[];
    float* Ks = smf;
    float* Vs = smf + 2*64*KP;

    int tid = threadIdx.x, lane = tid & 31, w = tid >> 5;
    int z = blockIdx.y;
    int b = z >> 3, h = z & 7;
    int q0 = blockIdx.x * 128;
    int gr = lane >> 2, t4 = lane & 3;

    const float* Qb = QKV + ((size_t)b*HW)*LD + h*DH;
    const float* Kb = QKV + ((size_t)b*HW)*LD + CCH + h*DH;
    const float* Vb = QKV + ((size_t)b*HW)*LD + 2*CCH + h*DH;

    auto stage = [&](int kt, int buf) {
        int row = tid >> 2;
        int cc  = (tid & 3) * 20;
        const float* kg = Kb + (size_t)(kt*64 + row)*LD + cc;
        const float* vg = Vb + (size_t)(kt*64 + row)*LD + cc;
        float* ksm = Ks + buf*64*KP + row*KP + cc;
        float* vsm = Vs + buf*64*VP + row*VP + cc;
        #pragma unroll
        for (int i = 0; i < 5; i++) {
            cpa16(ksm + i*4, kg + i*4, true);
            cpa16(vsm + i*4, vg + i*4, true);
        }
    };

    stage(0, 0);
    CP_COMMIT();

    const float qscale = 0.1118033988749895f;
    float qf[10][4];
    {
        const float* qp  = Qb + (size_t)(q0 + w*16 + gr)*LD;
        const float* qp8 = qp + 8*LD;
        #pragma unroll
        for (int ks = 0; ks < 10; ks++) {
            qf[ks][0] = qp [ks*8 + t4]     * qscale;
            qf[ks][1] = qp8[ks*8 + t4]     * qscale;
            qf[ks][2] = qp [ks*8 + t4 + 4] * qscale;
            qf[ks][3] = qp8[ks*8 + t4 + 4] * qscale;
        }
    }

    float m0v = -1e30f, m1v = -1e30f, l0 = 0.f, l1 = 0.f;
    float oa[10][4];
    #pragma unroll
    for (int ni = 0; ni < 10; ni++) { oa[ni][0]=oa[ni][1]=oa[ni][2]=oa[ni][3]=0.f; }

    for (int kt = 0; kt < 16; kt++) {
        if (kt + 1 < 16) stage(kt+1, (kt+1) & 1);
        CP_COMMIT();
        CP_WAIT1();
        __syncthreads();
        const float* Kc = Ks + (kt & 1)*64*KP;
        const float* Vc = Vs + (kt & 1)*64*VP;

        float s[8][4];
        #pragma unroll
        for (int ni = 0; ni < 8; ni++) { s[ni][0]=s[ni][1]=s[ni][2]=s[ni][3]=0.f; }
        #pragma unroll
        for (int ks = 0; ks < 10; ks++) {
            #pragma unroll
            for (int ni = 0; ni < 8; ni++) {
                uint32_t b0 = fu(Kc[(gr + 8*ni)*KP + ks*8 + t4]);
                uint32_t b1 = fu(Kc[(gr + 8*ni)*KP + ks*8 + t4 + 4]);
                mma8(s[ni], fu(qf[ks][0]), fu(qf[ks][1]), fu(qf[ks][2]), fu(qf[ks][3]), b0, b1);
            }
        }

        float tm0 = -1e30f, tm1 = -1e30f;
        #pragma unroll
        for (int ni = 0; ni < 8; ni++) {
            tm0 = fmaxf(tm0, fmaxf(s[ni][0], s[ni][1]));
            tm1 = fmaxf(tm1, fmaxf(s[ni][2], s[ni][3]));
        }
        tm0 = fmaxf(tm0, __shfl_xor_sync(~0u, tm0, 1));
        tm0 = fmaxf(tm0, __shfl_xor_sync(~0u, tm0, 2));
        tm1 = fmaxf(tm1, __shfl_xor_sync(~0u, tm1, 1));
        tm1 = fmaxf(tm1, __shfl_xor_sync(~0u, tm1, 2));
        float mn0 = fmaxf(m0v, tm0), mn1 = fmaxf(m1v, tm1);
        float al0 = __expf(m0v - mn0), al1 = __expf(m1v - mn1);
        m0v = mn0; m1v = mn1;
        float ts0 = 0.f, ts1 = 0.f;
        #pragma unroll
        for (int ni = 0; ni < 8; ni++) {
            s[ni][0] = __expf(s[ni][0] - mn0);
            s[ni][1] = __expf(s[ni][1] - mn0);
            s[ni][2] = __expf(s[ni][2] - mn1);
            s[ni][3] = __expf(s[ni][3] - mn1);
            ts0 += s[ni][0] + s[ni][1];
            ts1 += s[ni][2] + s[ni][3];
        }
        ts0 += __shfl_xor_sync(~0u, ts0, 1); ts0 += __shfl_xor_sync(~0u, ts0, 2);
        ts1 += __shfl_xor_sync(~0u, ts1, 1); ts1 += __shfl_xor_sync(~0u, ts1, 2);
        l0 = l0*al0 + ts0;
        l1 = l1*al1 + ts1;
        #pragma unroll
        for (int ni = 0; ni < 10; ni++) {
            oa[ni][0] *= al0; oa[ni][1] *= al0;
            oa[ni][2] *= al1; oa[ni][3] *= al1;
        }

        #pragma unroll
        for (int ks = 0; ks < 8; ks++) {
            int src = (lane & ~3) | (t4 >> 1);
            float v0 = __shfl_sync(~0u, s[ks][0], src);
            float v1 = __shfl_sync(~0u, s[ks][1], src);
            float v2 = __shfl_sync(~0u, s[ks][2], src);
            float v3 = __shfl_sync(~0u, s[ks][3], src);
            float w0 = __shfl_sync(~0u, s[ks][0], src + 2);
            float w1 = __shfl_sync(~0u, s[ks][1], src + 2);
            float w2 = __shfl_sync(~0u, s[ks][2], src + 2);
            float w3 = __shfl_sync(~0u, s[ks][3], src + 2);
            bool odd = t4 & 1;
            uint32_t a0 = fu(odd ? v1 : v0);
            uint32_t a1 = fu(odd ? v3 : v2);
            uint32_t a2 = fu(odd ? w1 : w0);
            uint32_t a3 = fu(odd ? w3 : w2);
            #pragma unroll
            for (int ni = 0; ni < 10; ni++) {
                uint32_t b0 = fu(Vc[(t4 + 8*ks)*VP + gr + 8*ni]);
                uint32_t b1 = fu(Vc[(t4 + 4 + 8*ks)*VP + gr + 8*ni]);
                mma8(oa[ni], a0, a1, a2, a3, b0, b1);
            }
        }
        __syncthreads();
    }

    float inv0 = 1.f / l0, inv1 = 1.f / l1;
    __half* Ob = O + ((size_t)(b*HW + q0 + w*16))*CCH + h*DH;
    #pragma unroll
    for (int ni = 0; ni < 10; ni++) {
        *(__half2*)(Ob + (size_t)gr*CCH + 8*ni + 2*t4) =
            __floats2half2_rn(oa[ni][0]*inv0, oa[ni][1]*inv0);
        *(__half2*)(Ob + (size_t)(gr+8)*CCH + 8*ni + 2*t4) =
            __floats2half2_rn(oa[ni][2]*inv1, oa[ni][3]*inv1);
    }
}

// ---------------- small-SK attention (cross-attn, SK=77), fp16 out ----------------
__global__ void attention(const float* __restrict__ Q, const float* __restrict__ Kp,
                          const float* __restrict__ V, __half* __restrict__ O,
                          int SK, int qs, int ks, int vs, int os) {
    int q = blockIdx.x % HW;
    int h = (blockIdx.x / HW) % NH;
    int b = blockIdx.x / (HW*NH);
    int tid = threadIdx.x;

    __shared__ float sq[DH];
    __shared__ float sp[128];
    __shared__ float red[128];

    const float scale = rsqrtf((float)DH);
    const float* qrow = Q + ((size_t)(b*HW + q))*qs + h*DH;
    if (tid < DH) sq[tid] = qrow[tid];
    __syncthreads();

    float lmax = -1e30f;
    if (tid < SK) {
        const float* krow = Kp + ((size_t)(b*SK + tid))*ks + h*DH;
        float s = 0.f;
        #pragma unroll 16
        for (int d = 0; d < DH; d++) s += sq[d] * krow[d];
        s *= scale;
        sp[tid] = s;
        lmax = s;
    }
    red[tid] = lmax; __syncthreads();
    for (int o = 64; o > 0; o >>= 1) {
        if (tid < o) red[tid] = fmaxf(red[tid], red[tid+o]);
        __syncthreads();
    }
    float m = red[0];
    __syncthreads();
    float lsum = 0.f;
    if (tid < SK) {
        float e = __expf(sp[tid] - m);
        sp[tid] = e; lsum = e;
    }
    red[tid] = lsum; __syncthreads();
    for (int o = 64; o > 0; o >>= 1) {
        if (tid < o) red[tid] += red[tid+o];
        __syncthreads();
    }
    float inv = 1.f / red[0];
    __syncthreads();

    if (tid < DH) {
        float o = 0.f;
        for (int j = 0; j < SK; j++)
            o += sp[j] * V[((size_t)(b*SK + j))*vs + h*DH + tid];
        O[((size_t)(b*HW + q))*os + h*DH + tid] = __float2half(o * inv);
    }
}

// ---------------- GeGLU: fp16 in, fp16 out ----------------
__global__ void geglu(const __half* __restrict__ ff, __half* __restrict__ out) {
    int idx = blockIdx.x * 256 + threadIdx.x;
    if (idx >= NB*HW*CCH) return;      // 4 elems per thread
    int m = idx / CCH;
    int j = idx % CCH;
    union { uint2 u; __half2 h[2]; } av, gv, rv;
    av.u = *(const uint2*)(ff + (size_t)m*8*CCH + j*4);
    gv.u = *(const uint2*)(ff + (size_t)m*8*CCH + 4*CCH + j*4);
    float a0 = __half2float(av.h[0].x), a1 = __half2float(av.h[0].y);
    float a2 = __half2float(av.h[1].x), a3 = __half2float(av.h[1].y);
    float g0 = __half2float(gv.h[0].x), g1 = __half2float(gv.h[0].y);
    float g2 = __half2float(gv.h[1].x), g3 = __half2float(gv.h[1].y);
    const float is2 = 0.70710678118654752f;
    rv.h[0] = __floats2half2_rn(a0 * 0.5f * g0 * (1.f + erff(g0*is2)),
                                a1 * 0.5f * g1 * (1.f + erff(g1*is2)));
    rv.h[1] = __floats2half2_rn(a2 * 0.5f * g2 * (1.f + erff(g2*is2)),
                                a3 * 0.5f * g3 * (1.f + erff(g3*is2)));
    *(uint2*)(out + (size_t)m*4*CCH + j*4) = rv.u;
}

// ---------------- final transpose + residual ----------------
__global__ void final_add(const float* __restrict__ tmp, const float* __restrict__ xin,
                          float* __restrict__ out) {
    __shared__ float tile[32][33];
    int n = blockIdx.z;
    int p0 = blockIdx.x*32, c0 = blockIdx.y*32;
    int tx = threadIdx.x, ty = threadIdx.y;
    #pragma unroll
    for (int i = 0; i < 4; i++) {
        int p = p0 + ty + i*8;
        tile[ty + i*8][tx] = tmp[((size_t)n*HW + p)*CCH + c0 + tx];
    }
    __syncthreads();
    #pragma unroll
    for (int i = 0; i < 4; i++) {
        int c = c0 + ty + i*8;
        size_t o = ((size_t)n*CCH + c)*HW + p0 + tx;
        out[o] = tile[tx][ty + i*8] + xin[o];
    }
}

// ---------------- host launch ----------------
extern "C" void kernel_launch(void* const* d_in, const int* in_sizes, int n_in,
                              void* d_out, int out_size) {
    const float* x        = (const float*)d_in[0];
    const float* context  = (const float*)d_in[1];
    const float* gn_s     = (const float*)d_in[2];
    const float* gn_b     = (const float*)d_in[3];
    const float* conv1_w  = (const float*)d_in[4];
    const float* conv1_b  = (const float*)d_in[5];
    const float* ln1_s    = (const float*)d_in[6];
    const float* ln1_b    = (const float*)d_in[7];
    const float* sa_in_w  = (const float*)d_in[8];
    const float* sa_out_w = (const float*)d_in[9];
    const float* sa_out_b = (const float*)d_in[10];
    const float* ln2_s    = (const float*)d_in[11];
    const float* ln2_b    = (const float*)d_in[12];
    const float* ca_q_w   = (const float*)d_in[13];
    const float* ca_k_w   = (const float*)d_in[14];
    const float* ca_v_w   = (const float*)d_in[15];
    const float* ca_out_w = (const float*)d_in[16];
    const float* ca_out_b = (const float*)d_in[17];
    const float* ln3_s    = (const float*)d_in[18];
    const float* ln3_b    = (const float*)d_in[19];
    const float* lin1_w   = (const float*)d_in[20];
    const float* lin1_b   = (const float*)d_in[21];
    const float* lin2_w   = (const float*)d_in[22];
    const float* lin2_b   = (const float*)d_in[23];
    const float* co_w     = (const float*)d_in[24];
    const float* co_b     = (const float*)d_in[25];
    float* out = (float*)d_out;

    float *xseq, *qkv, *kctx, *vctx, *tmp;
    __half *hgn, *ht, *hattn, *hctx, *hff, *hffg, *hx, *hw;
    cudaGetSymbolAddress((void**)&xseq, g_xseq);
    cudaGetSymbolAddress((void**)&qkv,  g_qkv);
    cudaGetSymbolAddress((void**)&kctx, g_kctx);
    cudaGetSymbolAddress((void**)&vctx, g_vctx);
    cudaGetSymbolAddress((void**)&tmp,  g_tmp);
    cudaGetSymbolAddress((void**)&hgn,  h_gn);
    cudaGetSymbolAddress((void**)&ht,   h_t);
    cudaGetSymbolAddress((void**)&hattn,h_attn);
    cudaGetSymbolAddress((void**)&hctx, h_ctx);
    cudaGetSymbolAddress((void**)&hff,  h_ff);
    cudaGetSymbolAddress((void**)&hffg, h_ffg);
    cudaGetSymbolAddress((void**)&hx,   h_x);
    cudaGetSymbolAddress((void**)&hw,   h_w);

    // fp16 weight layout, all [N,K]
    __half* sa_in_wT  = hw;                              // [1920][640]
    __half* sa_out_wT = sa_in_wT  + 1920*640;
    __half* ca_q_wT   = sa_out_wT + 640*640;
    __half* ca_k_wT   = ca_q_wT   + 640*640;             // [640][512]
    __half* ca_v_wT   = ca_k_wT   + 640*512;
    __half* ca_out_wT = ca_v_wT   + 640*512;
    __half* lin1_wT   = ca_out_wT + 640*640;             // [5120][640]
    __half* lin2_wT   = lin1_wT   + 5120*640;            // [640][2560]
    __half* conv1_wh  = lin2_wT   + 640*2560;            // [640][640] (already [N,K])
    __half* co_wh     = conv1_wh  + 640*640;

    cudaFuncSetAttribute(gemm_h,     cudaFuncAttributeMaxDynamicSharedMemorySize, GEMM_SMEM);
    cudaFuncSetAttribute(flash_attn, cudaFuncAttributeMaxDynamicSharedMemorySize, FLASH_SMEM);

    const int M = NB * HW;   // 8192
    const int MC = NB * SKCTX;  // 616
    dim3 tblk(32, 8);
    dim3 tgrid(HW/32, CCH/32, NB);
    auto ggrid = [](int N_, int M_) { return dim3(N_/128, (M_+127)/128); };

    // 0. weight conversion
    wtrans_h<<<dim3(3*CCH/32, CCH/32), tblk>>>(sa_in_w,  sa_in_wT,  CCH, 3*CCH);
    wtrans_h<<<dim3(CCH/32,   CCH/32), tblk>>>(sa_out_w, sa_out_wT, CCH, CCH);
    wtrans_h<<<dim3(CCH/32,   CCH/32), tblk>>>(ca_q_w,   ca_q_wT,   CCH, CCH);
    wtrans_h<<<dim3(CCH/32,  DCTX/32), tblk>>>(ca_k_w,   ca_k_wT,   DCTX, CCH);
    wtrans_h<<<dim3(CCH/32,  DCTX/32), tblk>>>(ca_v_w,   ca_v_wT,   DCTX, CCH);
    wtrans_h<<<dim3(CCH/32,   CCH/32), tblk>>>(ca_out_w, ca_out_wT, CCH, CCH);
    wtrans_h<<<dim3(8*CCH/32, CCH/32), tblk>>>(lin1_w,   lin1_wT,   CCH, 8*CCH);
    wtrans_h<<<dim3(CCH/32, 4*CCH/32), tblk>>>(lin2_w,   lin2_wT,   4*CCH, CCH);
    cvt_h<<<(CCH*CCH/4 + 255)/256, 256>>>(conv1_w, conv1_wh, CCH*CCH/4);
    cvt_h<<<(CCH*CCH/4 + 255)/256, 256>>>(co_w,    co_wh,    CCH*CCH/4);
    cvt_h<<<(MC*DCTX/4 + 255)/256, 256>>>(context, hctx,     MC*DCTX/4);

    // 1. GroupNorm + transpose (-> fp16)
    gn_stats<<<NB*GRP, 256>>>(x);
    gn_apply<<<tgrid, tblk>>>(x, gn_s, gn_b);

    // 2. conv1: xseq = hgn @ conv1_wh^T + b
    gemm_h<<<ggrid(CCH, M), 256, GEMM_SMEM>>>(hgn, CCH, conv1_wh, conv1_b, nullptr,
                                              xseq, nullptr, CCH, M, CCH, CCH);

    // 3. self-attention
    layernorm<<<M, 160>>>(xseq, ln1_s, ln1_b, ht);
    gemm_h<<<ggrid(3*CCH, M), 256, GEMM_SMEM>>>(ht, CCH, sa_in_wT, nullptr, nullptr,
                                                qkv, nullptr, 3*CCH, M, 3*CCH, CCH);
    flash_attn<<<dim3(HW/128, NB*NH), 256, FLASH_SMEM>>>(qkv, hattn);
    gemm_h<<<ggrid(CCH, M), 256, GEMM_SMEM>>>(hattn, CCH, sa_out_wT, sa_out_b, xseq,
                                              xseq, nullptr, CCH, M, CCH, CCH);

    // 4. cross-attention
    layernorm<<<M, 160>>>(xseq, ln2_s, ln2_b, ht);
    gemm_h<<<ggrid(CCH, M), 256, GEMM_SMEM>>>(ht, CCH, ca_q_wT, nullptr, nullptr,
                                              qkv, nullptr, CCH, M, CCH, CCH);
    gemm_h<<<ggrid(CCH, MC), 256, GEMM_SMEM>>>(hctx, DCTX, ca_k_wT, nullptr, nullptr,
                                               kctx, nullptr, CCH, MC, CCH, DCTX);
    gemm_h<<<ggrid(CCH, MC), 256, GEMM_SMEM>>>(hctx, DCTX, ca_v_wT, nullptr, nullptr,
                                               vctx, nullptr, CCH, MC, CCH, DCTX);
    attention<<<NB*NH*HW, 128>>>(qkv, kctx, vctx, hattn, SKCTX, CCH, CCH, CCH, CCH);
    gemm_h<<<ggrid(CCH, M), 256, GEMM_SMEM>>>(hattn, CCH, ca_out_wT, ca_out_b, xseq,
                                              xseq, nullptr, CCH, M, CCH, CCH);

    // 5. GeGLU FFN
    layernorm<<<M, 160>>>(xseq, ln3_s, ln3_b, ht);
    gemm_h<<<ggrid(8*CCH, M), 256, GEMM_SMEM>>>(ht, CCH, lin1_wT, lin1_b, nullptr,
                                                nullptr, hff, 8*CCH, M, 8*CCH, CCH);
    geglu<<<(NB*HW*CCH + 255)/256, 256>>>(hff, hffg);
    gemm_h<<<ggrid(CCH, M), 256, GEMM_SMEM>>>(hffg, 4*CCH, lin2_wT, lin2_b, xseq,
                                              xseq, hx, CCH, M, CCH, 4*CCH);

    // 6. final conv + long residual
    gemm_h<<<ggrid(CCH, M), 256, GEMM_SMEM>>>(hx, CCH, co_wh, co_b, nullptr,
                                              tmp, nullptr, CCH, M, CCH, CCH);
    final_add<<<tgrid, tblk>>>(tmp, x, out);
}

// round 7
// speedup vs baseline: 10.2404x; 1.0191x over previous
#include <cuda_runtime.h>
#include <cuda_fp16.h>
#include <math.h>
#include <stdint.h>

#define NB    8
#define CCH   640
#define HW    1024
#define NH    8
#define DH    80
#define DCTX  512
#define GRP   32
#define CPG   20
#define SKCTX 77

// ---------------- fp32 scratch ----------------
__device__ float  g_xseq [NB*HW*CCH];
__device__ float  g_qkv  [NB*HW*3*CCH];
__device__ float  g_kctx [NB*SKCTX*CCH];
__device__ float  g_vctx [NB*SKCTX*CCH];
__device__ float  g_tmp  [NB*HW*CCH];
__device__ float  g_gnstat[NB*GRP*2];
// ---------------- fp16 scratch ----------------
__device__ __half h_gn  [NB*HW*CCH];
__device__ __half h_t   [NB*HW*CCH];
__device__ __half h_attn[NB*HW*CCH];
__device__ __half h_ctx [NB*SKCTX*DCTX];
__device__ __half h_ff  [NB*HW*8*CCH];
__device__ __half h_ffg [NB*HW*4*CCH];
__device__ __half h_x   [NB*HW*CCH];
__device__ __half h_w   [8847360];       // all weights, fp16, [N,K]

// ---------------- GroupNorm stats ----------------
__global__ void gn_stats(const float* __restrict__ x) {
    int ng = blockIdx.x;
    int n = ng / GRP, g = ng % GRP;
    const float4* base = (const float4*)(x + ((size_t)n*CCH + (size_t)g*CPG) * HW);
    float s = 0.f, s2 = 0.f;
    for (int i = threadIdx.x; i < CPG*HW/4; i += 256) {
        float4 v = base[i];
        s  += v.x + v.y + v.z + v.w;
        s2 += v.x*v.x + v.y*v.y + v.z*v.z + v.w*v.w;
    }
    __shared__ float rs[256], rq[256];
    rs[threadIdx.x] = s; rq[threadIdx.x] = s2;
    __syncthreads();
    for (int o = 128; o > 0; o >>= 1) {
        if (threadIdx.x < o) { rs[threadIdx.x] += rs[threadIdx.x+o]; rq[threadIdx.x] += rq[threadIdx.x+o]; }
        __syncthreads();
    }
    if (threadIdx.x == 0) {
        float inv_n = 1.f / (float)(CPG*HW);
        float mu  = rs[0] * inv_n;
        float var = rq[0] * inv_n - mu*mu;
        g_gnstat[ng*2]   = mu;
        g_gnstat[ng*2+1] = rsqrtf(var + 1e-6f);
    }
}

// ---------------- GroupNorm apply + transpose -> fp16 [n,p,c] ----------------
__global__ void gn_apply(const float* __restrict__ x,
                         const float* __restrict__ s, const float* __restrict__ b) {
    __shared__ float tile[32][33];
    int n = blockIdx.z;
    int p0 = blockIdx.x*32, c0 = blockIdx.y*32;
    int tx = threadIdx.x, ty = threadIdx.y;
    #pragma unroll
    for (int i = 0; i < 4; i++) {
        int c = c0 + ty + i*8;
        int ng = n*GRP + c / CPG;
        float mu = g_gnstat[ng*2], is = g_gnstat[ng*2+1];
        float v = x[((size_t)n*CCH + c)*HW + p0 + tx];
        tile[ty + i*8][tx] = (v - mu) * is * s[c] + b[c];
    }
    __syncthreads();
    #pragma unroll
    for (int i = 0; i < 4; i++) {
        int p = p0 + ty + i*8;
        h_gn[((size_t)n*HW + p)*CCH + c0 + tx] = __float2half(tile[tx][ty + i*8]);
    }
}

// ---------------- weight transpose+convert fp32 [K,N] -> fp16 [N,K] ----------------
__global__ void wtrans_h(const float* __restrict__ src, __half* __restrict__ dst, int K, int N) {
    __shared__ float t[32][33];
    int k0 = blockIdx.y*32, n0 = blockIdx.x*32;
    int tx = threadIdx.x, ty = threadIdx.y;
    #pragma unroll
    for (int i = 0; i < 4; i++)
        t[ty + i*8][tx] = src[(size_t)(k0 + ty + i*8)*N + n0 + tx];
    __syncthreads();
    #pragma unroll
    for (int i = 0; i < 4; i++)
        dst[(size_t)(n0 + ty + i*8)*K + k0 + tx] = __float2half(t[tx][ty + i*8]);
}

// ---------------- straight convert fp32 -> fp16 ----------------
__global__ void cvt_h(const float* __restrict__ src, __half* __restrict__ dst, int n4) {
    int i = blockIdx.x * 256 + threadIdx.x;
    if (i >= n4) return;
    float4 v = ((const float4*)src)[i];
    __half2 p0 = __floats2half2_rn(v.x, v.y);
    __half2 p1 = __floats2half2_rn(v.z, v.w);
    union { uint2 u; __half2 h[2]; } pk; pk.h[0] = p0; pk.h[1] = p1;
    ((uint2*)dst)[i] = pk.u;
}

// ---------------- LayerNorm fp32 in -> fp16 out ----------------
__global__ __launch_bounds__(160)
void layernorm(const float* __restrict__ in,
               const float* __restrict__ s, const float* __restrict__ b,
               __half* __restrict__ out) {
    int row = blockIdx.x;
    int tid = threadIdx.x;
    const float4* r4 = (const float4*)(in + (size_t)row * CCH);
    float4 v = r4[tid];
    float sum = v.x + v.y + v.z + v.w;
    float sq  = v.x*v.x + v.y*v.y + v.z*v.z + v.w*v.w;
    #pragma unroll
    for (int o = 16; o > 0; o >>= 1) {
        sum += __shfl_xor_sync(~0u, sum, o);
        sq  += __shfl_xor_sync(~0u, sq,  o);
    }
    __shared__ float ws[5], wq[5];
    int w = tid >> 5;
    if ((tid & 31) == 0) { ws[w] = sum; wq[w] = sq; }
    __syncthreads();
    sum = ws[0] + ws[1] + ws[2] + ws[3] + ws[4];
    sq  = wq[0] + wq[1] + wq[2] + wq[3] + wq[4];
    float mu  = sum / (float)CCH;
    float inv = rsqrtf(sq / (float)CCH - mu*mu + 1e-5f);
    float4 sc = ((const float4*)s)[tid];
    float4 bb = ((const float4*)b)[tid];
    union { uint2 u; __half2 h[2]; } pk;
    pk.h[0] = __floats2half2_rn((v.x - mu) * inv * sc.x + bb.x, (v.y - mu) * inv * sc.y + bb.y);
    pk.h[1] = __floats2half2_rn((v.z - mu) * inv * sc.z + bb.z, (v.w - mu) * inv * sc.w + bb.w);
    ((uint2*)(out + (size_t)row * CCH))[tid] = pk.u;
}

// ---------------- mma / cp.async helpers ----------------
__device__ __forceinline__ void mma16h(float c[4], uint32_t a0, uint32_t a1, uint32_t a2, uint32_t a3,
                                       uint32_t b0, uint32_t b1) {
    asm volatile("mma.sync.aligned.m16n8k16.row.col.f32.f16.f16.f32 "
        "{%0,%1,%2,%3}, {%4,%5,%6,%7}, {%8,%9}, {%0,%1,%2,%3};"
        : "+f"(c[0]), "+f"(c[1]), "+f"(c[2]), "+f"(c[3])
        : "r"(a0), "r"(a1), "r"(a2), "r"(a3), "r"(b0), "r"(b1));
}
__device__ __forceinline__ void mma8(float c[4], uint32_t a0, uint32_t a1, uint32_t a2, uint32_t a3,
                                     uint32_t b0, uint32_t b1) {
    asm volatile("mma.sync.aligned.m16n8k8.row.col.f32.tf32.tf32.f32 "
        "{%0,%1,%2,%3}, {%4,%5,%6,%7}, {%8,%9}, {%0,%1,%2,%3};"
        : "+f"(c[0]), "+f"(c[1]), "+f"(c[2]), "+f"(c[3])
        : "r"(a0), "r"(a1), "r"(a2), "r"(a3), "r"(b0), "r"(b1));
}
__device__ __forceinline__ void ldsm4(uint32_t r[4], uint32_t addr) {
    asm volatile("ldmatrix.sync.aligned.m8n8.x4.shared.b16 {%0,%1,%2,%3}, [%4];"
        : "=r"(r[0]), "=r"(r[1]), "=r"(r[2]), "=r"(r[3]) : "r"(addr));
}
__device__ __forceinline__ void cpa16(void* dst, const void* src, bool valid) {
    uint32_t d = (uint32_t)__cvta_generic_to_shared(dst);
    int sz = valid ? 16 : 0;
    asm volatile("cp.async.cg.shared.global [%0], [%1], 16, %2;" :: "r"(d), "l"(src), "r"(sz));
}
#define CP_COMMIT() asm volatile("cp.async.commit_group;")
#define CP_WAIT1()  asm volatile("cp.async.wait_group 1;")
#define CP_WAIT2()  asm volatile("cp.async.wait_group 2;")
__device__ __forceinline__ uint32_t fu(float f) { return __float_as_uint(f); }

// ---------------- fp16 GEMM: 128x128x64, 3-stage cp.async + ldmatrix ----------------
#define RS36 36                     // row stride in u32 (64 halves + 16B pad)
#define BUFU (128*RS36)             // u32 per operand per stage
#define NST  3
#define GEMM_SMEM (NST*2*BUFU*4)    // 110592 B
__global__ __launch_bounds__(256)
void gemm_h(const __half* __restrict__ A, int lda,
            const __half* __restrict__ B,
            const float* __restrict__ bias,
            const float* __restrict__ res,
            float* __restrict__ C, __half* __restrict__ Ch, int ldc,
            int M, int N, int K) {
    extern __shared__ uint32_t sm[];
    uint32_t* As = sm;                 // [NST][BUFU]
    uint32_t* Bs = sm + NST*BUFU;      // [NST][BUFU]
    uint32_t a_u32 = (uint32_t)__cvta_generic_to_shared(As);

    int tid = threadIdx.x;
    int lane = tid & 31, warp = tid >> 5;
    int gr = lane >> 2, t4 = lane & 3;
    int wm = (warp >> 2) * 64, wn = (warp & 3) * 32;
    int bm = blockIdx.y * 128, bn = blockIdx.x * 128;

    // per-thread ldmatrix row offset within a 16-row fragment
    uint32_t lds_off = (uint32_t)((lane & 15) * (RS36*4) + ((lane >> 4) << 4));

    auto stage = [&](int kt, int buf) {
        #pragma unroll
        for (int i = 0; i < 4; i++) {           // A: 128 rows x 128B
            int c = tid + i*256;
            int row = c >> 3, seg = c & 7;
            int gm = bm + row;
            cpa16(As + buf*BUFU + row*RS36 + seg*4,
                  A + ((size_t)(gm < M ? gm : 0))*lda + kt*64 + seg*8, gm < M);
        }
        #pragma unroll
        for (int i = 0; i < 4; i++) {           // B: 128 rows x 128B
            int c = tid + i*256;
            int row = c >> 3, seg = c & 7;
            int gn = bn + row;
            cpa16(Bs + buf*BUFU + row*RS36 + seg*4,
                  B + ((size_t)(gn < N ? gn : 0))*K + kt*64 + seg*8, gn < N);
        }
    };

    float acc[4][4][4];
    #pragma unroll
    for (int i = 0; i < 4; i++)
        #pragma unroll
        for (int j = 0; j < 4; j++)
            #pragma unroll
            for (int r = 0; r < 4; r++) acc[i][j][r] = 0.f;

    int nk = K >> 6;
    stage(0, 0); CP_COMMIT();
    stage(1, 1); CP_COMMIT();

    int buf = 0;
    for (int t = 0; t < nk; t++) {
        if (t + 2 < nk) stage(t+2, (t+2) % NST);
        CP_COMMIT();
        CP_WAIT2();
        __syncthreads();

        const uint32_t* B_s = Bs + buf*BUFU;
        uint32_t a_base = a_u32 + buf*(BUFU*4) + lds_off;

        #pragma unroll
        for (int ks = 0; ks < 4; ks++) {        // 4 x k16
            uint32_t af[4][4], bf[4][2];
            #pragma unroll
            for (int mi = 0; mi < 4; mi++)
                ldsm4(af[mi], a_base + (uint32_t)((wm + mi*16)*(RS36*4) + ks*32));
            #pragma unroll
            for (int ni = 0; ni < 4; ni++) {
                int n0 = wn + ni*8 + gr;
                bf[ni][0] = B_s[n0*RS36 + ks*8 + t4];
                bf[ni][1] = B_s[n0*RS36 + ks*8 + t4 + 4];
            }
            #pragma unroll
            for (int mi = 0; mi < 4; mi++)
                #pragma unroll
                for (int ni = 0; ni < 4; ni++)
                    mma16h(acc[mi][ni], af[mi][0], af[mi][1], af[mi][2], af[mi][3],
                           bf[ni][0], bf[ni][1]);
        }
        __syncthreads();
        buf = (buf + 1 == NST) ? 0 : buf + 1;
    }

    #pragma unroll
    for (int mi = 0; mi < 4; mi++) {
        #pragma unroll
        for (int ni = 0; ni < 4; ni++) {
            int col0 = bn + wn + ni*8 + t4*2;
            #pragma unroll
            for (int half_r = 0; half_r < 2; half_r++) {
                int row = bm + wm + mi*16 + gr + half_r*8;
                if (row >= M) continue;
                float v0 = acc[mi][ni][half_r*2 + 0];
                float v1 = acc[mi][ni][half_r*2 + 1];
                if (bias) { v0 += bias[col0]; v1 += bias[col0+1]; }
                if (res) {
                    const float* rp = res + (size_t)row*ldc + col0;
                    v0 += rp[0]; v1 += rp[1];
                }
                if (C) *(float2*)(C + (size_t)row*ldc + col0) = make_float2(v0, v1);
                if (Ch) *(__half2*)(Ch + (size_t)row*ldc + col0) = __floats2half2_rn(v0, v1);
            }
        }
    }
}

// ---------------- fused flash self-attention (tf32 mma, fp32 qkv in, fp16 out) ----------------
#define KP 84
#define VP 88
#define FLASH_SMEM ((2*64*KP + 2*64*VP)*4)
__global__ __launch_bounds__(256)
void flash_attn(const float* __restrict__ QKV, __half* __restrict__ O) {
    constexpr int LD = 3*CCH;
    extern __shared__ float smf[];
    float* Ks = smf;
    float* Vs = smf + 2*64*KP;

    int tid = threadIdx.x, lane = tid & 31, w = tid >> 5;
    int z = blockIdx.y;
    int b = z >> 3, h = z & 7;
    int q0 = blockIdx.x * 128;
    int gr = lane >> 2, t4 = lane & 3;

    const float* Qb = QKV + ((size_t)b*HW)*LD + h*DH;
    const float* Kb = QKV + ((size_t)b*HW)*LD + CCH + h*DH;
    const float* Vb = QKV + ((size_t)b*HW)*LD + 2*CCH + h*DH;

    auto stage = [&](int kt, int buf) {
        int row = tid >> 2;
        int cc  = (tid & 3) * 20;
        const float* kg = Kb + (size_t)(kt*64 + row)*LD + cc;
        const float* vg = Vb + (size_t)(kt*64 + row)*LD + cc;
        float* ksm = Ks + buf*64*KP + row*KP + cc;
        float* vsm = Vs + buf*64*VP + row*VP + cc;
        #pragma unroll
        for (int i = 0; i < 5; i++) {
            cpa16(ksm + i*4, kg + i*4, true);
            cpa16(vsm + i*4, vg + i*4, true);
        }
    };

    stage(0, 0);
    CP_COMMIT();

    const float qscale = 0.1118033988749895f;
    float qf[10][4];
    {
        const float* qp  = Qb + (size_t)(q0 + w*16 + gr)*LD;
        const float* qp8 = qp + 8*LD;
        #pragma unroll
        for (int ks = 0; ks < 10; ks++) {
            qf[ks][0] = qp [ks*8 + t4]     * qscale;
            qf[ks][1] = qp8[ks*8 + t4]     * qscale;
            qf[ks][2] = qp [ks*8 + t4 + 4] * qscale;
            qf[ks][3] = qp8[ks*8 + t4 + 4] * qscale;
        }
    }

    float m0v = -1e30f, m1v = -1e30f, l0 = 0.f, l1 = 0.f;
    float oa[10][4];
    #pragma unroll
    for (int ni = 0; ni < 10; ni++) { oa[ni][0]=oa[ni][1]=oa[ni][2]=oa[ni][3]=0.f; }

    for (int kt = 0; kt < 16; kt++) {
        if (kt + 1 < 16) stage(kt+1, (kt+1) & 1);
        CP_COMMIT();
        CP_WAIT1();
        __syncthreads();
        const float* Kc = Ks + (kt & 1)*64*KP;
        const float* Vc = Vs + (kt & 1)*64*VP;

        float s[8][4];
        #pragma unroll
        for (int ni = 0; ni < 8; ni++) { s[ni][0]=s[ni][1]=s[ni][2]=s[ni][3]=0.f; }
        #pragma unroll
        for (int ks = 0; ks < 10; ks++) {
            #pragma unroll
            for (int ni = 0; ni < 8; ni++) {
                uint32_t b0 = fu(Kc[(gr + 8*ni)*KP + ks*8 + t4]);
                uint32_t b1 = fu(Kc[(gr + 8*ni)*KP + ks*8 + t4 + 4]);
                mma8(s[ni], fu(qf[ks][0]), fu(qf[ks][1]), fu(qf[ks][2]), fu(qf[ks][3]), b0, b1);
            }
        }

        float tm0 = -1e30f, tm1 = -1e30f;
        #pragma unroll
        for (int ni = 0; ni < 8; ni++) {
            tm0 = fmaxf(tm0, fmaxf(s[ni][0], s[ni][1]));
            tm1 = fmaxf(tm1, fmaxf(s[ni][2], s[ni][3]));
        }
        tm0 = fmaxf(tm0, __shfl_xor_sync(~0u, tm0, 1));
        tm0 = fmaxf(tm0, __shfl_xor_sync(~0u, tm0, 2));
        tm1 = fmaxf(tm1, __shfl_xor_sync(~0u, tm1, 1));
        tm1 = fmaxf(tm1, __shfl_xor_sync(~0u, tm1, 2));
        float mn0 = fmaxf(m0v, tm0), mn1 = fmaxf(m1v, tm1);
        float al0 = __expf(m0v - mn0), al1 = __expf(m1v - mn1);
        m0v = mn0; m1v = mn1;
        float ts0 = 0.f, ts1 = 0.f;
        #pragma unroll
        for (int ni = 0; ni < 8; ni++) {
            s[ni][0] = __expf(s[ni][0] - mn0);
            s[ni][1] = __expf(s[ni][1] - mn0);
            s[ni][2] = __expf(s[ni][2] - mn1);
            s[ni][3] = __expf(s[ni][3] - mn1);
            ts0 += s[ni][0] + s[ni][1];
            ts1 += s[ni][2] + s[ni][3];
        }
        ts0 += __shfl_xor_sync(~0u, ts0, 1); ts0 += __shfl_xor_sync(~0u, ts0, 2);
        ts1 += __shfl_xor_sync(~0u, ts1, 1); ts1 += __shfl_xor_sync(~0u, ts1, 2);
        l0 = l0*al0 + ts0;
        l1 = l1*al1 + ts1;
        #pragma unroll
        for (int ni = 0; ni < 10; ni++) {
            oa[ni][0] *= al0; oa[ni][1] *= al0;
            oa[ni][2] *= al1; oa[ni][3] *= al1;
        }

        #pragma unroll
        for (int ks = 0; ks < 8; ks++) {
            int src = (lane & ~3) | (t4 >> 1);
            float v0 = __shfl_sync(~0u, s[ks][0], src);
            float v1 = __shfl_sync(~0u, s[ks][1], src);
            float v2 = __shfl_sync(~0u, s[ks][2], src);
            float v3 = __shfl_sync(~0u, s[ks][3], src);
            float w0 = __shfl_sync(~0u, s[ks][0], src + 2);
            float w1 = __shfl_sync(~0u, s[ks][1], src + 2);
            float w2 = __shfl_sync(~0u, s[ks][2], src + 2);
            float w3 = __shfl_sync(~0u, s[ks][3], src + 2);
            bool odd = t4 & 1;
            uint32_t a0 = fu(odd ? v1 : v0);
            uint32_t a1 = fu(odd ? v3 : v2);
            uint32_t a2 = fu(odd ? w1 : w0);
            uint32_t a3 = fu(odd ? w3 : w2);
            #pragma unroll
            for (int ni = 0; ni < 10; ni++) {
                uint32_t b0 = fu(Vc[(t4 + 8*ks)*VP + gr + 8*ni]);
                uint32_t b1 = fu(Vc[(t4 + 4 + 8*ks)*VP + gr + 8*ni]);
                mma8(oa[ni], a0, a1, a2, a3, b0, b1);
            }
        }
        __syncthreads();
    }

    float inv0 = 1.f / l0, inv1 = 1.f / l1;
    __half* Ob = O + ((size_t)(b*HW + q0 + w*16))*CCH + h*DH;
    #pragma unroll
    for (int ni = 0; ni < 10; ni++) {
        *(__half2*)(Ob + (size_t)gr*CCH + 8*ni + 2*t4) =
            __floats2half2_rn(oa[ni][0]*inv0, oa[ni][1]*inv0);
        *(__half2*)(Ob + (size_t)(gr+8)*CCH + 8*ni + 2*t4) =
            __floats2half2_rn(oa[ni][2]*inv1, oa[ni][3]*inv1);
    }
}

// ---------------- small-SK attention (cross-attn, SK=77), fp16 out ----------------
__global__ void attention(const float* __restrict__ Q, const float* __restrict__ Kp,
                          const float* __restrict__ V, __half* __restrict__ O,
                          int SK, int qs, int ks, int vs, int os) {
    int q = blockIdx.x % HW;
    int h = (blockIdx.x / HW) % NH;
    int b = blockIdx.x / (HW*NH);
    int tid = threadIdx.x;

    __shared__ float sq[DH];
    __shared__ float sp[128];
    __shared__ float red[128];

    const float scale = rsqrtf((float)DH);
    const float* qrow = Q + ((size_t)(b*HW + q))*qs + h*DH;
    if (tid < DH) sq[tid] = qrow[tid];
    __syncthreads();

    float lmax = -1e30f;
    if (tid < SK) {
        const float* krow = Kp + ((size_t)(b*SK + tid))*ks + h*DH;
        float s = 0.f;
        #pragma unroll 16
        for (int d = 0; d < DH; d++) s += sq[d] * krow[d];
        s *= scale;
        sp[tid] = s;
        lmax = s;
    }
    red[tid] = lmax; __syncthreads();
    for (int o = 64; o > 0; o >>= 1) {
        if (tid < o) red[tid] = fmaxf(red[tid], red[tid+o]);
        __syncthreads();
    }
    float m = red[0];
    __syncthreads();
    float lsum = 0.f;
    if (tid < SK) {
        float e = __expf(sp[tid] - m);
        sp[tid] = e; lsum = e;
    }
    red[tid] = lsum; __syncthreads();
    for (int o = 64; o > 0; o >>= 1) {
        if (tid < o) red[tid] += red[tid+o];
        __syncthreads();
    }
    float inv = 1.f / red[0];
    __syncthreads();

    if (tid < DH) {
        float o = 0.f;
        for (int j = 0; j < SK; j++)
            o += sp[j] * V[((size_t)(b*SK + j))*vs + h*DH + tid];
        O[((size_t)(b*HW + q))*os + h*DH + tid] = __float2half(o * inv);
    }
}

// ---------------- GeGLU: fp16 in, fp16 out ----------------
__global__ void geglu(const __half* __restrict__ ff, __half* __restrict__ out) {
    int idx = blockIdx.x * 256 + threadIdx.x;
    if (idx >= NB*HW*CCH) return;      // 4 elems per thread
    int m = idx / CCH;
    int j = idx % CCH;
    union { uint2 u; __half2 h[2]; } av, gv, rv;
    av.u = *(const uint2*)(ff + (size_t)m*8*CCH + j*4);
    gv.u = *(const uint2*)(ff + (size_t)m*8*CCH + 4*CCH + j*4);
    float a0 = __half2float(av.h[0].x), a1 = __half2float(av.h[0].y);
    float a2 = __half2float(av.h[1].x), a3 = __half2float(av.h[1].y);
    float g0 = __half2float(gv.h[0].x), g1 = __half2float(gv.h[0].y);
    float g2 = __half2float(gv.h[1].x), g3 = __half2float(gv.h[1].y);
    const float is2 = 0.70710678118654752f;
    rv.h[0] = __floats2half2_rn(a0 * 0.5f * g0 * (1.f + erff(g0*is2)),
                                a1 * 0.5f * g1 * (1.f + erff(g1*is2)));
    rv.h[1] = __floats2half2_rn(a2 * 0.5f * g2 * (1.f + erff(g2*is2)),
                                a3 * 0.5f * g3 * (1.f + erff(g3*is2)));
    *(uint2*)(out + (size_t)m*4*CCH + j*4) = rv.u;
}

// ---------------- final transpose + residual ----------------
__global__ void final_add(const float* __restrict__ tmp, const float* __restrict__ xin,
                          float* __restrict__ out) {
    __shared__ float tile[32][33];
    int n = blockIdx.z;
    int p0 = blockIdx.x*32, c0 = blockIdx.y*32;
    int tx = threadIdx.x, ty = threadIdx.y;
    #pragma unroll
    for (int i = 0; i < 4; i++) {
        int p = p0 + ty + i*8;
        tile[ty + i*8][tx] = tmp[((size_t)n*HW + p)*CCH + c0 + tx];
    }
    __syncthreads();
    #pragma unroll
    for (int i = 0; i < 4; i++) {
        int c = c0 + ty + i*8;
        size_t o = ((size_t)n*CCH + c)*HW + p0 + tx;
        out[o] = tile[tx][ty + i*8] + xin[o];
    }
}

// ---------------- host launch ----------------
extern "C" void kernel_launch(void* const* d_in, const int* in_sizes, int n_in,
                              void* d_out, int out_size) {
    const float* x        = (const float*)d_in[0];
    const float* context  = (const float*)d_in[1];
    const float* gn_s     = (const float*)d_in[2];
    const float* gn_b     = (const float*)d_in[3];
    const float* conv1_w  = (const float*)d_in[4];
    const float* conv1_b  = (const float*)d_in[5];
    const float* ln1_s    = (const float*)d_in[6];
    const float* ln1_b    = (const float*)d_in[7];
    const float* sa_in_w  = (const float*)d_in[8];
    const float* sa_out_w = (const float*)d_in[9];
    const float* sa_out_b = (const float*)d_in[10];
    const float* ln2_s    = (const float*)d_in[11];
    const float* ln2_b    = (const float*)d_in[12];
    const float* ca_q_w   = (const float*)d_in[13];
    const float* ca_k_w   = (const float*)d_in[14];
    const float* ca_v_w   = (const float*)d_in[15];
    const float* ca_out_w = (const float*)d_in[16];
    const float* ca_out_b = (const float*)d_in[17];
    const float* ln3_s    = (const float*)d_in[18];
    const float* ln3_b    = (const float*)d_in[19];
    const float* lin1_w   = (const float*)d_in[20];
    const float* lin1_b   = (const float*)d_in[21];
    const float* lin2_w   = (const float*)d_in[22];
    const float* lin2_b   = (const float*)d_in[23];
    const float* co_w     = (const float*)d_in[24];
    const float* co_b     = (const float*)d_in[25];
    float* out = (float*)d_out;

    float *xseq, *qkv, *kctx, *vctx, *tmp;
    __half *hgn, *ht, *hattn, *hctx, *hff, *hffg, *hx, *hw;
    cudaGetSymbolAddress((void**)&xseq, g_xseq);
    cudaGetSymbolAddress((void**)&qkv,  g_qkv);
    cudaGetSymbolAddress((void**)&kctx, g_kctx);
    cudaGetSymbolAddress((void**)&vctx, g_vctx);
    cudaGetSymbolAddress((void**)&tmp,  g_tmp);
    cudaGetSymbolAddress((void**)&hgn,  h_gn);
    cudaGetSymbolAddress((void**)&ht,   h_t);
    cudaGetSymbolAddress((void**)&hattn,h_attn);
    cudaGetSymbolAddress((void**)&hctx, h_ctx);
    cudaGetSymbolAddress((void**)&hff,  h_ff);
    cudaGetSymbolAddress((void**)&hffg, h_ffg);
    cudaGetSymbolAddress((void**)&hx,   h_x);
    cudaGetSymbolAddress((void**)&hw,   h_w);

    // fp16 weight layout, all [N,K]
    __half* sa_in_wT  = hw;                              // [1920][640]
    __half* sa_out_wT = sa_in_wT  + 1920*640;
    __half* ca_q_wT   = sa_out_wT + 640*640;
    __half* ca_k_wT   = ca_q_wT   + 640*640;             // [640][512]
    __half* ca_v_wT   = ca_k_wT   + 640*512;
    __half* ca_out_wT = ca_v_wT   + 640*512;
    __half* lin1_wT   = ca_out_wT + 640*640;             // [5120][640]
    __half* lin2_wT   = lin1_wT   + 5120*640;            // [640][2560]
    __half* conv1_wh  = lin2_wT   + 640*2560;            // [640][640] (already [N,K])
    __half* co_wh     = conv1_wh  + 640*640;

    cudaFuncSetAttribute(gemm_h,     cudaFuncAttributeMaxDynamicSharedMemorySize, GEMM_SMEM);
    cudaFuncSetAttribute(flash_attn, cudaFuncAttributeMaxDynamicSharedMemorySize, FLASH_SMEM);

    const int M = NB * HW;   // 8192
    const int MC = NB * SKCTX;  // 616
    dim3 tblk(32, 8);
    dim3 tgrid(HW/32, CCH/32, NB);
    auto ggrid = [](int N_, int M_) { return dim3(N_/128, (M_+127)/128); };

    // 0. weight conversion
    wtrans_h<<<dim3(3*CCH/32, CCH/32), tblk>>>(sa_in_w,  sa_in_wT,  CCH, 3*CCH);
    wtrans_h<<<dim3(CCH/32,   CCH/32), tblk>>>(sa_out_w, sa_out_wT, CCH, CCH);
    wtrans_h<<<dim3(CCH/32,   CCH/32), tblk>>>(ca_q_w,   ca_q_wT,   CCH, CCH);
    wtrans_h<<<dim3(CCH/32,  DCTX/32), tblk>>>(ca_k_w,   ca_k_wT,   DCTX, CCH);
    wtrans_h<<<dim3(CCH/32,  DCTX/32), tblk>>>(ca_v_w,   ca_v_wT,   DCTX, CCH);
    wtrans_h<<<dim3(CCH/32,   CCH/32), tblk>>>(ca_out_w, ca_out_wT, CCH, CCH);
    wtrans_h<<<dim3(8*CCH/32, CCH/32), tblk>>>(lin1_w,   lin1_wT,   CCH, 8*CCH);
    wtrans_h<<<dim3(CCH/32, 4*CCH/32), tblk>>>(lin2_w,   lin2_wT,   4*CCH, CCH);
    cvt_h<<<(CCH*CCH/4 + 255)/256, 256>>>(conv1_w, conv1_wh, CCH*CCH/4);
    cvt_h<<<(CCH*CCH/4 + 255)/256, 256>>>(co_w,    co_wh,    CCH*CCH/4);
    cvt_h<<<(MC*DCTX/4 + 255)/256, 256>>>(context, hctx,     MC*DCTX/4);

    // 1. GroupNorm + transpose (-> fp16)
    gn_stats<<<NB*GRP, 256>>>(x);
    gn_apply<<<tgrid, tblk>>>(x, gn_s, gn_b);

    // 2. conv1: xseq = hgn @ conv1_wh^T + b
    gemm_h<<<ggrid(CCH, M), 256, GEMM_SMEM>>>(hgn, CCH, conv1_wh, conv1_b, nullptr,
                                              xseq, nullptr, CCH, M, CCH, CCH);

    // 3. self-attention
    layernorm<<<M, 160>>>(xseq, ln1_s, ln1_b, ht);
    gemm_h<<<ggrid(3*CCH, M), 256, GEMM_SMEM>>>(ht, CCH, sa_in_wT, nullptr, nullptr,
                                                qkv, nullptr, 3*CCH, M, 3*CCH, CCH);
    flash_attn<<<dim3(HW/128, NB*NH), 256, FLASH_SMEM>>>(qkv, hattn);
    gemm_h<<<ggrid(CCH, M), 256, GEMM_SMEM>>>(hattn, CCH, sa_out_wT, sa_out_b, xseq,
                                              xseq, nullptr, CCH, M, CCH, CCH);

    // 4. cross-attention
    layernorm<<<M, 160>>>(xseq, ln2_s, ln2_b, ht);
    gemm_h<<<ggrid(CCH, M), 256, GEMM_SMEM>>>(ht, CCH, ca_q_wT, nullptr, nullptr,
                                              qkv, nullptr, CCH, M, CCH, CCH);
    gemm_h<<<ggrid(CCH, MC), 256, GEMM_SMEM>>>(hctx, DCTX, ca_k_wT, nullptr, nullptr,
                                               kctx, nullptr, CCH, MC, CCH, DCTX);
    gemm_h<<<ggrid(CCH, MC), 256, GEMM_SMEM>>>(hctx, DCTX, ca_v_wT, nullptr, nullptr,
                                               vctx, nullptr, CCH, MC, CCH, DCTX);
    attention<<<NB*NH*HW, 128>>>(qkv, kctx, vctx, hattn, SKCTX, CCH, CCH, CCH, CCH);
    gemm_h<<<ggrid(CCH, M), 256, GEMM_SMEM>>>(hattn, CCH, ca_out_wT, ca_out_b, xseq,
                                              xseq, nullptr, CCH, M, CCH, CCH);

    // 5. GeGLU FFN
    layernorm<<<M, 160>>>(xseq, ln3_s, ln3_b, ht);
    gemm_h<<<ggrid(8*CCH, M), 256, GEMM_SMEM>>>(ht, CCH, lin1_wT, lin1_b, nullptr,
                                                nullptr, hff, 8*CCH, M, 8*CCH, CCH);
    geglu<<<(NB*HW*CCH + 255)/256, 256>>>(hff, hffg);
    gemm_h<<<ggrid(CCH, M), 256, GEMM_SMEM>>>(hffg, 4*CCH, lin2_wT, lin2_b, xseq,
                                              xseq, hx, CCH, M, CCH, 4*CCH);

    // 6. final conv + long residual
    gemm_h<<<ggrid(CCH, M), 256, GEMM_SMEM>>>(hx, CCH, co_wh, co_b, nullptr,
                                              tmp, nullptr, CCH, M, CCH, CCH);
    final_add<<<tgrid, tblk>>>(tmp, x, out);
}

// round 8
// speedup vs baseline: 28.3180x; 2.7653x over previous
#include <cuda_runtime.h>
#include <cuda_fp16.h>
#include <math.h>
#include <stdint.h>

#define NB    8
#define CCH   640
#define HW    1024
#define NH    8
#define DH    80
#define DCTX  512
#define GRP   32
#define CPG   20
#define SKCTX 77

// ---------------- fp32 scratch ----------------
__device__ float  g_xseq [NB*HW*CCH];
__device__ float  g_tmp  [NB*HW*CCH];
__device__ float  g_gnstat[NB*GRP*2];
// ---------------- fp16 scratch ----------------
__device__ __half h_gn  [NB*HW*CCH];
__device__ __half h_t   [NB*HW*CCH];
__device__ __half h_attn[NB*HW*CCH];
__device__ __half h_ctx [NB*SKCTX*DCTX];
__device__ __half h_kctx[NB*SKCTX*CCH];
__device__ __half h_vctx[NB*SKCTX*CCH];
__device__ __half h_ff  [NB*HW*8*CCH];
__device__ __half h_ffg [NB*HW*4*CCH];
__device__ __half h_x   [NB*HW*CCH];
__device__ __half h_qkv [NB*HW*3*CCH];
__device__ __half h_vt  [NB*CCH*HW];     // V transposed: [b][c(=h*80+d)][p]
__device__ __half h_w   [8847360];       // all weights, fp16, [N,K]

// ---------------- GroupNorm stats ----------------
__global__ void gn_stats(const float* __restrict__ x) {
    int ng = blockIdx.x;
    int n = ng / GRP, g = ng % GRP;
    const float4* base = (const float4*)(x + ((size_t)n*CCH + (size_t)g*CPG) * HW);
    float s = 0.f, s2 = 0.f;
    for (int i = threadIdx.x; i < CPG*HW/4; i += 256) {
        float4 v = base[i];
        s  += v.x + v.y + v.z + v.w;
        s2 += v.x*v.x + v.y*v.y + v.z*v.z + v.w*v.w;
    }
    __shared__ float rs[256], rq[256];
    rs[threadIdx.x] = s; rq[threadIdx.x] = s2;
    __syncthreads();
    for (int o = 128; o > 0; o >>= 1) {
        if (threadIdx.x < o) { rs[threadIdx.x] += rs[threadIdx.x+o]; rq[threadIdx.x] += rq[threadIdx.x+o]; }
        __syncthreads();
    }
    if (threadIdx.x == 0) {
        float inv_n = 1.f / (float)(CPG*HW);
        float mu  = rs[0] * inv_n;
        float var = rq[0] * inv_n - mu*mu;
        g_gnstat[ng*2]   = mu;
        g_gnstat[ng*2+1] = rsqrtf(var + 1e-6f);
    }
}

// ---------------- GroupNorm apply + transpose -> fp16 [n,p,c] ----------------
__global__ void gn_apply(const float* __restrict__ x,
                         const float* __restrict__ s, const float* __restrict__ b) {
    __shared__ float tile[32][33];
    int n = blockIdx.z;
    int p0 = blockIdx.x*32, c0 = blockIdx.y*32;
    int tx = threadIdx.x, ty = threadIdx.y;
    #pragma unroll
    for (int i = 0; i < 4; i++) {
        int c = c0 + ty + i*8;
        int ng = n*GRP + c / CPG;
        float mu = g_gnstat[ng*2], is = g_gnstat[ng*2+1];
        float v = x[((size_t)n*CCH + c)*HW + p0 + tx];
        tile[ty + i*8][tx] = (v - mu) * is * s[c] + b[c];
    }
    __syncthreads();
    #pragma unroll
    for (int i = 0; i < 4; i++) {
        int p = p0 + ty + i*8;
        h_gn[((size_t)n*HW + p)*CCH + c0 + tx] = __float2half(tile[tx][ty + i*8]);
    }
}

// ---------------- weight transpose+convert fp32 [K,N] -> fp16 [N,K] ----------------
__global__ void wtrans_h(const float* __restrict__ src, __half* __restrict__ dst, int K, int N) {
    __shared__ float t[32][33];
    int k0 = blockIdx.y*32, n0 = blockIdx.x*32;
    int tx = threadIdx.x, ty = threadIdx.y;
    #pragma unroll
    for (int i = 0; i < 4; i++)
        t[ty + i*8][tx] = src[(size_t)(k0 + ty + i*8)*N + n0 + tx];
    __syncthreads();
    #pragma unroll
    for (int i = 0; i < 4; i++)
        dst[(size_t)(n0 + ty + i*8)*K + k0 + tx] = __float2half(t[tx][ty + i*8]);
}

// ---------------- V transpose (fp16): qkv V-part [p][c] -> vt [b][c][p] ----------------
__global__ void vtrans(const __half* __restrict__ qkv, __half* __restrict__ vt) {
    __shared__ __half tile[32][33];
    int b = blockIdx.z;
    int p0 = blockIdx.x*32, c0 = blockIdx.y*32;
    int tx = threadIdx.x, ty = threadIdx.y;
    #pragma unroll
    for (int i = 0; i < 4; i++) {
        int p = p0 + ty + i*8;
        tile[ty + i*8][tx] = qkv[((size_t)(b*HW + p))*(3*CCH) + 2*CCH + c0 + tx];
    }
    __syncthreads();
    #pragma unroll
    for (int i = 0; i < 4; i++) {
        int c = c0 + ty + i*8;
        vt[((size_t)b*CCH + c)*HW + p0 + tx] = tile[tx][ty + i*8];
    }
}

// ---------------- straight convert fp32 -> fp16 ----------------
__global__ void cvt_h(const float* __restrict__ src, __half* __restrict__ dst, int n4) {
    int i = blockIdx.x * 256 + threadIdx.x;
    if (i >= n4) return;
    float4 v = ((const float4*)src)[i];
    __half2 p0 = __floats2half2_rn(v.x, v.y);
    __half2 p1 = __floats2half2_rn(v.z, v.w);
    union { uint2 u; __half2 h[2]; } pk; pk.h[0] = p0; pk.h[1] = p1;
    ((uint2*)dst)[i] = pk.u;
}

// ---------------- LayerNorm fp32 in -> fp16 out ----------------
__global__ __launch_bounds__(160)
void layernorm(const float* __restrict__ in,
               const float* __restrict__ s, const float* __restrict__ b,
               __half* __restrict__ out) {
    int row = blockIdx.x;
    int tid = threadIdx.x;
    const float4* r4 = (const float4*)(in + (size_t)row * CCH);
    float4 v = r4[tid];
    float sum = v.x + v.y + v.z + v.w;
    float sq  = v.x*v.x + v.y*v.y + v.z*v.z + v.w*v.w;
    #pragma unroll
    for (int o = 16; o > 0; o >>= 1) {
        sum += __shfl_xor_sync(~0u, sum, o);
        sq  += __shfl_xor_sync(~0u, sq,  o);
    }
    __shared__ float ws[5], wq[5];
    int w = tid >> 5;
    if ((tid & 31) == 0) { ws[w] = sum; wq[w] = sq; }
    __syncthreads();
    sum = ws[0] + ws[1] + ws[2] + ws[3] + ws[4];
    sq  = wq[0] + wq[1] + wq[2] + wq[3] + wq[4];
    float mu  = sum / (float)CCH;
    float inv = rsqrtf(sq / (float)CCH - mu*mu + 1e-5f);
    float4 sc = ((const float4*)s)[tid];
    float4 bb = ((const float4*)b)[tid];
    union { uint2 u; __half2 h[2]; } pk;
    pk.h[0] = __floats2half2_rn((v.x - mu) * inv * sc.x + bb.x, (v.y - mu) * inv * sc.y + bb.y);
    pk.h[1] = __floats2half2_rn((v.z - mu) * inv * sc.z + bb.z, (v.w - mu) * inv * sc.w + bb.w);
    ((uint2*)(out + (size_t)row * CCH))[tid] = pk.u;
}

// ---------------- mma / cp.async helpers ----------------
__device__ __forceinline__ void mma16h(float c[4], uint32_t a0, uint32_t a1, uint32_t a2, uint32_t a3,
                                       uint32_t b0, uint32_t b1) {
    asm volatile("mma.sync.aligned.m16n8k16.row.col.f32.f16.f16.f32 "
        "{%0,%1,%2,%3}, {%4,%5,%6,%7}, {%8,%9}, {%0,%1,%2,%3};"
        : "+f"(c[0]), "+f"(c[1]), "+f"(c[2]), "+f"(c[3])
        : "r"(a0), "r"(a1), "r"(a2), "r"(a3), "r"(b0), "r"(b1));
}
__device__ __forceinline__ void ldsm4(uint32_t r[4], uint32_t addr) {
    asm volatile("ldmatrix.sync.aligned.m8n8.x4.shared.b16 {%0,%1,%2,%3}, [%4];"
        : "=r"(r[0]), "=r"(r[1]), "=r"(r[2]), "=r"(r[3]) : "r"(addr));
}
__device__ __forceinline__ void cpa16(void* dst, const void* src, bool valid) {
    uint32_t d = (uint32_t)__cvta_generic_to_shared(dst);
    int sz = valid ? 16 : 0;
    asm volatile("cp.async.cg.shared.global [%0], [%1], 16, %2;" :: "r"(d), "l"(src), "r"(sz));
}
#define CP_COMMIT() asm volatile("cp.async.commit_group;")
#define CP_WAIT1()  asm volatile("cp.async.wait_group 1;")
#define CP_WAIT2()  asm volatile("cp.async.wait_group 2;")
__device__ __forceinline__ uint32_t hpack(float a, float b) {
    __half2 h = __floats2half2_rn(a, b);
    return *(uint32_t*)&h;
}

// ---------------- fp16 GEMM: 128x128x64, 3-stage cp.async + ldmatrix ----------------
#define RS36 36
#define BUFU (128*RS36)
#define NST  3
#define GEMM_SMEM (NST*2*BUFU*4)
__global__ __launch_bounds__(256)
void gemm_h(const __half* __restrict__ A, int lda,
            const __half* __restrict__ B,
            const float* __restrict__ bias,
            const float* __restrict__ res,
            float* __restrict__ C, __half* __restrict__ Ch, int ldc,
            int M, int N, int K) {
    extern __shared__ uint32_t sm[];
    uint32_t* As = sm;
    uint32_t* Bs = sm + NST*BUFU;
    uint32_t a_u32 = (uint32_t)__cvta_generic_to_shared(As);

    int tid = threadIdx.x;
    int lane = tid & 31, warp = tid >> 5;
    int gr = lane >> 2, t4 = lane & 3;
    int wm = (warp >> 2) * 64, wn = (warp & 3) * 32;
    int bm = blockIdx.y * 128, bn = blockIdx.x * 128;

    uint32_t lds_off = (uint32_t)((lane & 15) * (RS36*4) + ((lane >> 4) << 4));

    auto stage = [&](int kt, int buf) {
        #pragma unroll
        for (int i = 0; i < 4; i++) {
            int c = tid + i*256;
            int row = c >> 3, seg = c & 7;
            int gm = bm + row;
            cpa16(As + buf*BUFU + row*RS36 + seg*4,
                  A + ((size_t)(gm < M ? gm : 0))*lda + kt*64 + seg*8, gm < M);
        }
        #pragma unroll
        for (int i = 0; i < 4; i++) {
            int c = tid + i*256;
            int row = c >> 3, seg = c & 7;
            int gn = bn + row;
            cpa16(Bs + buf*BUFU + row*RS36 + seg*4,
                  B + ((size_t)(gn < N ? gn : 0))*K + kt*64 + seg*8, gn < N);
        }
    };

    float acc[4][4][4];
    #pragma unroll
    for (int i = 0; i < 4; i++)
        #pragma unroll
        for (int j = 0; j < 4; j++)
            #pragma unroll
            for (int r = 0; r < 4; r++) acc[i][j][r] = 0.f;

    int nk = K >> 6;
    stage(0, 0); CP_COMMIT();
    stage(1, 1); CP_COMMIT();

    int buf = 0;
    for (int t = 0; t < nk; t++) {
        if (t + 2 < nk) stage(t+2, (t+2) % NST);
        CP_COMMIT();
        CP_WAIT2();
        __syncthreads();

        const uint32_t* B_s = Bs + buf*BUFU;
        uint32_t a_base = a_u32 + buf*(BUFU*4) + lds_off;

        #pragma unroll
        for (int ks = 0; ks < 4; ks++) {
            uint32_t af[4][4], bf[4][2];
            #pragma unroll
            for (int mi = 0; mi < 4; mi++)
                ldsm4(af[mi], a_base + (uint32_t)((wm + mi*16)*(RS36*4) + ks*32));
            #pragma unroll
            for (int ni = 0; ni < 4; ni++) {
                int n0 = wn + ni*8 + gr;
                bf[ni][0] = B_s[n0*RS36 + ks*8 + t4];
                bf[ni][1] = B_s[n0*RS36 + ks*8 + t4 + 4];
            }
            #pragma unroll
            for (int mi = 0; mi < 4; mi++)
                #pragma unroll
                for (int ni = 0; ni < 4; ni++)
                    mma16h(acc[mi][ni], af[mi][0], af[mi][1], af[mi][2], af[mi][3],
                           bf[ni][0], bf[ni][1]);
        }
        __syncthreads();
        buf = (buf + 1 == NST) ? 0 : buf + 1;
    }

    #pragma unroll
    for (int mi = 0; mi < 4; mi++) {
        #pragma unroll
        for (int ni = 0; ni < 4; ni++) {
            int col0 = bn + wn + ni*8 + t4*2;
            #pragma unroll
            for (int half_r = 0; half_r < 2; half_r++) {
                int row = bm + wm + mi*16 + gr + half_r*8;
                if (row >= M) continue;
                float v0 = acc[mi][ni][half_r*2 + 0];
                float v1 = acc[mi][ni][half_r*2 + 1];
                if (bias) { v0 += bias[col0]; v1 += bias[col0+1]; }
                if (res) {
                    const float* rp = res + (size_t)row*ldc + col0;
                    v0 += rp[0]; v1 += rp[1];
                }
                if (C) *(float2*)(C + (size_t)row*ldc + col0) = make_float2(v0, v1);
                if (Ch) *(__half2*)(Ch + (size_t)row*ldc + col0) = __floats2half2_rn(v0, v1);
            }
        }
    }
}

// ---------------- fused flash self-attention, full fp16 mma ----------------
// K tile: [64 keys][88 halves], Vt tile: [80 dh][72 halves]. Double-buffered cp.async.
#define KSR 88
#define VSR 72
__global__ __launch_bounds__(256)
void flash_h(const __half* __restrict__ QKV, const __half* __restrict__ VT,
             __half* __restrict__ O) {
    constexpr int LD = 3*CCH;
    __shared__ __half Ks[2][64*KSR];
    __shared__ __half Vs[2][80*VSR];

    int tid = threadIdx.x, lane = tid & 31, w = tid >> 5;
    int z = blockIdx.y;
    int b = z >> 3, h = z & 7;
    int q0 = blockIdx.x * 128;
    int gr = lane >> 2, t4 = lane & 3;

    const __half* Kb  = QKV + ((size_t)b*HW)*LD + CCH + h*DH;
    const __half* Vtb = VT + ((size_t)b*CCH + h*DH)*HW;

    auto stage = [&](int kt, int buf) {
        // K: 64 rows x 10 segs of 16B
        #pragma unroll
        for (int i = 0; i < 3; i++) {
            int s = tid + i*256;
            if (s < 640) {
                int r = s / 10, g = s - r*10;
                cpa16(&Ks[buf][r*KSR + g*8], Kb + (size_t)(kt*64 + r)*LD + g*8, true);
            }
        }
        // Vt: 80 rows x 8 segs of 16B
        #pragma unroll
        for (int i = 0; i < 3; i++) {
            int s = tid + i*256;
            if (s < 640) {
                int r = s >> 3, g = s & 7;
                cpa16(&Vs[buf][r*VSR + g*8], Vtb + (size_t)r*HW + kt*64 + g*8, true);
            }
        }
    };

    stage(0, 0);
    CP_COMMIT();

    // Q fragments fp16 (scaled)
    const __half2 qs2 = __float2half2_rn(0.1118033988749895f);
    uint32_t qf[5][4];
    {
        const __half* qp  = QKV + (size_t)(b*HW + q0 + w*16 + gr)*LD + h*DH;
        const __half* qp8 = qp + 8*LD;
        #pragma unroll
        for (int ks = 0; ks < 5; ks++) {
            __half2 v0 = __hmul2(*(const __half2*)(qp  + ks*16 + 2*t4),     qs2);
            __half2 v1 = __hmul2(*(const __half2*)(qp8 + ks*16 + 2*t4),     qs2);
            __half2 v2 = __hmul2(*(const __half2*)(qp  + ks*16 + 8 + 2*t4), qs2);
            __half2 v3 = __hmul2(*(const __half2*)(qp8 + ks*16 + 8 + 2*t4), qs2);
            qf[ks][0] = *(uint32_t*)&v0; qf[ks][1] = *(uint32_t*)&v1;
            qf[ks][2] = *(uint32_t*)&v2; qf[ks][3] = *(uint32_t*)&v3;
        }
    }

    float m0v = -1e30f, m1v = -1e30f, l0 = 0.f, l1 = 0.f;
    float oa[10][4];
    #pragma unroll
    for (int ni = 0; ni < 10; ni++) { oa[ni][0]=oa[ni][1]=oa[ni][2]=oa[ni][3]=0.f; }

    for (int kt = 0; kt < 16; kt++) {
        if (kt + 1 < 16) stage(kt+1, (kt+1) & 1);
        CP_COMMIT();
        CP_WAIT1();
        __syncthreads();
        const __half* Kc = Ks[kt & 1];
        const __half* Vc = Vs[kt & 1];

        // S = Q @ K^T : 16 x 64 per warp, 5 k16-steps x 8 n-blocks
        float s[8][4];
        #pragma unroll
        for (int ni = 0; ni < 8; ni++) { s[ni][0]=s[ni][1]=s[ni][2]=s[ni][3]=0.f; }
        #pragma unroll
        for (int ks = 0; ks < 5; ks++) {
            #pragma unroll
            for (int ni = 0; ni < 8; ni++) {
                uint32_t b0 = *(const uint32_t*)&Kc[(8*ni + gr)*KSR + ks*16 + 2*t4];
                uint32_t b1 = *(const uint32_t*)&Kc[(8*ni + gr)*KSR + ks*16 + 8 + 2*t4];
                mma16h(s[ni], qf[ks][0], qf[ks][1], qf[ks][2], qf[ks][3], b0, b1);
            }
        }

        // online softmax
        float tm0 = -1e30f, tm1 = -1e30f;
        #pragma unroll
        for (int ni = 0; ni < 8; ni++) {
            tm0 = fmaxf(tm0, fmaxf(s[ni][0], s[ni][1]));
            tm1 = fmaxf(tm1, fmaxf(s[ni][2], s[ni][3]));
        }
        tm0 = fmaxf(tm0, __shfl_xor_sync(~0u, tm0, 1));
        tm0 = fmaxf(tm0, __shfl_xor_sync(~0u, tm0, 2));
        tm1 = fmaxf(tm1, __shfl_xor_sync(~0u, tm1, 1));
        tm1 = fmaxf(tm1, __shfl_xor_sync(~0u, tm1, 2));
        float mn0 = fmaxf(m0v, tm0), mn1 = fmaxf(m1v, tm1);
        float al0 = __expf(m0v - mn0), al1 = __expf(m1v - mn1);
        m0v = mn0; m1v = mn1;
        float ts0 = 0.f, ts1 = 0.f;
        #pragma unroll
        for (int ni = 0; ni < 8; ni++) {
            s[ni][0] = __expf(s[ni][0] - mn0);
            s[ni][1] = __expf(s[ni][1] - mn0);
            s[ni][2] = __expf(s[ni][2] - mn1);
            s[ni][3] = __expf(s[ni][3] - mn1);
            ts0 += s[ni][0] + s[ni][1];
            ts1 += s[ni][2] + s[ni][3];
        }
        ts0 += __shfl_xor_sync(~0u, ts0, 1); ts0 += __shfl_xor_sync(~0u, ts0, 2);
        ts1 += __shfl_xor_sync(~0u, ts1, 1); ts1 += __shfl_xor_sync(~0u, ts1, 2);
        l0 = l0*al0 + ts0;
        l1 = l1*al1 + ts1;
        #pragma unroll
        for (int ni = 0; ni < 10; ni++) {
            oa[ni][0] *= al0; oa[ni][1] *= al0;
            oa[ni][2] *= al1; oa[ni][3] *= al1;
        }

        // O += P @ V : P fragments are direct register packs of the score C-frags
        #pragma unroll
        for (int ks = 0; ks < 4; ks++) {
            uint32_t a0 = hpack(s[2*ks][0],   s[2*ks][1]);
            uint32_t a1 = hpack(s[2*ks][2],   s[2*ks][3]);
            uint32_t a2 = hpack(s[2*ks+1][0], s[2*ks+1][1]);
            uint32_t a3 = hpack(s[2*ks+1][2], s[2*ks+1][3]);
            #pragma unroll
            for (int ni = 0; ni < 10; ni++) {
                uint32_t b0 = *(const uint32_t*)&Vc[(8*ni + gr)*VSR + ks*16 + 2*t4];
                uint32_t b1 = *(const uint32_t*)&Vc[(8*ni + gr)*VSR + ks*16 + 8 + 2*t4];
                mma16h(oa[ni], a0, a1, a2, a3, b0, b1);
            }
        }
        __syncthreads();
    }

    float inv0 = 1.f / l0, inv1 = 1.f / l1;
    __half* Ob = O + ((size_t)(b*HW + q0 + w*16))*CCH + h*DH;
    #pragma unroll
    for (int ni = 0; ni < 10; ni++) {
        *(__half2*)(Ob + (size_t)gr*CCH + 8*ni + 2*t4) =
            __floats2half2_rn(oa[ni][0]*inv0, oa[ni][1]*inv0);
        *(__half2*)(Ob + (size_t)(gr+8)*CCH + 8*ni + 2*t4) =
            __floats2half2_rn(oa[ni][2]*inv1, oa[ni][3]*inv1);
    }
}

// ---------------- tiled fp16 cross-attention (SK=77, padded to 80) ----------------
__global__ __launch_bounds__(256)
void xattn_h(const __half* __restrict__ Q, const __half* __restrict__ Kc_g,
             const __half* __restrict__ Vc_g, __half* __restrict__ O) {
    __shared__ __half Ks[80*KSR];
    __shared__ __half Vt[80*KSR];

    int tid = threadIdx.x, lane = tid & 31, w = tid >> 5;
    int z = blockIdx.y;
    int b = z >> 3, h = z & 7;
    int q0 = blockIdx.x * 128;
    int gr = lane >> 2, t4 = lane & 3;

    // zero both tiles (covers key padding 77..79)
    for (int i = tid; i < 80*KSR; i += 256) { Ks[i] = __half(0.f); Vt[i] = __half(0.f); }
    __syncthreads();

    const __half* kc = Kc_g + (size_t)(b*SKCTX)*CCH + h*DH;
    const __half* vc = Vc_g + (size_t)(b*SKCTX)*CCH + h*DH;
    for (int idx = tid; idx < SKCTX*40; idx += 256) {
        int key = idx / 40, d2 = idx - key*40;
        __half2 kv = *(const __half2*)(kc + (size_t)key*CCH + 2*d2);
        __half2 vv = *(const __half2*)(vc + (size_t)key*CCH + 2*d2);
        *(__half2*)&Ks[key*KSR + 2*d2] = kv;
        Vt[(2*d2)*KSR + key]   = vv.x;
        Vt[(2*d2+1)*KSR + key] = vv.y;
    }
    __syncthreads();

    // Q fragments (scaled)
    const __half2 qs2 = __float2half2_rn(0.1118033988749895f);
    uint32_t qf[5][4];
    {
        const __half* qp  = Q + (size_t)(b*HW + q0 + w*16 + gr)*CCH + h*DH;
        const __half* qp8 = qp + 8*CCH;
        #pragma unroll
        for (int ks = 0; ks < 5; ks++) {
            __half2 v0 = __hmul2(*(const __half2*)(qp  + ks*16 + 2*t4),     qs2);
            __half2 v1 = __hmul2(*(const __half2*)(qp8 + ks*16 + 2*t4),     qs2);
            __half2 v2 = __hmul2(*(const __half2*)(qp  + ks*16 + 8 + 2*t4), qs2);
            __half2 v3 = __hmul2(*(const __half2*)(qp8 + ks*16 + 8 + 2*t4), qs2);
            qf[ks][0] = *(uint32_t*)&v0; qf[ks][1] = *(uint32_t*)&v1;
            qf[ks][2] = *(uint32_t*)&v2; qf[ks][3] = *(uint32_t*)&v3;
        }
    }

    // S = Q @ K^T : 16 x 80 per warp
    float s[10][4];
    #pragma unroll
    for (int ni = 0; ni < 10; ni++) { s[ni][0]=s[ni][1]=s[ni][2]=s[ni][3]=0.f; }
    #pragma unroll
    for (int ks = 0; ks < 5; ks++) {
        #pragma unroll
        for (int ni = 0; ni < 10; ni++) {
            uint32_t b0 = *(const uint32_t*)&Ks[(8*ni + gr)*KSR + ks*16 + 2*t4];
            uint32_t b1 = *(const uint32_t*)&Ks[(8*ni + gr)*KSR + ks*16 + 8 + 2*t4];
            mma16h(s[ni], qf[ks][0], qf[ks][1], qf[ks][2], qf[ks][3], b0, b1);
        }
    }
    // mask padded keys (cols 77..79 live in ni=9: col0 = 72+2t4, col1 = col0+1)
    if (t4 == 3) { s[9][0] = -1e30f; s[9][2] = -1e30f; }
    if (t4 >= 2) { s[9][1] = -1e30f; s[9][3] = -1e30f; }

    // softmax (single tile)
    float m0 = -1e30f, m1 = -1e30f;
    #pragma unroll
    for (int ni = 0; ni < 10; ni++) {
        m0 = fmaxf(m0, fmaxf(s[ni][0], s[ni][1]));
        m1 = fmaxf(m1, fmaxf(s[ni][2], s[ni][3]));
    }
    m0 = fmaxf(m0, __shfl_xor_sync(~0u, m0, 1));
    m0 = fmaxf(m0, __shfl_xor_sync(~0u, m0, 2));
    m1 = fmaxf(m1, __shfl_xor_sync(~0u, m1, 1));
    m1 = fmaxf(m1, __shfl_xor_sync(~0u, m1, 2));
    float l0 = 0.f, l1 = 0.f;
    #pragma unroll
    for (int ni = 0; ni < 10; ni++) {
        s[ni][0] = __expf(s[ni][0] - m0);
        s[ni][1] = __expf(s[ni][1] - m0);
        s[ni][2] = __expf(s[ni][2] - m1);
        s[ni][3] = __expf(s[ni][3] - m1);
        l0 += s[ni][0] + s[ni][1];
        l1 += s[ni][2] + s[ni][3];
    }
    l0 += __shfl_xor_sync(~0u, l0, 1); l0 += __shfl_xor_sync(~0u, l0, 2);
    l1 += __shfl_xor_sync(~0u, l1, 1); l1 += __shfl_xor_sync(~0u, l1, 2);

    // O = P @ V : 5 k16 steps over 80 keys
    float oa[10][4];
    #pragma unroll
    for (int ni = 0; ni < 10; ni++) { oa[ni][0]=oa[ni][1]=oa[ni][2]=oa[ni][3]=0.f; }
    #pragma unroll
    for (int ks = 0; ks < 5; ks++) {
        uint32_t a0 = hpack(s[2*ks][0],   s[2*ks][1]);
        uint32_t a1 = hpack(s[2*ks][2],   s[2*ks][3]);
        uint32_t a2 = hpack(s[2*ks+1][0], s[2*ks+1][1]);
        uint32_t a3 = hpack(s[2*ks+1][2], s[2*ks+1][3]);
        #pragma unroll
        for (int ni = 0; ni < 10; ni++) {
            uint32_t b0 = *(const uint32_t*)&Vt[(8*ni + gr)*KSR + ks*16 + 2*t4];
            uint32_t b1 = *(const uint32_t*)&Vt[(8*ni + gr)*KSR + ks*16 + 8 + 2*t4];
            mma16h(oa[ni], a0, a1, a2, a3, b0, b1);
        }
    }

    float inv0 = 1.f / l0, inv1 = 1.f / l1;
    __half* Ob = O + ((size_t)(b*HW + q0 + w*16))*CCH + h*DH;
    #pragma unroll
    for (int ni = 0; ni < 10; ni++) {
        *(__half2*)(Ob + (size_t)gr*CCH + 8*ni + 2*t4) =
            __floats2half2_rn(oa[ni][0]*inv0, oa[ni][1]*inv0);
        *(__half2*)(Ob + (size_t)(gr+8)*CCH + 8*ni + 2*t4) =
            __floats2half2_rn(oa[ni][2]*inv1, oa[ni][3]*inv1);
    }
}

// ---------------- GeGLU: fp16 in, fp16 out ----------------
__global__ void geglu(const __half* __restrict__ ff, __half* __restrict__ out) {
    int idx = blockIdx.x * 256 + threadIdx.x;
    if (idx >= NB*HW*CCH) return;
    int m = idx / CCH;
    int j = idx % CCH;
    union { uint2 u; __half2 h[2]; } av, gv, rv;
    av.u = *(const uint2*)(ff + (size_t)m*8*CCH + j*4);
    gv.u = *(const uint2*)(ff + (size_t)m*8*CCH + 4*CCH + j*4);
    float a0 = __half2float(av.h[0].x), a1 = __half2float(av.h[0].y);
    float a2 = __half2float(av.h[1].x), a3 = __half2float(av.h[1].y);
    float g0 = __half2float(gv.h[0].x), g1 = __half2float(gv.h[0].y);
    float g2 = __half2float(gv.h[1].x), g3 = __half2float(gv.h[1].y);
    const float is2 = 0.70710678118654752f;
    rv.h[0] = __floats2half2_rn(a0 * 0.5f * g0 * (1.f + erff(g0*is2)),
                                a1 * 0.5f * g1 * (1.f + erff(g1*is2)));
    rv.h[1] = __floats2half2_rn(a2 * 0.5f * g2 * (1.f + erff(g2*is2)),
                                a3 * 0.5f * g3 * (1.f + erff(g3*is2)));
    *(uint2*)(out + (size_t)m*4*CCH + j*4) = rv.u;
}

// ---------------- final transpose + residual ----------------
__global__ void final_add(const float* __restrict__ tmp, const float* __restrict__ xin,
                          float* __restrict__ out) {
    __shared__ float tile[32][33];
    int n = blockIdx.z;
    int p0 = blockIdx.x*32, c0 = blockIdx.y*32;
    int tx = threadIdx.x, ty = threadIdx.y;
    #pragma unroll
    for (int i = 0; i < 4; i++) {
        int p = p0 + ty + i*8;
        tile[ty + i*8][tx] = tmp[((size_t)n*HW + p)*CCH + c0 + tx];
    }
    __syncthreads();
    #pragma unroll
    for (int i = 0; i < 4; i++) {
        int c = c0 + ty + i*8;
        size_t o = ((size_t)n*CCH + c)*HW + p0 + tx;
        out[o] = tile[tx][ty + i*8] + xin[o];
    }
}

// ---------------- host launch ----------------
extern "C" void kernel_launch(void* const* d_in, const int* in_sizes, int n_in,
                              void* d_out, int out_size) {
    const float* x        = (const float*)d_in[0];
    const float* context  = (const float*)d_in[1];
    const float* gn_s     = (const float*)d_in[2];
    const float* gn_b     = (const float*)d_in[3];
    const float* conv1_w  = (const float*)d_in[4];
    const float* conv1_b  = (const float*)d_in[5];
    const float* ln1_s    = (const float*)d_in[6];
    const float* ln1_b    = (const float*)d_in[7];
    const float* sa_in_w  = (const float*)d_in[8];
    const float* sa_out_w = (const float*)d_in[9];
    const float* sa_out_b = (const float*)d_in[10];
    const float* ln2_s    = (const float*)d_in[11];
    const float* ln2_b    = (const float*)d_in[12];
    const float* ca_q_w   = (const float*)d_in[13];
    const float* ca_k_w   = (const float*)d_in[14];
    const float* ca_v_w   = (const float*)d_in[15];
    const float* ca_out_w = (const float*)d_in[16];
    const float* ca_out_b = (const float*)d_in[17];
    const float* ln3_s    = (const float*)d_in[18];
    const float* ln3_b    = (const float*)d_in[19];
    const float* lin1_w   = (const float*)d_in[20];
    const float* lin1_b   = (const float*)d_in[21];
    const float* lin2_w   = (const float*)d_in[22];
    const float* lin2_b   = (const float*)d_in[23];
    const float* co_w     = (const float*)d_in[24];
    const float* co_b     = (const float*)d_in[25];
    float* out = (float*)d_out;

    float *xseq, *tmp;
    __half *hgn, *ht, *hattn, *hctx, *hkc, *hvc, *hff, *hffg, *hx, *hqkv, *hvt, *hw;
    cudaGetSymbolAddress((void**)&xseq, g_xseq);
    cudaGetSymbolAddress((void**)&tmp,  g_tmp);
    cudaGetSymbolAddress((void**)&hgn,  h_gn);
    cudaGetSymbolAddress((void**)&ht,   h_t);
    cudaGetSymbolAddress((void**)&hattn,h_attn);
    cudaGetSymbolAddress((void**)&hctx, h_ctx);
    cudaGetSymbolAddress((void**)&hkc,  h_kctx);
    cudaGetSymbolAddress((void**)&hvc,  h_vctx);
    cudaGetSymbolAddress((void**)&hff,  h_ff);
    cudaGetSymbolAddress((void**)&hffg, h_ffg);
    cudaGetSymbolAddress((void**)&hx,   h_x);
    cudaGetSymbolAddress((void**)&hqkv, h_qkv);
    cudaGetSymbolAddress((void**)&hvt,  h_vt);
    cudaGetSymbolAddress((void**)&hw,   h_w);

    __half* sa_in_wT  = hw;
    __half* sa_out_wT = sa_in_wT  + 1920*640;
    __half* ca_q_wT   = sa_out_wT + 640*640;
    __half* ca_k_wT   = ca_q_wT   + 640*640;
    __half* ca_v_wT   = ca_k_wT   + 640*512;
    __half* ca_out_wT = ca_v_wT   + 640*512;
    __half* lin1_wT   = ca_out_wT + 640*640;
    __half* lin2_wT   = lin1_wT   + 5120*640;
    __half* conv1_wh  = lin2_wT   + 640*2560;
    __half* co_wh     = conv1_wh  + 640*640;

    cudaFuncSetAttribute(gemm_h, cudaFuncAttributeMaxDynamicSharedMemorySize, GEMM_SMEM);

    const int M = NB * HW;      // 8192
    const int MC = NB * SKCTX;  // 616
    dim3 tblk(32, 8);
    dim3 tgrid(HW/32, CCH/32, NB);
    auto ggrid = [](int N_, int M_) { return dim3(N_/128, (M_+127)/128); };

    // 0. weight conversion
    wtrans_h<<<dim3(3*CCH/32, CCH/32), tblk>>>(sa_in_w,  sa_in_wT,  CCH, 3*CCH);
    wtrans_h<<<dim3(CCH/32,   CCH/32), tblk>>>(sa_out_w, sa_out_wT, CCH, CCH);
    wtrans_h<<<dim3(CCH/32,   CCH/32), tblk>>>(ca_q_w,   ca_q_wT,   CCH, CCH);
    wtrans_h<<<dim3(CCH/32,  DCTX/32), tblk>>>(ca_k_w,   ca_k_wT,   DCTX, CCH);
    wtrans_h<<<dim3(CCH/32,  DCTX/32), tblk>>>(ca_v_w,   ca_v_wT,   DCTX, CCH);
    wtrans_h<<<dim3(CCH/32,   CCH/32), tblk>>>(ca_out_w, ca_out_wT, CCH, CCH);
    wtrans_h<<<dim3(8*CCH/32, CCH/32), tblk>>>(lin1_w,   lin1_wT,   CCH, 8*CCH);
    wtrans_h<<<dim3(CCH/32, 4*CCH/32), tblk>>>(lin2_w,   lin2_wT,   4*CCH, CCH);
    cvt_h<<<(CCH*CCH/4 + 255)/256, 256>>>(conv1_w, conv1_wh, CCH*CCH/4);
    cvt_h<<<(CCH*CCH/4 + 255)/256, 256>>>(co_w,    co_wh,    CCH*CCH/4);
    cvt_h<<<(MC*DCTX/4 + 255)/256, 256>>>(context, hctx,     MC*DCTX/4);

    // 1. GroupNorm + transpose (-> fp16)
    gn_stats<<<NB*GRP, 256>>>(x);
    gn_apply<<<tgrid, tblk>>>(x, gn_s, gn_b);

    // 2. conv1
    gemm_h<<<ggrid(CCH, M), 256, GEMM_SMEM>>>(hgn, CCH, conv1_wh, conv1_b, nullptr,
                                              xseq, nullptr, CCH, M, CCH, CCH);

    // 3. self-attention (all fp16)
    layernorm<<<M, 160>>>(xseq, ln1_s, ln1_b, ht);
    gemm_h<<<ggrid(3*CCH, M), 256, GEMM_SMEM>>>(ht, CCH, sa_in_wT, nullptr, nullptr,
                                                nullptr, hqkv, 3*CCH, M, 3*CCH, CCH);
    vtrans<<<dim3(HW/32, CCH/32, NB), tblk>>>(hqkv, hvt);
    flash_h<<<dim3(HW/128, NB*NH), 256>>>(hqkv, hvt, hattn);
    gemm_h<<<ggrid(CCH, M), 256, GEMM_SMEM>>>(hattn, CCH, sa_out_wT, sa_out_b, xseq,
                                              xseq, nullptr, CCH, M, CCH, CCH);

    // 4. cross-attention (all fp16)
    layernorm<<<M, 160>>>(xseq, ln2_s, ln2_b, ht);
    gemm_h<<<ggrid(CCH, M), 256, GEMM_SMEM>>>(ht, CCH, ca_q_wT, nullptr, nullptr,
                                              nullptr, hqkv, CCH, M, CCH, CCH);
    gemm_h<<<ggrid(CCH, MC), 256, GEMM_SMEM>>>(hctx, DCTX, ca_k_wT, nullptr, nullptr,
                                               nullptr, hkc, CCH, MC, CCH, DCTX);
    gemm_h<<<ggrid(CCH, MC), 256, GEMM_SMEM>>>(hctx, DCTX, ca_v_wT, nullptr, nullptr,
                                               nullptr, hvc, CCH, MC, CCH, DCTX);
    xattn_h<<<dim3(HW/128, NB*NH), 256>>>(hqkv, hkc, hvc, hattn);
    gemm_h<<<ggrid(CCH, M), 256, GEMM_SMEM>>>(hattn, CCH, ca_out_wT, ca_out_b, xseq,
                                              xseq, nullptr, CCH, M, CCH, CCH);

    // 5. GeGLU FFN
    layernorm<<<M, 160>>>(xseq, ln3_s, ln3_b, ht);
    gemm_h<<<ggrid(8*CCH, M), 256, GEMM_SMEM>>>(ht, CCH, lin1_wT, lin1_b, nullptr,
                                                nullptr, hff, 8*CCH, M, 8*CCH, CCH);
    geglu<<<(NB*HW*CCH + 255)/256, 256>>>(hff, hffg);
    gemm_h<<<ggrid(CCH, M), 256, GEMM_SMEM>>>(hffg, 4*CCH, lin2_wT, lin2_b, xseq,
                                              xseq, hx, CCH, M, CCH, 4*CCH);

    // 6. final conv + long residual
    gemm_h<<<ggrid(CCH, M), 256, GEMM_SMEM>>>(hx, CCH, co_wh, co_b, nullptr,
                                              tmp, nullptr, CCH, M, CCH, CCH);
    final_add<<<tgrid, tblk>>>(tmp, x, out);
}

// round 9
// speedup vs baseline: 29.4352x; 1.0395x over previous
#include <cuda_runtime.h>
#include <cuda_fp16.h>
#include <math.h>
#include <stdint.h>

#define NB    8
#define CCH   640
#define HW    1024
#define NH    8
#define DH    80
#define DCTX  512
#define GRP   32
#define CPG   20
#define SKCTX 77

// ---------------- fp32 scratch ----------------
__device__ float  g_xseq [NB*HW*CCH];
__device__ float  g_gnstat[NB*GRP*2];
__device__ float  g_lin1bi[8*CCH];       // interleaved lin1 bias
// ---------------- fp16 scratch ----------------
__device__ __half h_gn  [NB*HW*CCH];
__device__ __half h_t   [NB*HW*CCH];
__device__ __half h_attn[NB*HW*CCH];
__device__ __half h_ctx [NB*SKCTX*DCTX];
__device__ __half h_kctx[NB*SKCTX*CCH];
__device__ __half h_vctx[NB*SKCTX*CCH];
__device__ __half h_ffg [NB*HW*4*CCH];
__device__ __half h_x   [NB*HW*CCH];
__device__ __half h_qkv [NB*HW*3*CCH];
__device__ __half h_vt  [NB*CCH*HW];
__device__ __half h_w   [8847360];       // all weights, fp16, [N,K]

// ---------------- GroupNorm stats ----------------
__global__ void gn_stats(const float* __restrict__ x) {
    int ng = blockIdx.x;
    int n = ng / GRP, g = ng % GRP;
    const float4* base = (const float4*)(x + ((size_t)n*CCH + (size_t)g*CPG) * HW);
    float s = 0.f, s2 = 0.f;
    for (int i = threadIdx.x; i < CPG*HW/4; i += 256) {
        float4 v = base[i];
        s  += v.x + v.y + v.z + v.w;
        s2 += v.x*v.x + v.y*v.y + v.z*v.z + v.w*v.w;
    }
    __shared__ float rs[256], rq[256];
    rs[threadIdx.x] = s; rq[threadIdx.x] = s2;
    __syncthreads();
    for (int o = 128; o > 0; o >>= 1) {
        if (threadIdx.x < o) { rs[threadIdx.x] += rs[threadIdx.x+o]; rq[threadIdx.x] += rq[threadIdx.x+o]; }
        __syncthreads();
    }
    if (threadIdx.x == 0) {
        float inv_n = 1.f / (float)(CPG*HW);
        float mu  = rs[0] * inv_n;
        float var = rq[0] * inv_n - mu*mu;
        g_gnstat[ng*2]   = mu;
        g_gnstat[ng*2+1] = rsqrtf(var + 1e-6f);
    }
}

// ---------------- GroupNorm apply + transpose -> fp16 [n,p,c] ----------------
__global__ void gn_apply(const float* __restrict__ x,
                         const float* __restrict__ s, const float* __restrict__ b) {
    __shared__ float tile[32][33];
    int n = blockIdx.z;
    int p0 = blockIdx.x*32, c0 = blockIdx.y*32;
    int tx = threadIdx.x, ty = threadIdx.y;
    #pragma unroll
    for (int i = 0; i < 4; i++) {
        int c = c0 + ty + i*8;
        int ng = n*GRP + c / CPG;
        float mu = g_gnstat[ng*2], is = g_gnstat[ng*2+1];
        float v = x[((size_t)n*CCH + c)*HW + p0 + tx];
        tile[ty + i*8][tx] = (v - mu) * is * s[c] + b[c];
    }
    __syncthreads();
    #pragma unroll
    for (int i = 0; i < 4; i++) {
        int p = p0 + ty + i*8;
        h_gn[((size_t)n*HW + p)*CCH + c0 + tx] = __float2half(tile[tx][ty + i*8]);
    }
}

// ---------------- merged weight transpose+convert (8 segments, one launch) ----------------
struct WSeg { const float* src; __half* dst; int K, N, tilesX, tileOff, ileave; };
struct W8 { WSeg w[8]; };
__global__ void wtrans_all(W8 ws) {
    __shared__ float t[32][33];
    int bid = blockIdx.x;
    int si = 0;
    #pragma unroll
    for (int i = 1; i < 8; i++)
        if (bid >= ws.w[i].tileOff) si = i;
    WSeg sg = ws.w[si];
    int local = bid - sg.tileOff;
    int n0 = (local % sg.tilesX) * 32;
    int k0 = (local / sg.tilesX) * 32;
    int tx = threadIdx.x, ty = threadIdx.y;
    #pragma unroll
    for (int i = 0; i < 4; i++)
        t[ty + i*8][tx] = sg.src[(size_t)(k0 + ty + i*8)*sg.N + n0 + tx];
    __syncthreads();
    int half = sg.N >> 1;
    #pragma unroll
    for (int i = 0; i < 4; i++) {
        int r = n0 + ty + i*8;
        int rr = sg.ileave ? ((r < half) ? 2*r : 2*(r - half) + 1) : r;
        sg.dst[(size_t)rr*sg.K + k0 + tx] = __float2half(t[tx][ty + i*8]);
    }
}

// ---------------- merged straight converts (3 segments) ----------------
__global__ void cvt_all(const float* s0, __half* d0, int e0,
                        const float* s1, __half* d1, int e1,
                        const float* s2, __half* d2, int e2) {
    int i = blockIdx.x * 256 + threadIdx.x;
    const float* s; __half* d; int off;
    if (i < e0) { s = s0; d = d0; off = i; }
    else if (i < e0 + e1) { s = s1; d = d1; off = i - e0; }
    else if (i < e0 + e1 + e2) { s = s2; d = d2; off = i - e0 - e1; }
    else return;
    float4 v = ((const float4*)s)[off];
    union { uint2 u; __half2 h[2]; } pk;
    pk.h[0] = __floats2half2_rn(v.x, v.y);
    pk.h[1] = __floats2half2_rn(v.z, v.w);
    ((uint2*)d)[off] = pk.u;
}

// ---------------- lin1 bias interleave ----------------
__global__ void bias_il(const float* __restrict__ b, float* __restrict__ bi) {
    int j = blockIdx.x * 256 + threadIdx.x;
    if (j < 4*CCH) {
        bi[2*j]   = b[j];
        bi[2*j+1] = b[j + 4*CCH];
    }
}

// ---------------- V transpose (fp16) ----------------
__global__ void vtrans(const __half* __restrict__ qkv, __half* __restrict__ vt) {
    __shared__ __half tile[32][33];
    int b = blockIdx.z;
    int p0 = blockIdx.x*32, c0 = blockIdx.y*32;
    int tx = threadIdx.x, ty = threadIdx.y;
    #pragma unroll
    for (int i = 0; i < 4; i++) {
        int p = p0 + ty + i*8;
        tile[ty + i*8][tx] = qkv[((size_t)(b*HW + p))*(3*CCH) + 2*CCH + c0 + tx];
    }
    __syncthreads();
    #pragma unroll
    for (int i = 0; i < 4; i++) {
        int c = c0 + ty + i*8;
        vt[((size_t)b*CCH + c)*HW + p0 + tx] = tile[tx][ty + i*8];
    }
}

// ---------------- LayerNorm fp32 in -> fp16 out ----------------
__global__ __launch_bounds__(160)
void layernorm(const float* __restrict__ in,
               const float* __restrict__ s, const float* __restrict__ b,
               __half* __restrict__ out) {
    int row = blockIdx.x;
    int tid = threadIdx.x;
    const float4* r4 = (const float4*)(in + (size_t)row * CCH);
    float4 v = r4[tid];
    float sum = v.x + v.y + v.z + v.w;
    float sq  = v.x*v.x + v.y*v.y + v.z*v.z + v.w*v.w;
    #pragma unroll
    for (int o = 16; o > 0; o >>= 1) {
        sum += __shfl_xor_sync(~0u, sum, o);
        sq  += __shfl_xor_sync(~0u, sq,  o);
    }
    __shared__ float ws[5], wq[5];
    int w = tid >> 5;
    if ((tid & 31) == 0) { ws[w] = sum; wq[w] = sq; }
    __syncthreads();
    sum = ws[0] + ws[1] + ws[2] + ws[3] + ws[4];
    sq  = wq[0] + wq[1] + wq[2] + wq[3] + wq[4];
    float mu  = sum / (float)CCH;
    float inv = rsqrtf(sq / (float)CCH - mu*mu + 1e-5f);
    float4 sc = ((const float4*)s)[tid];
    float4 bb = ((const float4*)b)[tid];
    union { uint2 u; __half2 h[2]; } pk;
    pk.h[0] = __floats2half2_rn((v.x - mu) * inv * sc.x + bb.x, (v.y - mu) * inv * sc.y + bb.y);
    pk.h[1] = __floats2half2_rn((v.z - mu) * inv * sc.z + bb.z, (v.w - mu) * inv * sc.w + bb.w);
    ((uint2*)(out + (size_t)row * CCH))[tid] = pk.u;
}

// ---------------- mma / cp.async helpers ----------------
__device__ __forceinline__ void mma16h(float c[4], uint32_t a0, uint32_t a1, uint32_t a2, uint32_t a3,
                                       uint32_t b0, uint32_t b1) {
    asm volatile("mma.sync.aligned.m16n8k16.row.col.f32.f16.f16.f32 "
        "{%0,%1,%2,%3}, {%4,%5,%6,%7}, {%8,%9}, {%0,%1,%2,%3};"
        : "+f"(c[0]), "+f"(c[1]), "+f"(c[2]), "+f"(c[3])
        : "r"(a0), "r"(a1), "r"(a2), "r"(a3), "r"(b0), "r"(b1));
}
__device__ __forceinline__ void ldsm4(uint32_t r[4], uint32_t addr) {
    asm volatile("ldmatrix.sync.aligned.m8n8.x4.shared.b16 {%0,%1,%2,%3}, [%4];"
        : "=r"(r[0]), "=r"(r[1]), "=r"(r[2]), "=r"(r[3]) : "r"(addr));
}
__device__ __forceinline__ void cpa16(void* dst, const void* src, bool valid) {
    uint32_t d = (uint32_t)__cvta_generic_to_shared(dst);
    int sz = valid ? 16 : 0;
    asm volatile("cp.async.cg.shared.global [%0], [%1], 16, %2;" :: "r"(d), "l"(src), "r"(sz));
}
#define CP_COMMIT() asm volatile("cp.async.commit_group;")
#define CP_WAIT1()  asm volatile("cp.async.wait_group 1;")
__device__ __forceinline__ uint32_t hpack(float a, float b) {
    __half2 h = __floats2half2_rn(a, b);
    return *(uint32_t*)&h;
}

// ---------------- fp16 GEMM: 128x128x64, 3-stage cp.async + ldmatrix ----------------
// MODE 0: normal (bias/res, fp32 and/or fp16 out)
// MODE 1: geglu epilogue (interleaved a/g columns; half out at col/2, row stride ldc)
// MODE 2: transposed NCHW out + residual (res = x in NCHW, C = out in NCHW)
#define RS36 36
#define BUFU (128*RS36)
#define NST  3
#define GEMM_SMEM (NST*2*BUFU*4)
template<int MODE>
__global__ __launch_bounds__(256)
void gemm_h(const __half* __restrict__ A, int lda,
            const __half* __restrict__ B,
            const float* __restrict__ bias,
            const float* __restrict__ res,
            float* __restrict__ C, __half* __restrict__ Ch, int ldc,
            int M, int N, int K) {
    extern __shared__ uint32_t sm[];
    uint32_t* As = sm;
    uint32_t* Bs = sm + NST*BUFU;
    uint32_t a_u32 = (uint32_t)__cvta_generic_to_shared(As);

    int tid = threadIdx.x;
    int lane = tid & 31, warp = tid >> 5;
    int gr = lane >> 2, t4 = lane & 3;
    int wm = (warp >> 2) * 64, wn = (warp & 3) * 32;
    int bm = blockIdx.y * 128, bn = blockIdx.x * 128;

    uint32_t lds_off = (uint32_t)((lane & 15) * (RS36*4) + ((lane >> 4) << 4));

    auto stage = [&](int kt, int buf) {
        #pragma unroll
        for (int i = 0; i < 4; i++) {
            int c = tid + i*256;
            int row = c >> 3, seg = c & 7;
            int gm = bm + row;
            cpa16(As + buf*BUFU + row*RS36 + seg*4,
                  A + ((size_t)(gm < M ? gm : 0))*lda + kt*64 + seg*8, gm < M);
        }
        #pragma unroll
        for (int i = 0; i < 4; i++) {
            int c = tid + i*256;
            int row = c >> 3, seg = c & 7;
            int gn = bn + row;
            cpa16(Bs + buf*BUFU + row*RS36 + seg*4,
                  B + ((size_t)(gn < N ? gn : 0))*K + kt*64 + seg*8, gn < N);
        }
    };

    float acc[4][4][4];
    #pragma unroll
    for (int i = 0; i < 4; i++)
        #pragma unroll
        for (int j = 0; j < 4; j++)
            #pragma unroll
            for (int r = 0; r < 4; r++) acc[i][j][r] = 0.f;

    int nk = K >> 6;
    stage(0, 0); CP_COMMIT();
    stage(1, 1); CP_COMMIT();

    int buf = 0;
    for (int t = 0; t < nk; t++) {
        CP_WAIT1();                       // tile t resident
        __syncthreads();                  // everyone done with compute(t-1)
        if (t + 2 < nk) stage(t+2, (t+2) % NST);
        CP_COMMIT();

        const uint32_t* B_s = Bs + buf*BUFU;
        uint32_t a_base = a_u32 + buf*(BUFU*4) + lds_off;

        #pragma unroll
        for (int ks = 0; ks < 4; ks++) {
            uint32_t af[4][4], bf[4][2];
            #pragma unroll
            for (int mi = 0; mi < 4; mi++)
                ldsm4(af[mi], a_base + (uint32_t)((wm + mi*16)*(RS36*4) + ks*32));
            #pragma unroll
            for (int ni = 0; ni < 4; ni++) {
                int n0 = wn + ni*8 + gr;
                bf[ni][0] = B_s[n0*RS36 + ks*8 + t4];
                bf[ni][1] = B_s[n0*RS36 + ks*8 + t4 + 4];
            }
            #pragma unroll
            for (int mi = 0; mi < 4; mi++)
                #pragma unroll
                for (int ni = 0; ni < 4; ni++)
                    mma16h(acc[mi][ni], af[mi][0], af[mi][1], af[mi][2], af[mi][3],
                           bf[ni][0], bf[ni][1]);
        }
        buf = (buf + 1 == NST) ? 0 : buf + 1;
    }

    if (MODE == 2) {
        // transposed epilogue: eb[c][p], then coalesced NCHW store + residual
        __syncthreads();
        float* eb = (float*)sm;          // [128][132]
        #pragma unroll
        for (int mi = 0; mi < 4; mi++) {
            #pragma unroll
            for (int ni = 0; ni < 4; ni++) {
                int col_l = wn + ni*8 + t4*2;
                int col0  = bn + col_l;
                #pragma unroll
                for (int half_r = 0; half_r < 2; half_r++) {
                    int row_l = wm + mi*16 + gr + half_r*8;
                    eb[(col_l)*132 + row_l]   = acc[mi][ni][half_r*2 + 0] + bias[col0];
                    eb[(col_l+1)*132 + row_l] = acc[mi][ni][half_r*2 + 1] + bias[col0+1];
                }
            }
        }
        __syncthreads();
        int n = bm >> 10, p0 = bm & 1023;
        for (int i = tid; i < 128*32; i += 256) {
            int c = i >> 5, seg = i & 5 ? (i & 31) : (i & 31);  // seg = i & 31
            seg = i & 31;
            size_t off = ((size_t)(n*CCH + bn + c))*HW + p0 + seg*4;
            const float* e = eb + c*132 + seg*4;
            float4 xr = *(const float4*)(res + off);
            float4 v = make_float4(e[0] + xr.x, e[1] + xr.y, e[2] + xr.z, e[3] + xr.w);
            *(float4*)(C + off) = v;
        }
        return;
    }

    #pragma unroll
    for (int mi = 0; mi < 4; mi++) {
        #pragma unroll
        for (int ni = 0; ni < 4; ni++) {
            int col0 = bn + wn + ni*8 + t4*2;
            #pragma unroll
            for (int half_r = 0; half_r < 2; half_r++) {
                int row = bm + wm + mi*16 + gr + half_r*8;
                if (row >= M) continue;
                float v0 = acc[mi][ni][half_r*2 + 0];
                float v1 = acc[mi][ni][half_r*2 + 1];
                if (MODE == 1) {
                    float a = v0 + bias[col0];
                    float g = v1 + bias[col0+1];
                    float ge = 0.5f * g * (1.f + erff(g * 0.70710678118654752f));
                    Ch[(size_t)row*ldc + (col0 >> 1)] = __float2half(a * ge);
                } else {
                    if (bias) { v0 += bias[col0]; v1 += bias[col0+1]; }
                    if (res) {
                        const float* rp = res + (size_t)row*ldc + col0;
                        v0 += rp[0]; v1 += rp[1];
                    }
                    if (C) *(float2*)(C + (size_t)row*ldc + col0) = make_float2(v0, v1);
                    if (Ch) *(__half2*)(Ch + (size_t)row*ldc + col0) = __floats2half2_rn(v0, v1);
                }
            }
        }
    }
}

// ---------------- fused flash self-attention, full fp16 mma ----------------
#define KSR 88
#define VSR 72
__global__ __launch_bounds__(256)
void flash_h(const __half* __restrict__ QKV, const __half* __restrict__ VT,
             __half* __restrict__ O) {
    constexpr int LD = 3*CCH;
    __shared__ __half Ks[2][64*KSR];
    __shared__ __half Vs[2][80*VSR];

    int tid = threadIdx.x, lane = tid & 31, w = tid >> 5;
    int z = blockIdx.y;
    int b = z >> 3, h = z & 7;
    int q0 = blockIdx.x * 128;
    int gr = lane >> 2, t4 = lane & 3;

    const __half* Kb  = QKV + ((size_t)b*HW)*LD + CCH + h*DH;
    const __half* Vtb = VT + ((size_t)b*CCH + h*DH)*HW;

    auto stage = [&](int kt, int buf) {
        #pragma unroll
        for (int i = 0; i < 3; i++) {
            int s = tid + i*256;
            if (s < 640) {
                int r = s / 10, g = s - r*10;
                cpa16(&Ks[buf][r*KSR + g*8], Kb + (size_t)(kt*64 + r)*LD + g*8, true);
            }
        }
        #pragma unroll
        for (int i = 0; i < 3; i++) {
            int s = tid + i*256;
            if (s < 640) {
                int r = s >> 3, g = s & 7;
                cpa16(&Vs[buf][r*VSR + g*8], Vtb + (size_t)r*HW + kt*64 + g*8, true);
            }
        }
    };

    stage(0, 0);
    CP_COMMIT();

    const __half2 qs2 = __float2half2_rn(0.1118033988749895f);
    uint32_t qf[5][4];
    {
        const __half* qp  = QKV + (size_t)(b*HW + q0 + w*16 + gr)*LD + h*DH;
        const __half* qp8 = qp + 8*LD;
        #pragma unroll
        for (int ks = 0; ks < 5; ks++) {
            __half2 v0 = __hmul2(*(const __half2*)(qp  + ks*16 + 2*t4),     qs2);
            __half2 v1 = __hmul2(*(const __half2*)(qp8 + ks*16 + 2*t4),     qs2);
            __half2 v2 = __hmul2(*(const __half2*)(qp  + ks*16 + 8 + 2*t4), qs2);
            __half2 v3 = __hmul2(*(const __half2*)(qp8 + ks*16 + 8 + 2*t4), qs2);
            qf[ks][0] = *(uint32_t*)&v0; qf[ks][1] = *(uint32_t*)&v1;
            qf[ks][2] = *(uint32_t*)&v2; qf[ks][3] = *(uint32_t*)&v3;
        }
    }

    float m0v = -1e30f, m1v = -1e30f, l0 = 0.f, l1 = 0.f;
    float oa[10][4];
    #pragma unroll
    for (int ni = 0; ni < 10; ni++) { oa[ni][0]=oa[ni][1]=oa[ni][2]=oa[ni][3]=0.f; }

    for (int kt = 0; kt < 16; kt++) {
        if (kt + 1 < 16) stage(kt+1, (kt+1) & 1);
        CP_COMMIT();
        CP_WAIT1();
        __syncthreads();
        const __half* Kc = Ks[kt & 1];
        const __half* Vc = Vs[kt & 1];

        float s[8][4];
        #pragma unroll
        for (int ni = 0; ni < 8; ni++) { s[ni][0]=s[ni][1]=s[ni][2]=s[ni][3]=0.f; }
        #pragma unroll
        for (int ks = 0; ks < 5; ks++) {
            #pragma unroll
            for (int ni = 0; ni < 8; ni++) {
                uint32_t b0 = *(const uint32_t*)&Kc[(8*ni + gr)*KSR + ks*16 + 2*t4];
                uint32_t b1 = *(const uint32_t*)&Kc[(8*ni + gr)*KSR + ks*16 + 8 + 2*t4];
                mma16h(s[ni], qf[ks][0], qf[ks][1], qf[ks][2], qf[ks][3], b0, b1);
            }
        }

        float tm0 = -1e30f, tm1 = -1e30f;
        #pragma unroll
        for (int ni = 0; ni < 8; ni++) {
            tm0 = fmaxf(tm0, fmaxf(s[ni][0], s[ni][1]));
            tm1 = fmaxf(tm1, fmaxf(s[ni][2], s[ni][3]));
        }
        tm0 = fmaxf(tm0, __shfl_xor_sync(~0u, tm0, 1));
        tm0 = fmaxf(tm0, __shfl_xor_sync(~0u, tm0, 2));
        tm1 = fmaxf(tm1, __shfl_xor_sync(~0u, tm1, 1));
        tm1 = fmaxf(tm1, __shfl_xor_sync(~0u, tm1, 2));
        float mn0 = fmaxf(m0v, tm0), mn1 = fmaxf(m1v, tm1);
        float al0 = __expf(m0v - mn0), al1 = __expf(m1v - mn1);
        m0v = mn0; m1v = mn1;
        float ts0 = 0.f, ts1 = 0.f;
        #pragma unroll
        for (int ni = 0; ni < 8; ni++) {
            s[ni][0] = __expf(s[ni][0] - mn0);
            s[ni][1] = __expf(s[ni][1] - mn0);
            s[ni][2] = __expf(s[ni][2] - mn1);
            s[ni][3] = __expf(s[ni][3] - mn1);
            ts0 += s[ni][0] + s[ni][1];
            ts1 += s[ni][2] + s[ni][3];
        }
        ts0 += __shfl_xor_sync(~0u, ts0, 1); ts0 += __shfl_xor_sync(~0u, ts0, 2);
        ts1 += __shfl_xor_sync(~0u, ts1, 1); ts1 += __shfl_xor_sync(~0u, ts1, 2);
        l0 = l0*al0 + ts0;
        l1 = l1*al1 + ts1;
        #pragma unroll
        for (int ni = 0; ni < 10; ni++) {
            oa[ni][0] *= al0; oa[ni][1] *= al0;
            oa[ni][2] *= al1; oa[ni][3] *= al1;
        }

        #pragma unroll
        for (int ks = 0; ks < 4; ks++) {
            uint32_t a0 = hpack(s[2*ks][0],   s[2*ks][1]);
            uint32_t a1 = hpack(s[2*ks][2],   s[2*ks][3]);
            uint32_t a2 = hpack(s[2*ks+1][0], s[2*ks+1][1]);
            uint32_t a3 = hpack(s[2*ks+1][2], s[2*ks+1][3]);
            #pragma unroll
            for (int ni = 0; ni < 10; ni++) {
                uint32_t b0 = *(const uint32_t*)&Vc[(8*ni + gr)*VSR + ks*16 + 2*t4];
                uint32_t b1 = *(const uint32_t*)&Vc[(8*ni + gr)*VSR + ks*16 + 8 + 2*t4];
                mma16h(oa[ni], a0, a1, a2, a3, b0, b1);
            }
        }
        __syncthreads();
    }

    float inv0 = 1.f / l0, inv1 = 1.f / l1;
    __half* Ob = O + ((size_t)(b*HW + q0 + w*16))*CCH + h*DH;
    #pragma unroll
    for (int ni = 0; ni < 10; ni++) {
        *(__half2*)(Ob + (size_t)gr*CCH + 8*ni + 2*t4) =
            __floats2half2_rn(oa[ni][0]*inv0, oa[ni][1]*inv0);
        *(__half2*)(Ob + (size_t)(gr+8)*CCH + 8*ni + 2*t4) =
            __floats2half2_rn(oa[ni][2]*inv1, oa[ni][3]*inv1);
    }
}

// ---------------- tiled fp16 cross-attention (SK=77, padded to 80) ----------------
__global__ __launch_bounds__(256)
void xattn_h(const __half* __restrict__ Q, const __half* __restrict__ Kc_g,
             const __half* __restrict__ Vc_g, __half* __restrict__ O) {
    __shared__ __half Ks[80*KSR];
    __shared__ __half Vt[80*KSR];

    int tid = threadIdx.x, lane = tid & 31, w = tid >> 5;
    int z = blockIdx.y;
    int b = z >> 3, h = z & 7;
    int q0 = blockIdx.x * 128;
    int gr = lane >> 2, t4 = lane & 3;

    for (int i = tid; i < 80*KSR; i += 256) { Ks[i] = __half(0.f); Vt[i] = __half(0.f); }
    __syncthreads();

    const __half* kc = Kc_g + (size_t)(b*SKCTX)*CCH + h*DH;
    const __half* vc = Vc_g + (size_t)(b*SKCTX)*CCH + h*DH;
    for (int idx = tid; idx < SKCTX*40; idx += 256) {
        int key = idx / 40, d2 = idx - key*40;
        __half2 kv = *(const __half2*)(kc + (size_t)key*CCH + 2*d2);
        __half2 vv = *(const __half2*)(vc + (size_t)key*CCH + 2*d2);
        *(__half2*)&Ks[key*KSR + 2*d2] = kv;
        Vt[(2*d2)*KSR + key]   = vv.x;
        Vt[(2*d2+1)*KSR + key] = vv.y;
    }
    __syncthreads();

    const __half2 qs2 = __float2half2_rn(0.1118033988749895f);
    uint32_t qf[5][4];
    {
        const __half* qp  = Q + (size_t)(b*HW + q0 + w*16 + gr)*CCH + h*DH;
        const __half* qp8 = qp + 8*CCH;
        #pragma unroll
        for (int ks = 0; ks < 5; ks++) {
            __half2 v0 = __hmul2(*(const __half2*)(qp  + ks*16 + 2*t4),     qs2);
            __half2 v1 = __hmul2(*(const __half2*)(qp8 + ks*16 + 2*t4),     qs2);
            __half2 v2 = __hmul2(*(const __half2*)(qp  + ks*16 + 8 + 2*t4), qs2);
            __half2 v3 = __hmul2(*(const __half2*)(qp8 + ks*16 + 8 + 2*t4), qs2);
            qf[ks][0] = *(uint32_t*)&v0; qf[ks][1] = *(uint32_t*)&v1;
            qf[ks][2] = *(uint32_t*)&v2; qf[ks][3] = *(uint32_t*)&v3;
        }
    }

    float s[10][4];
    #pragma unroll
    for (int ni = 0; ni < 10; ni++) { s[ni][0]=s[ni][1]=s[ni][2]=s[ni][3]=0.f; }
    #pragma unroll
    for (int ks = 0; ks < 5; ks++) {
        #pragma unroll
        for (int ni = 0; ni < 10; ni++) {
            uint32_t b0 = *(const uint32_t*)&Ks[(8*ni + gr)*KSR + ks*16 + 2*t4];
            uint32_t b1 = *(const uint32_t*)&Ks[(8*ni + gr)*KSR + ks*16 + 8 + 2*t4];
            mma16h(s[ni], qf[ks][0], qf[ks][1], qf[ks][2], qf[ks][3], b0, b1);
        }
    }
    if (t4 == 3) { s[9][0] = -1e30f; s[9][2] = -1e30f; }
    if (t4 >= 2) { s[9][1] = -1e30f; s[9][3] = -1e30f; }

    float m0 = -1e30f, m1 = -1e30f;
    #pragma unroll
    for (int ni = 0; ni < 10; ni++) {
        m0 = fmaxf(m0, fmaxf(s[ni][0], s[ni][1]));
        m1 = fmaxf(m1, fmaxf(s[ni][2], s[ni][3]));
    }
    m0 = fmaxf(m0, __shfl_xor_sync(~0u, m0, 1));
    m0 = fmaxf(m0, __shfl_xor_sync(~0u, m0, 2));
    m1 = fmaxf(m1, __shfl_xor_sync(~0u, m1, 1));
    m1 = fmaxf(m1, __shfl_xor_sync(~0u, m1, 2));
    float l0 = 0.f, l1 = 0.f;
    #pragma unroll
    for (int ni = 0; ni < 10; ni++) {
        s[ni][0] = __expf(s[ni][0] - m0);
        s[ni][1] = __expf(s[ni][1] - m0);
        s[ni][2] = __expf(s[ni][2] - m1);
        s[ni][3] = __expf(s[ni][3] - m1);
        l0 += s[ni][0] + s[ni][1];
        l1 += s[ni][2] + s[ni][3];
    }
    l0 += __shfl_xor_sync(~0u, l0, 1); l0 += __shfl_xor_sync(~0u, l0, 2);
    l1 += __shfl_xor_sync(~0u, l1, 1); l1 += __shfl_xor_sync(~0u, l1, 2);

    float oa[10][4];
    #pragma unroll
    for (int ni = 0; ni < 10; ni++) { oa[ni][0]=oa[ni][1]=oa[ni][2]=oa[ni][3]=0.f; }
    #pragma unroll
    for (int ks = 0; ks < 5; ks++) {
        uint32_t a0 = hpack(s[2*ks][0],   s[2*ks][1]);
        uint32_t a1 = hpack(s[2*ks][2],   s[2*ks][3]);
        uint32_t a2 = hpack(s[2*ks+1][0], s[2*ks+1][1]);
        uint32_t a3 = hpack(s[2*ks+1][2], s[2*ks+1][3]);
        #pragma unroll
        for (int ni = 0; ni < 10; ni++) {
            uint32_t b0 = *(const uint32_t*)&Vt[(8*ni + gr)*KSR + ks*16 + 2*t4];
            uint32_t b1 = *(const uint32_t*)&Vt[(8*ni + gr)*KSR + ks*16 + 8 + 2*t4];
            mma16h(oa[ni], a0, a1, a2, a3, b0, b1);
        }
    }

    float inv0 = 1.f / l0, inv1 = 1.f / l1;
    __half* Ob = O + ((size_t)(b*HW + q0 + w*16))*CCH + h*DH;
    #pragma unroll
    for (int ni = 0; ni < 10; ni++) {
        *(__half2*)(Ob + (size_t)gr*CCH + 8*ni + 2*t4) =
            __floats2half2_rn(oa[ni][0]*inv0, oa[ni][1]*inv0);
        *(__half2*)(Ob + (size_t)(gr+8)*CCH + 8*ni + 2*t4) =
            __floats2half2_rn(oa[ni][2]*inv1, oa[ni][3]*inv1);
    }
}

// ---------------- host launch ----------------
extern "C" void kernel_launch(void* const* d_in, const int* in_sizes, int n_in,
                              void* d_out, int out_size) {
    const float* x        = (const float*)d_in[0];
    const float* context  = (const float*)d_in[1];
    const float* gn_s     = (const float*)d_in[2];
    const float* gn_b     = (const float*)d_in[3];
    const float* conv1_w  = (const float*)d_in[4];
    const float* conv1_b  = (const float*)d_in[5];
    const float* ln1_s    = (const float*)d_in[6];
    const float* ln1_b    = (const float*)d_in[7];
    const float* sa_in_w  = (const float*)d_in[8];
    const float* sa_out_w = (const float*)d_in[9];
    const float* sa_out_b = (const float*)d_in[10];
    const float* ln2_s    = (const float*)d_in[11];
    const float* ln2_b    = (const float*)d_in[12];
    const float* ca_q_w   = (const float*)d_in[13];
    const float* ca_k_w   = (const float*)d_in[14];
    const float* ca_v_w   = (const float*)d_in[15];
    const float* ca_out_w = (const float*)d_in[16];
    const float* ca_out_b = (const float*)d_in[17];
    const float* ln3_s    = (const float*)d_in[18];
    const float* ln3_b    = (const float*)d_in[19];
    const float* lin1_w   = (const float*)d_in[20];
    const float* lin1_b   = (const float*)d_in[21];
    const float* lin2_w   = (const float*)d_in[22];
    const float* lin2_b   = (const float*)d_in[23];
    const float* co_w     = (const float*)d_in[24];
    const float* co_b     = (const float*)d_in[25];
    float* out = (float*)d_out;

    float *xseq, *lin1bi;
    __half *hgn, *ht, *hattn, *hctx, *hkc, *hvc, *hffg, *hx, *hqkv, *hvt, *hw;
    cudaGetSymbolAddress((void**)&xseq, g_xseq);
    cudaGetSymbolAddress((void**)&lin1bi, g_lin1bi);
    cudaGetSymbolAddress((void**)&hgn,  h_gn);
    cudaGetSymbolAddress((void**)&ht,   h_t);
    cudaGetSymbolAddress((void**)&hattn,h_attn);
    cudaGetSymbolAddress((void**)&hctx, h_ctx);
    cudaGetSymbolAddress((void**)&hkc,  h_kctx);
    cudaGetSymbolAddress((void**)&hvc,  h_vctx);
    cudaGetSymbolAddress((void**)&hffg, h_ffg);
    cudaGetSymbolAddress((void**)&hx,   h_x);
    cudaGetSymbolAddress((void**)&hqkv, h_qkv);
    cudaGetSymbolAddress((void**)&hvt,  h_vt);
    cudaGetSymbolAddress((void**)&hw,   h_w);

    __half* sa_in_wT  = hw;
    __half* sa_out_wT = sa_in_wT  + 1920*640;
    __half* ca_q_wT   = sa_out_wT + 640*640;
    __half* ca_k_wT   = ca_q_wT   + 640*640;
    __half* ca_v_wT   = ca_k_wT   + 640*512;
    __half* ca_out_wT = ca_v_wT   + 640*512;
    __half* lin1_wT   = ca_out_wT + 640*640;      // interleaved [a0,g0,a1,g1,...]
    __half* lin2_wT   = lin1_wT   + 5120*640;
    __half* conv1_wh  = lin2_wT   + 640*2560;
    __half* co_wh     = conv1_wh  + 640*640;

    cudaFuncSetAttribute(gemm_h<0>, cudaFuncAttributeMaxDynamicSharedMemorySize, GEMM_SMEM);
    cudaFuncSetAttribute(gemm_h<1>, cudaFuncAttributeMaxDynamicSharedMemorySize, GEMM_SMEM);
    cudaFuncSetAttribute(gemm_h<2>, cudaFuncAttributeMaxDynamicSharedMemorySize, GEMM_SMEM);

    const int M = NB * HW;      // 8192
    const int MC = NB * SKCTX;  // 616
    dim3 tblk(32, 8);
    dim3 tgrid(HW/32, CCH/32, NB);
    auto ggrid = [](int N_, int M_) { return dim3(N_/128, (M_+127)/128); };

    // 0. merged weight prep (one transpose kernel + one convert kernel + bias interleave)
    {
        W8 ws;
        auto mk = [](const float* s, __half* d, int K, int N, int off, int il) {
            WSeg w; w.src = s; w.dst = d; w.K = K; w.N = N;
            w.tilesX = N/32; w.tileOff = off; w.ileave = il; return w;
        };
        int off = 0;
        ws.w[0] = mk(sa_in_w,  sa_in_wT,  CCH, 3*CCH, off, 0); off += (3*CCH/32)*(CCH/32);
        ws.w[1] = mk(sa_out_w, sa_out_wT, CCH, CCH,   off, 0); off += (CCH/32)*(CCH/32);
        ws.w[2] = mk(ca_q_w,   ca_q_wT,   CCH, CCH,   off, 0); off += (CCH/32)*(CCH/32);
        ws.w[3] = mk(ca_k_w,   ca_k_wT,   DCTX, CCH,  off, 0); off += (CCH/32)*(DCTX/32);
        ws.w[4] = mk(ca_v_w,   ca_v_wT,   DCTX, CCH,  off, 0); off += (CCH/32)*(DCTX/32);
        ws.w[5] = mk(ca_out_w, ca_out_wT, CCH, CCH,   off, 0); off += (CCH/32)*(CCH/32);
        ws.w[6] = mk(lin1_w,   lin1_wT,   CCH, 8*CCH, off, 1); off += (8*CCH/32)*(CCH/32);
        ws.w[7] = mk(lin2_w,   lin2_wT,   4*CCH, CCH, off, 0); off += (CCH/32)*(4*CCH/32);
        wtrans_all<<<off, tblk>>>(ws);
    }
    {
        int e0 = CCH*CCH/4, e1 = CCH*CCH/4, e2 = MC*DCTX/4;
        cvt_all<<<(e0+e1+e2 + 255)/256, 256>>>(conv1_w, conv1_wh, e0,
                                               co_w, co_wh, e1,
                                               context, hctx, e2);
    }
    bias_il<<<(4*CCH + 255)/256, 256>>>(lin1_b, lin1bi);

    // 1. GroupNorm + transpose (-> fp16)
    gn_stats<<<NB*GRP, 256>>>(x);
    gn_apply<<<tgrid, tblk>>>(x, gn_s, gn_b);

    // 2. conv1
    gemm_h<0><<<ggrid(CCH, M), 256, GEMM_SMEM>>>(hgn, CCH, conv1_wh, conv1_b, nullptr,
                                                 xseq, nullptr, CCH, M, CCH, CCH);

    // 3. self-attention
    layernorm<<<M, 160>>>(xseq, ln1_s, ln1_b, ht);
    gemm_h<0><<<ggrid(3*CCH, M), 256, GEMM_SMEM>>>(ht, CCH, sa_in_wT, nullptr, nullptr,
                                                   nullptr, hqkv, 3*CCH, M, 3*CCH, CCH);
    vtrans<<<dim3(HW/32, CCH/32, NB), tblk>>>(hqkv, hvt);
    flash_h<<<dim3(HW/128, NB*NH), 256>>>(hqkv, hvt, hattn);
    gemm_h<0><<<ggrid(CCH, M), 256, GEMM_SMEM>>>(hattn, CCH, sa_out_wT, sa_out_b, xseq,
                                                 xseq, nullptr, CCH, M, CCH, CCH);

    // 4. cross-attention
    layernorm<<<M, 160>>>(xseq, ln2_s, ln2_b, ht);
    gemm_h<0><<<ggrid(CCH, M), 256, GEMM_SMEM>>>(ht, CCH, ca_q_wT, nullptr, nullptr,
                                                 nullptr, hqkv, CCH, M, CCH, CCH);
    gemm_h<0><<<ggrid(CCH, MC), 256, GEMM_SMEM>>>(hctx, DCTX, ca_k_wT, nullptr, nullptr,
                                                  nullptr, hkc, CCH, MC, CCH, DCTX);
    gemm_h<0><<<ggrid(CCH, MC), 256, GEMM_SMEM>>>(hctx, DCTX, ca_v_wT, nullptr, nullptr,
                                                  nullptr, hvc, CCH, MC, CCH, DCTX);
    xattn_h<<<dim3(HW/128, NB*NH), 256>>>(hqkv, hkc, hvc, hattn);
    gemm_h<0><<<ggrid(CCH, M), 256, GEMM_SMEM>>>(hattn, CCH, ca_out_wT, ca_out_b, xseq,
                                                 xseq, nullptr, CCH, M, CCH, CCH);

    // 5. GeGLU FFN (geglu fused into lin1 epilogue via interleaved weights)
    layernorm<<<M, 160>>>(xseq, ln3_s, ln3_b, ht);
    gemm_h<1><<<ggrid(8*CCH, M), 256, GEMM_SMEM>>>(ht, CCH, lin1_wT, lin1bi, nullptr,
                                                   nullptr, hffg, 4*CCH, M, 8*CCH, CCH);
    gemm_h<0><<<ggrid(CCH, M), 256, GEMM_SMEM>>>(hffg, 4*CCH, lin2_wT, lin2_b, xseq,
                                                 xseq, hx, CCH, M, CCH, 4*CCH);

    // 6. final conv + long residual, fused transposed epilogue
    gemm_h<2><<<ggrid(CCH, M), 256, GEMM_SMEM>>>(hx, CCH, co_wh, co_b, x,
                                                 out, nullptr, CCH, M, CCH, CCH);
}

// round 10
// speedup vs baseline: 31.6505x; 1.0753x over previous
#include <cuda_runtime.h>
#include <cuda_fp16.h>
#include <math.h>
#include <stdint.h>

#define NB    8
#define CCH   640
#define HW    1024
#define NH    8
#define DH    80
#define DCTX  512
#define GRP   32
#define CPG   20
#define SKCTX 77

// ---------------- fp32 scratch ----------------
__device__ float  g_xseq [NB*HW*CCH];
__device__ float  g_gnstat[NB*GRP*2];
__device__ float  g_lin1bi[8*CCH];
// ---------------- fp16 scratch ----------------
__device__ __half h_gn  [NB*HW*CCH];
__device__ __half h_t   [NB*HW*CCH];
__device__ __half h_attn[NB*HW*CCH];
__device__ __half h_ctx [NB*SKCTX*DCTX];
__device__ __half h_kv  [NB*SKCTX*2*CCH];
__device__ __half h_ffg [NB*HW*4*CCH];
__device__ __half h_x   [NB*HW*CCH];
__device__ __half h_qkv [NB*HW*3*CCH];
__device__ __half h_vt  [NB*CCH*HW];
__device__ __half h_w   [8847360];       // all weights, fp16, [N,K]

// ---------------- GroupNorm stats (1024 threads) ----------------
__global__ __launch_bounds__(1024)
void gn_stats(const float* __restrict__ x) {
    int ng = blockIdx.x;
    int n = ng / GRP, g = ng % GRP;
    const float4* base = (const float4*)(x + ((size_t)n*CCH + (size_t)g*CPG) * HW);
    float s = 0.f, s2 = 0.f;
    for (int i = threadIdx.x; i < CPG*HW/4; i += 1024) {
        float4 v = base[i];
        s  += v.x + v.y + v.z + v.w;
        s2 += v.x*v.x + v.y*v.y + v.z*v.z + v.w*v.w;
    }
    __shared__ float rs[1024], rq[1024];
    rs[threadIdx.x] = s; rq[threadIdx.x] = s2;
    __syncthreads();
    for (int o = 512; o > 0; o >>= 1) {
        if (threadIdx.x < o) { rs[threadIdx.x] += rs[threadIdx.x+o]; rq[threadIdx.x] += rq[threadIdx.x+o]; }
        __syncthreads();
    }
    if (threadIdx.x == 0) {
        float inv_n = 1.f / (float)(CPG*HW);
        float mu  = rs[0] * inv_n;
        float var = rq[0] * inv_n - mu*mu;
        g_gnstat[ng*2]   = mu;
        g_gnstat[ng*2+1] = rsqrtf(var + 1e-6f);
    }
}

// ---------------- GroupNorm apply + transpose -> fp16 [n,p,c] ----------------
__global__ void gn_apply(const float* __restrict__ x,
                         const float* __restrict__ s, const float* __restrict__ b) {
    __shared__ float tile[32][33];
    int n = blockIdx.z;
    int p0 = blockIdx.x*32, c0 = blockIdx.y*32;
    int tx = threadIdx.x, ty = threadIdx.y;
    #pragma unroll
    for (int i = 0; i < 4; i++) {
        int c = c0 + ty + i*8;
        int ng = n*GRP + c / CPG;
        float mu = g_gnstat[ng*2], is = g_gnstat[ng*2+1];
        float v = x[((size_t)n*CCH + c)*HW + p0 + tx];
        tile[ty + i*8][tx] = (v - mu) * is * s[c] + b[c];
    }
    __syncthreads();
    #pragma unroll
    for (int i = 0; i < 4; i++) {
        int p = p0 + ty + i*8;
        h_gn[((size_t)n*HW + p)*CCH + c0 + tx] = __float2half(tile[tx][ty + i*8]);
    }
}

// ---------------- merged weight transpose+convert ----------------
struct WSeg { const float* src; __half* dst; int K, N, tilesX, tileOff, ileave; };
struct W8 { WSeg w[8]; };
__global__ void wtrans_all(W8 ws) {
    __shared__ float t[32][33];
    int bid = blockIdx.x;
    int si = 0;
    #pragma unroll
    for (int i = 1; i < 8; i++)
        if (bid >= ws.w[i].tileOff) si = i;
    WSeg sg = ws.w[si];
    int local = bid - sg.tileOff;
    int n0 = (local % sg.tilesX) * 32;
    int k0 = (local / sg.tilesX) * 32;
    int tx = threadIdx.x, ty = threadIdx.y;
    #pragma unroll
    for (int i = 0; i < 4; i++)
        t[ty + i*8][tx] = sg.src[(size_t)(k0 + ty + i*8)*sg.N + n0 + tx];
    __syncthreads();
    int half = sg.N >> 1;
    #pragma unroll
    for (int i = 0; i < 4; i++) {
        int r = n0 + ty + i*8;
        int rr = sg.ileave ? ((r < half) ? 2*r : 2*(r - half) + 1) : r;
        sg.dst[(size_t)rr*sg.K + k0 + tx] = __float2half(t[tx][ty + i*8]);
    }
}

// ---------------- merged straight converts ----------------
__global__ void cvt_all(const float* s0, __half* d0, int e0,
                        const float* s1, __half* d1, int e1,
                        const float* s2, __half* d2, int e2) {
    int i = blockIdx.x * 256 + threadIdx.x;
    const float* s; __half* d; int off;
    if (i < e0) { s = s0; d = d0; off = i; }
    else if (i < e0 + e1) { s = s1; d = d1; off = i - e0; }
    else if (i < e0 + e1 + e2) { s = s2; d = d2; off = i - e0 - e1; }
    else return;
    float4 v = ((const float4*)s)[off];
    union { uint2 u; __half2 h[2]; } pk;
    pk.h[0] = __floats2half2_rn(v.x, v.y);
    pk.h[1] = __floats2half2_rn(v.z, v.w);
    ((uint2*)d)[off] = pk.u;
}

// ---------------- lin1 bias interleave ----------------
__global__ void bias_il(const float* __restrict__ b, float* __restrict__ bi) {
    int j = blockIdx.x * 256 + threadIdx.x;
    if (j < 4*CCH) {
        bi[2*j]   = b[j];
        bi[2*j+1] = b[j + 4*CCH];
    }
}

// ---------------- V transpose (fp16) ----------------
__global__ void vtrans(const __half* __restrict__ qkv, __half* __restrict__ vt) {
    __shared__ __half tile[32][33];
    int b = blockIdx.z;
    int p0 = blockIdx.x*32, c0 = blockIdx.y*32;
    int tx = threadIdx.x, ty = threadIdx.y;
    #pragma unroll
    for (int i = 0; i < 4; i++) {
        int p = p0 + ty + i*8;
        tile[ty + i*8][tx] = qkv[((size_t)(b*HW + p))*(3*CCH) + 2*CCH + c0 + tx];
    }
    __syncthreads();
    #pragma unroll
    for (int i = 0; i < 4; i++) {
        int c = c0 + ty + i*8;
        vt[((size_t)b*CCH + c)*HW + p0 + tx] = tile[tx][ty + i*8];
    }
}

// ---------------- LayerNorm fp32 in -> fp16 out ----------------
__global__ __launch_bounds__(160)
void layernorm(const float* __restrict__ in,
               const float* __restrict__ s, const float* __restrict__ b,
               __half* __restrict__ out) {
    int row = blockIdx.x;
    int tid = threadIdx.x;
    const float4* r4 = (const float4*)(in + (size_t)row * CCH);
    float4 v = r4[tid];
    float sum = v.x + v.y + v.z + v.w;
    float sq  = v.x*v.x + v.y*v.y + v.z*v.z + v.w*v.w;
    #pragma unroll
    for (int o = 16; o > 0; o >>= 1) {
        sum += __shfl_xor_sync(~0u, sum, o);
        sq  += __shfl_xor_sync(~0u, sq,  o);
    }
    __shared__ float ws[5], wq[5];
    int w = tid >> 5;
    if ((tid & 31) == 0) { ws[w] = sum; wq[w] = sq; }
    __syncthreads();
    sum = ws[0] + ws[1] + ws[2] + ws[3] + ws[4];
    sq  = wq[0] + wq[1] + wq[2] + wq[3] + wq[4];
    float mu  = sum / (float)CCH;
    float inv = rsqrtf(sq / (float)CCH - mu*mu + 1e-5f);
    float4 sc = ((const float4*)s)[tid];
    float4 bb = ((const float4*)b)[tid];
    union { uint2 u; __half2 h[2]; } pk;
    pk.h[0] = __floats2half2_rn((v.x - mu) * inv * sc.x + bb.x, (v.y - mu) * inv * sc.y + bb.y);
    pk.h[1] = __floats2half2_rn((v.z - mu) * inv * sc.z + bb.z, (v.w - mu) * inv * sc.w + bb.w);
    ((uint2*)(out + (size_t)row * CCH))[tid] = pk.u;
}

// ---------------- mma / cp.async helpers ----------------
__device__ __forceinline__ void mma16h(float c[4], uint32_t a0, uint32_t a1, uint32_t a2, uint32_t a3,
                                       uint32_t b0, uint32_t b1) {
    asm volatile("mma.sync.aligned.m16n8k16.row.col.f32.f16.f16.f32 "
        "{%0,%1,%2,%3}, {%4,%5,%6,%7}, {%8,%9}, {%0,%1,%2,%3};"
        : "+f"(c[0]), "+f"(c[1]), "+f"(c[2]), "+f"(c[3])
        : "r"(a0), "r"(a1), "r"(a2), "r"(a3), "r"(b0), "r"(b1));
}
__device__ __forceinline__ void ldsm4(uint32_t r[4], uint32_t addr) {
    asm volatile("ldmatrix.sync.aligned.m8n8.x4.shared.b16 {%0,%1,%2,%3}, [%4];"
        : "=r"(r[0]), "=r"(r[1]), "=r"(r[2]), "=r"(r[3]) : "r"(addr));
}
__device__ __forceinline__ void cpa16(void* dst, const void* src, bool valid) {
    uint32_t d = (uint32_t)__cvta_generic_to_shared(dst);
    int sz = valid ? 16 : 0;
    asm volatile("cp.async.cg.shared.global [%0], [%1], 16, %2;" :: "r"(d), "l"(src), "r"(sz));
}
#define CP_COMMIT() asm volatile("cp.async.commit_group;")
#define CP_WAIT1()  asm volatile("cp.async.wait_group 1;")
__device__ __forceinline__ uint32_t hpack(float a, float b) {
    __half2 h = __floats2half2_rn(a, b);
    return *(uint32_t*)&h;
}

// ---------------- fp16 GEMM: 128x128x64, 3-stage cp.async, all-ldmatrix ----------------
#define RS36 36
#define BUFU (128*RS36)
#define NST  3
#define GEMM_SMEM (NST*2*BUFU*4)
template<int MODE>
__global__ __launch_bounds__(256)
void gemm_h(const __half* __restrict__ A, int lda,
            const __half* __restrict__ B,
            const float* __restrict__ bias,
            const float* __restrict__ res,
            float* __restrict__ C, __half* __restrict__ Ch, int ldc,
            int M, int N, int K) {
    extern __shared__ uint32_t sm[];
    uint32_t* As = sm;
    uint32_t* Bs = sm + NST*BUFU;
    uint32_t a_u32 = (uint32_t)__cvta_generic_to_shared(As);
    uint32_t b_u32 = (uint32_t)__cvta_generic_to_shared(Bs);

    int tid = threadIdx.x;
    int lane = tid & 31, warp = tid >> 5;
    int gr = lane >> 2, t4 = lane & 3;
    int wm = (warp >> 2) * 64, wn = (warp & 3) * 32;
    int bm = blockIdx.y * 128, bn = blockIdx.x * 128;

    uint32_t lds_off  = (uint32_t)((lane & 15) * (RS36*4) + ((lane >> 4) << 4));
    // B ldmatrix lane offset: rows (lane&7) + ((lane>>4)<<3), k-sub = (lane>>3)&1
    uint32_t ldsb_off = (uint32_t)(((lane & 7) + ((lane >> 4) << 3)) * (RS36*4)
                                   + (((lane >> 3) & 1) << 4));

    auto stage = [&](int kt, int buf) {
        #pragma unroll
        for (int i = 0; i < 4; i++) {
            int c = tid + i*256;
            int row = c >> 3, seg = c & 7;
            int gm = bm + row;
            cpa16(As + buf*BUFU + row*RS36 + seg*4,
                  A + ((size_t)(gm < M ? gm : 0))*lda + kt*64 + seg*8, gm < M);
        }
        #pragma unroll
        for (int i = 0; i < 4; i++) {
            int c = tid + i*256;
            int row = c >> 3, seg = c & 7;
            int gn = bn + row;
            cpa16(Bs + buf*BUFU + row*RS36 + seg*4,
                  B + ((size_t)(gn < N ? gn : 0))*K + kt*64 + seg*8, gn < N);
        }
    };

    float acc[4][4][4];
    #pragma unroll
    for (int i = 0; i < 4; i++)
        #pragma unroll
        for (int j = 0; j < 4; j++)
            #pragma unroll
            for (int r = 0; r < 4; r++) acc[i][j][r] = 0.f;

    int nk = K >> 6;
    stage(0, 0); CP_COMMIT();
    stage(1, 1); CP_COMMIT();

    int buf = 0;
    for (int t = 0; t < nk; t++) {
        CP_WAIT1();
        __syncthreads();
        if (t + 2 < nk) stage(t+2, (t+2) % NST);
        CP_COMMIT();

        uint32_t a_base = a_u32 + buf*(BUFU*4) + lds_off;
        uint32_t b_base = b_u32 + buf*(BUFU*4) + ldsb_off;

        #pragma unroll
        for (int ks = 0; ks < 4; ks++) {
            uint32_t af[4][4], bf[4][2];
            #pragma unroll
            for (int mi = 0; mi < 4; mi++)
                ldsm4(af[mi], a_base + (uint32_t)((wm + mi*16)*(RS36*4) + ks*32));
            #pragma unroll
            for (int p = 0; p < 2; p++) {
                uint32_t r[4];
                ldsm4(r, b_base + (uint32_t)((wn + p*16)*(RS36*4) + ks*32));
                bf[2*p][0]   = r[0]; bf[2*p][1]   = r[1];
                bf[2*p+1][0] = r[2]; bf[2*p+1][1] = r[3];
            }
            #pragma unroll
            for (int mi = 0; mi < 4; mi++)
                #pragma unroll
                for (int ni = 0; ni < 4; ni++)
                    mma16h(acc[mi][ni], af[mi][0], af[mi][1], af[mi][2], af[mi][3],
                           bf[ni][0], bf[ni][1]);
        }
        buf = (buf + 1 == NST) ? 0 : buf + 1;
    }

    if (MODE == 2) {
        __syncthreads();
        float* eb = (float*)sm;          // [128 cols][132]
        #pragma unroll
        for (int mi = 0; mi < 4; mi++) {
            #pragma unroll
            for (int ni = 0; ni < 4; ni++) {
                int col_l = wn + ni*8 + t4*2;
                int col0  = bn + col_l;
                #pragma unroll
                for (int half_r = 0; half_r < 2; half_r++) {
                    int row_l = wm + mi*16 + gr + half_r*8;
                    eb[(col_l)*132 + row_l]   = acc[mi][ni][half_r*2 + 0] + bias[col0];
                    eb[(col_l+1)*132 + row_l] = acc[mi][ni][half_r*2 + 1] + bias[col0+1];
                }
            }
        }
        __syncthreads();
        int n = bm >> 10, p0 = bm & 1023;
        for (int i = tid; i < 128*32; i += 256) {
            int c = i >> 5, seg = i & 31;
            size_t off = ((size_t)(n*CCH + bn + c))*HW + p0 + seg*4;
            const float* e = eb + c*132 + seg*4;
            float4 xr = *(const float4*)(res + off);
            *(float4*)(C + off) = make_float4(e[0]+xr.x, e[1]+xr.y, e[2]+xr.z, e[3]+xr.w);
        }
        return;
    }

    #pragma unroll
    for (int mi = 0; mi < 4; mi++) {
        #pragma unroll
        for (int ni = 0; ni < 4; ni++) {
            int col0 = bn + wn + ni*8 + t4*2;
            #pragma unroll
            for (int half_r = 0; half_r < 2; half_r++) {
                int row = bm + wm + mi*16 + gr + half_r*8;
                if (row >= M) continue;
                float v0 = acc[mi][ni][half_r*2 + 0];
                float v1 = acc[mi][ni][half_r*2 + 1];
                if (MODE == 1) {
                    float a = v0 + bias[col0];
                    float g = v1 + bias[col0+1];
                    float ge = 0.5f * g * (1.f + erff(g * 0.70710678118654752f));
                    Ch[(size_t)row*ldc + (col0 >> 1)] = __float2half(a * ge);
                } else {
                    if (bias) { v0 += bias[col0]; v1 += bias[col0+1]; }
                    if (res) {
                        const float* rp = res + (size_t)row*ldc + col0;
                        v0 += rp[0]; v1 += rp[1];
                    }
                    if (C) *(float2*)(C + (size_t)row*ldc + col0) = make_float2(v0, v1);
                    if (Ch) *(__half2*)(Ch + (size_t)row*ldc + col0) = __floats2half2_rn(v0, v1);
                }
            }
        }
    }
}

// ---------------- fused flash self-attention, full fp16 mma ----------------
#define KSR 88
#define VSR 72
__global__ __launch_bounds__(256)
void flash_h(const __half* __restrict__ QKV, const __half* __restrict__ VT,
             __half* __restrict__ O) {
    constexpr int LD = 3*CCH;
    __shared__ __half Ks[2][64*KSR];
    __shared__ __half Vs[2][80*VSR];

    int tid = threadIdx.x, lane = tid & 31, w = tid >> 5;
    int z = blockIdx.y;
    int b = z >> 3, h = z & 7;
    int q0 = blockIdx.x * 128;
    int gr = lane >> 2, t4 = lane & 3;

    const __half* Kb  = QKV + ((size_t)b*HW)*LD + CCH + h*DH;
    const __half* Vtb = VT + ((size_t)b*CCH + h*DH)*HW;

    auto stage = [&](int kt, int buf) {
        #pragma unroll
        for (int i = 0; i < 3; i++) {
            int s = tid + i*256;
            if (s < 640) {
                int r = s / 10, g = s - r*10;
                cpa16(&Ks[buf][r*KSR + g*8], Kb + (size_t)(kt*64 + r)*LD + g*8, true);
            }
        }
        #pragma unroll
        for (int i = 0; i < 3; i++) {
            int s = tid + i*256;
            if (s < 640) {
                int r = s >> 3, g = s & 7;
                cpa16(&Vs[buf][r*VSR + g*8], Vtb + (size_t)r*HW + kt*64 + g*8, true);
            }
        }
    };

    stage(0, 0);
    CP_COMMIT();

    const __half2 qs2 = __float2half2_rn(0.1118033988749895f);
    uint32_t qf[5][4];
    {
        const __half* qp  = QKV + (size_t)(b*HW + q0 + w*16 + gr)*LD + h*DH;
        const __half* qp8 = qp + 8*LD;
        #pragma unroll
        for (int ks = 0; ks < 5; ks++) {
            __half2 v0 = __hmul2(*(const __half2*)(qp  + ks*16 + 2*t4),     qs2);
            __half2 v1 = __hmul2(*(const __half2*)(qp8 + ks*16 + 2*t4),     qs2);
            __half2 v2 = __hmul2(*(const __half2*)(qp  + ks*16 + 8 + 2*t4), qs2);
            __half2 v3 = __hmul2(*(const __half2*)(qp8 + ks*16 + 8 + 2*t4), qs2);
            qf[ks][0] = *(uint32_t*)&v0; qf[ks][1] = *(uint32_t*)&v1;
            qf[ks][2] = *(uint32_t*)&v2; qf[ks][3] = *(uint32_t*)&v3;
        }
    }

    float m0v = -1e30f, m1v = -1e30f, l0 = 0.f, l1 = 0.f;
    float oa[10][4];
    #pragma unroll
    for (int ni = 0; ni < 10; ni++) { oa[ni][0]=oa[ni][1]=oa[ni][2]=oa[ni][3]=0.f; }

    for (int kt = 0; kt < 16; kt++) {
        if (kt + 1 < 16) stage(kt+1, (kt+1) & 1);
        CP_COMMIT();
        CP_WAIT1();
        __syncthreads();
        const __half* Kc = Ks[kt & 1];
        const __half* Vc = Vs[kt & 1];

        float s[8][4];
        #pragma unroll
        for (int ni = 0; ni < 8; ni++) { s[ni][0]=s[ni][1]=s[ni][2]=s[ni][3]=0.f; }
        #pragma unroll
        for (int ks = 0; ks < 5; ks++) {
            #pragma unroll
            for (int ni = 0; ni < 8; ni++) {
                uint32_t b0 = *(const uint32_t*)&Kc[(8*ni + gr)*KSR + ks*16 + 2*t4];
                uint32_t b1 = *(const uint32_t*)&Kc[(8*ni + gr)*KSR + ks*16 + 8 + 2*t4];
                mma16h(s[ni], qf[ks][0], qf[ks][1], qf[ks][2], qf[ks][3], b0, b1);
            }
        }

        float tm0 = -1e30f, tm1 = -1e30f;
        #pragma unroll
        for (int ni = 0; ni < 8; ni++) {
            tm0 = fmaxf(tm0, fmaxf(s[ni][0], s[ni][1]));
            tm1 = fmaxf(tm1, fmaxf(s[ni][2], s[ni][3]));
        }
        tm0 = fmaxf(tm0, __shfl_xor_sync(~0u, tm0, 1));
        tm0 = fmaxf(tm0, __shfl_xor_sync(~0u, tm0, 2));
        tm1 = fmaxf(tm1, __shfl_xor_sync(~0u, tm1, 1));
        tm1 = fmaxf(tm1, __shfl_xor_sync(~0u, tm1, 2));
        float mn0 = fmaxf(m0v, tm0), mn1 = fmaxf(m1v, tm1);
        float al0 = __expf(m0v - mn0), al1 = __expf(m1v - mn1);
        m0v = mn0; m1v = mn1;
        float ts0 = 0.f, ts1 = 0.f;
        #pragma unroll
        for (int ni = 0; ni < 8; ni++) {
            s[ni][0] = __expf(s[ni][0] - mn0);
            s[ni][1] = __expf(s[ni][1] - mn0);
            s[ni][2] = __expf(s[ni][2] - mn1);
            s[ni][3] = __expf(s[ni][3] - mn1);
            ts0 += s[ni][0] + s[ni][1];
            ts1 += s[ni][2] + s[ni][3];
        }
        ts0 += __shfl_xor_sync(~0u, ts0, 1); ts0 += __shfl_xor_sync(~0u, ts0, 2);
        ts1 += __shfl_xor_sync(~0u, ts1, 1); ts1 += __shfl_xor_sync(~0u, ts1, 2);
        l0 = l0*al0 + ts0;
        l1 = l1*al1 + ts1;
        #pragma unroll
        for (int ni = 0; ni < 10; ni++) {
            oa[ni][0] *= al0; oa[ni][1] *= al0;
            oa[ni][2] *= al1; oa[ni][3] *= al1;
        }

        #pragma unroll
        for (int ks = 0; ks < 4; ks++) {
            uint32_t a0 = hpack(s[2*ks][0],   s[2*ks][1]);
            uint32_t a1 = hpack(s[2*ks][2],   s[2*ks][3]);
            uint32_t a2 = hpack(s[2*ks+1][0], s[2*ks+1][1]);
            uint32_t a3 = hpack(s[2*ks+1][2], s[2*ks+1][3]);
            #pragma unroll
            for (int ni = 0; ni < 10; ni++) {
                uint32_t b0 = *(const uint32_t*)&Vc[(8*ni + gr)*VSR + ks*16 + 2*t4];
                uint32_t b1 = *(const uint32_t*)&Vc[(8*ni + gr)*VSR + ks*16 + 8 + 2*t4];
                mma16h(oa[ni], a0, a1, a2, a3, b0, b1);
            }
        }
        __syncthreads();
    }

    float inv0 = 1.f / l0, inv1 = 1.f / l1;
    __half* Ob = O + ((size_t)(b*HW + q0 + w*16))*CCH + h*DH;
    #pragma unroll
    for (int ni = 0; ni < 10; ni++) {
        *(__half2*)(Ob + (size_t)gr*CCH + 8*ni + 2*t4) =
            __floats2half2_rn(oa[ni][0]*inv0, oa[ni][1]*inv0);
        *(__half2*)(Ob + (size_t)(gr+8)*CCH + 8*ni + 2*t4) =
            __floats2half2_rn(oa[ni][2]*inv1, oa[ni][3]*inv1);
    }
}

// ---------------- tiled fp16 cross-attention (SK=77, padded to 80) ----------------
// KV buffer: [b*SKCTX + key][1280], k at col 0, v at col 640.
__global__ __launch_bounds__(256)
void xattn_h(const __half* __restrict__ Q, const __half* __restrict__ KV,
             __half* __restrict__ O) {
    __shared__ __half Ks[80*KSR];
    __shared__ __half Vt[80*KSR];

    int tid = threadIdx.x, lane = tid & 31, w = tid >> 5;
    int z = blockIdx.y;
    int b = z >> 3, h = z & 7;
    int q0 = blockIdx.x * 128;
    int gr = lane >> 2, t4 = lane & 3;

    for (int i = tid; i < 80*KSR; i += 256) { Ks[i] = __half(0.f); Vt[i] = __half(0.f); }
    __syncthreads();

    const __half* kc = KV + (size_t)(b*SKCTX)*(2*CCH) + h*DH;
    const __half* vc = kc + CCH;
    for (int idx = tid; idx < SKCTX*40; idx += 256) {
        int key = idx / 40, d2 = idx - key*40;
        __half2 kv = *(const __half2*)(kc + (size_t)key*(2*CCH) + 2*d2);
        __half2 vv = *(const __half2*)(vc + (size_t)key*(2*CCH) + 2*d2);
        *(__half2*)&Ks[key*KSR + 2*d2] = kv;
        Vt[(2*d2)*KSR + key]   = vv.x;
        Vt[(2*d2+1)*KSR + key] = vv.y;
    }
    __syncthreads();

    const __half2 qs2 = __float2half2_rn(0.1118033988749895f);
    uint32_t qf[5][4];
    {
        const __half* qp  = Q + (size_t)(b*HW + q0 + w*16 + gr)*CCH + h*DH;
        const __half* qp8 = qp + 8*CCH;
        #pragma unroll
        for (int ks = 0; ks < 5; ks++) {
            __half2 v0 = __hmul2(*(const __half2*)(qp  + ks*16 + 2*t4),     qs2);
            __half2 v1 = __hmul2(*(const __half2*)(qp8 + ks*16 + 2*t4),     qs2);
            __half2 v2 = __hmul2(*(const __half2*)(qp  + ks*16 + 8 + 2*t4), qs2);
            __half2 v3 = __hmul2(*(const __half2*)(qp8 + ks*16 + 8 + 2*t4), qs2);
            qf[ks][0] = *(uint32_t*)&v0; qf[ks][1] = *(uint32_t*)&v1;
            qf[ks][2] = *(uint32_t*)&v2; qf[ks][3] = *(uint32_t*)&v3;
        }
    }

    float s[10][4];
    #pragma unroll
    for (int ni = 0; ni < 10; ni++) { s[ni][0]=s[ni][1]=s[ni][2]=s[ni][3]=0.f; }
    #pragma unroll
    for (int ks = 0; ks < 5; ks++) {
        #pragma unroll
        for (int ni = 0; ni < 10; ni++) {
            uint32_t b0 = *(const uint32_t*)&Ks[(8*ni + gr)*KSR + ks*16 + 2*t4];
            uint32_t b1 = *(const uint32_t*)&Ks[(8*ni + gr)*KSR + ks*16 + 8 + 2*t4];
            mma16h(s[ni], qf[ks][0], qf[ks][1], qf[ks][2], qf[ks][3], b0, b1);
        }
    }
    if (t4 == 3) { s[9][0] = -1e30f; s[9][2] = -1e30f; }
    if (t4 >= 2) { s[9][1] = -1e30f; s[9][3] = -1e30f; }

    float m0 = -1e30f, m1 = -1e30f;
    #pragma unroll
    for (int ni = 0; ni < 10; ni++) {
        m0 = fmaxf(m0, fmaxf(s[ni][0], s[ni][1]));
        m1 = fmaxf(m1, fmaxf(s[ni][2], s[ni][3]));
    }
    m0 = fmaxf(m0, __shfl_xor_sync(~0u, m0, 1));
    m0 = fmaxf(m0, __shfl_xor_sync(~0u, m0, 2));
    m1 = fmaxf(m1, __shfl_xor_sync(~0u, m1, 1));
    m1 = fmaxf(m1, __shfl_xor_sync(~0u, m1, 2));
    float l0 = 0.f, l1 = 0.f;
    #pragma unroll
    for (int ni = 0; ni < 10; ni++) {
        s[ni][0] = __expf(s[ni][0] - m0);
        s[ni][1] = __expf(s[ni][1] - m0);
        s[ni][2] = __expf(s[ni][2] - m1);
        s[ni][3] = __expf(s[ni][3] - m1);
        l0 += s[ni][0] + s[ni][1];
        l1 += s[ni][2] + s[ni][3];
    }
    l0 += __shfl_xor_sync(~0u, l0, 1); l0 += __shfl_xor_sync(~0u, l0, 2);
    l1 += __shfl_xor_sync(~0u, l1, 1); l1 += __shfl_xor_sync(~0u, l1, 2);

    float oa[10][4];
    #pragma unroll
    for (int ni = 0; ni < 10; ni++) { oa[ni][0]=oa[ni][1]=oa[ni][2]=oa[ni][3]=0.f; }
    #pragma unroll
    for (int ks = 0; ks < 5; ks++) {
        uint32_t a0 = hpack(s[2*ks][0],   s[2*ks][1]);
        uint32_t a1 = hpack(s[2*ks][2],   s[2*ks][3]);
        uint32_t a2 = hpack(s[2*ks+1][0], s[2*ks+1][1]);
        uint32_t a3 = hpack(s[2*ks+1][2], s[2*ks+1][3]);
        #pragma unroll
        for (int ni = 0; ni < 10; ni++) {
            uint32_t b0 = *(const uint32_t*)&Vt[(8*ni + gr)*KSR + ks*16 + 2*t4];
            uint32_t b1 = *(const uint32_t*)&Vt[(8*ni + gr)*KSR + ks*16 + 8 + 2*t4];
            mma16h(oa[ni], a0, a1, a2, a3, b0, b1);
        }
    }

    float inv0 = 1.f / l0, inv1 = 1.f / l1;
    __half* Ob = O + ((size_t)(b*HW + q0 + w*16))*CCH + h*DH;
    #pragma unroll
    for (int ni = 0; ni < 10; ni++) {
        *(__half2*)(Ob + (size_t)gr*CCH + 8*ni + 2*t4) =
            __floats2half2_rn(oa[ni][0]*inv0, oa[ni][1]*inv0);
        *(__half2*)(Ob + (size_t)(gr+8)*CCH + 8*ni + 2*t4) =
            __floats2half2_rn(oa[ni][2]*inv1, oa[ni][3]*inv1);
    }
}

// ---------------- host launch ----------------
extern "C" void kernel_launch(void* const* d_in, const int* in_sizes, int n_in,
                              void* d_out, int out_size) {
    const float* x        = (const float*)d_in[0];
    const float* context  = (const float*)d_in[1];
    const float* gn_s     = (const float*)d_in[2];
    const float* gn_b     = (const float*)d_in[3];
    const float* conv1_w  = (const float*)d_in[4];
    const float* conv1_b  = (const float*)d_in[5];
    const float* ln1_s    = (const float*)d_in[6];
    const float* ln1_b    = (const float*)d_in[7];
    const float* sa_in_w  = (const float*)d_in[8];
    const float* sa_out_w = (const float*)d_in[9];
    const float* sa_out_b = (const float*)d_in[10];
    const float* ln2_s    = (const float*)d_in[11];
    const float* ln2_b    = (const float*)d_in[12];
    const float* ca_q_w   = (const float*)d_in[13];
    const float* ca_k_w   = (const float*)d_in[14];
    const float* ca_v_w   = (const float*)d_in[15];
    const float* ca_out_w = (const float*)d_in[16];
    const float* ca_out_b = (const float*)d_in[17];
    const float* ln3_s    = (const float*)d_in[18];
    const float* ln3_b    = (const float*)d_in[19];
    const float* lin1_w   = (const float*)d_in[20];
    const float* lin1_b   = (const float*)d_in[21];
    const float* lin2_w   = (const float*)d_in[22];
    const float* lin2_b   = (const float*)d_in[23];
    const float* co_w     = (const float*)d_in[24];
    const float* co_b     = (const float*)d_in[25];
    float* out = (float*)d_out;

    float *xseq, *lin1bi;
    __half *hgn, *ht, *hattn, *hctx, *hkv, *hffg, *hx, *hqkv, *hvt, *hw;
    cudaGetSymbolAddress((void**)&xseq, g_xseq);
    cudaGetSymbolAddress((void**)&lin1bi, g_lin1bi);
    cudaGetSymbolAddress((void**)&hgn,  h_gn);
    cudaGetSymbolAddress((void**)&ht,   h_t);
    cudaGetSymbolAddress((void**)&hattn,h_attn);
    cudaGetSymbolAddress((void**)&hctx, h_ctx);
    cudaGetSymbolAddress((void**)&hkv,  h_kv);
    cudaGetSymbolAddress((void**)&hffg, h_ffg);
    cudaGetSymbolAddress((void**)&hx,   h_x);
    cudaGetSymbolAddress((void**)&hqkv, h_qkv);
    cudaGetSymbolAddress((void**)&hvt,  h_vt);
    cudaGetSymbolAddress((void**)&hw,   h_w);

    __half* sa_in_wT  = hw;
    __half* sa_out_wT = sa_in_wT  + 1920*640;
    __half* ca_q_wT   = sa_out_wT + 640*640;
    __half* ca_k_wT   = ca_q_wT   + 640*640;      // [640][512]
    __half* ca_v_wT   = ca_k_wT   + 640*512;      // [640][512] (contiguous -> combined N=1280)
    __half* ca_out_wT = ca_v_wT   + 640*512;
    __half* lin1_wT   = ca_out_wT + 640*640;      // interleaved [a0,g0,...]
    __half* lin2_wT   = lin1_wT   + 5120*640;
    __half* conv1_wh  = lin2_wT   + 640*2560;
    __half* co_wh     = conv1_wh  + 640*640;
    (void)ca_v_wT;

    cudaFuncSetAttribute(gemm_h<0>, cudaFuncAttributeMaxDynamicSharedMemorySize, GEMM_SMEM);
    cudaFuncSetAttribute(gemm_h<1>, cudaFuncAttributeMaxDynamicSharedMemorySize, GEMM_SMEM);
    cudaFuncSetAttribute(gemm_h<2>, cudaFuncAttributeMaxDynamicSharedMemorySize, GEMM_SMEM);

    const int M = NB * HW;      // 8192
    const int MC = NB * SKCTX;  // 616
    dim3 tblk(32, 8);
    dim3 tgrid(HW/32, CCH/32, NB);
    auto ggrid = [](int N_, int M_) { return dim3(N_/128, (M_+127)/128); };

    // 0. weight prep
    {
        W8 ws;
        auto mk = [](const float* s, __half* d, int K, int N, int off, int il) {
            WSeg w; w.src = s; w.dst = d; w.K = K; w.N = N;
            w.tilesX = N/32; w.tileOff = off; w.ileave = il; return w;
        };
        int off = 0;
        ws.w[0] = mk(sa_in_w,  sa_in_wT,  CCH, 3*CCH, off, 0); off += (3*CCH/32)*(CCH/32);
        ws.w[1] = mk(sa_out_w, sa_out_wT, CCH, CCH,   off, 0); off += (CCH/32)*(CCH/32);
        ws.w[2] = mk(ca_q_w,   ca_q_wT,   CCH, CCH,   off, 0); off += (CCH/32)*(CCH/32);
        ws.w[3] = mk(ca_k_w,   ca_k_wT,   DCTX, CCH,  off, 0); off += (CCH/32)*(DCTX/32);
        ws.w[4] = mk(ca_v_w,   ca_v_wT,   DCTX, CCH,  off, 0); off += (CCH/32)*(DCTX/32);
        ws.w[5] = mk(ca_out_w, ca_out_wT, CCH, CCH,   off, 0); off += (CCH/32)*(CCH/32);
        ws.w[6] = mk(lin1_w,   lin1_wT,   CCH, 8*CCH, off, 1); off += (8*CCH/32)*(CCH/32);
        ws.w[7] = mk(lin2_w,   lin2_wT,   4*CCH, CCH, off, 0); off += (CCH/32)*(4*CCH/32);
        wtrans_all<<<off, tblk>>>(ws);
    }
    {
        int e0 = CCH*CCH/4, e1 = CCH*CCH/4, e2 = MC*DCTX/4;
        cvt_all<<<(e0+e1+e2 + 255)/256, 256>>>(conv1_w, conv1_wh, e0,
                                               co_w, co_wh, e1,
                                               context, hctx, e2);
    }
    bias_il<<<(4*CCH + 255)/256, 256>>>(lin1_b, lin1bi);

    // 1. GroupNorm + transpose
    gn_stats<<<NB*GRP, 1024>>>(x);
    gn_apply<<<tgrid, tblk>>>(x, gn_s, gn_b);

    // 2. conv1
    gemm_h<0><<<ggrid(CCH, M), 256, GEMM_SMEM>>>(hgn, CCH, conv1_wh, conv1_b, nullptr,
                                                 xseq, nullptr, CCH, M, CCH, CCH);

    // 3. self-attention
    layernorm<<<M, 160>>>(xseq, ln1_s, ln1_b, ht);
    gemm_h<0><<<ggrid(3*CCH, M), 256, GEMM_SMEM>>>(ht, CCH, sa_in_wT, nullptr, nullptr,
                                                   nullptr, hqkv, 3*CCH, M, 3*CCH, CCH);
    vtrans<<<dim3(HW/32, CCH/32, NB), tblk>>>(hqkv, hvt);
    flash_h<<<dim3(HW/128, NB*NH), 256>>>(hqkv, hvt, hattn);
    gemm_h<0><<<ggrid(CCH, M), 256, GEMM_SMEM>>>(hattn, CCH, sa_out_wT, sa_out_b, xseq,
                                                 xseq, nullptr, CCH, M, CCH, CCH);

    // 4. cross-attention (k+v in one GEMM, N=1280)
    layernorm<<<M, 160>>>(xseq, ln2_s, ln2_b, ht);
    gemm_h<0><<<ggrid(CCH, M), 256, GEMM_SMEM>>>(ht, CCH, ca_q_wT, nullptr, nullptr,
                                                 nullptr, hqkv, CCH, M, CCH, CCH);
    gemm_h<0><<<ggrid(2*CCH, MC), 256, GEMM_SMEM>>>(hctx, DCTX, ca_k_wT, nullptr, nullptr,
                                                    nullptr, hkv, 2*CCH, MC, 2*CCH, DCTX);
    xattn_h<<<dim3(HW/128, NB*NH), 256>>>(hqkv, hkv, hattn);
    gemm_h<0><<<ggrid(CCH, M), 256, GEMM_SMEM>>>(hattn, CCH, ca_out_wT, ca_out_b, xseq,
                                                 xseq, nullptr, CCH, M, CCH, CCH);

    // 5. GeGLU FFN (fused geglu)
    layernorm<<<M, 160>>>(xseq, ln3_s, ln3_b, ht);
    gemm_h<1><<<ggrid(8*CCH, M), 256, GEMM_SMEM>>>(ht, CCH, lin1_wT, lin1bi, nullptr,
                                                   nullptr, hffg, 4*CCH, M, 8*CCH, CCH);
    gemm_h<0><<<ggrid(CCH, M), 256, GEMM_SMEM>>>(hffg, 4*CCH, lin2_wT, lin2_b, xseq,
                                                 xseq, hx, CCH, M, CCH, 4*CCH);

    // 6. final conv + long residual, fused transposed epilogue
    gemm_h<2><<<ggrid(CCH, M), 256, GEMM_SMEM>>>(hx, CCH, co_wh, co_b, x,
                                                 out, nullptr, CCH, M, CCH, CCH);
}

// round 11
// speedup vs baseline: 34.3489x; 1.0853x over previous
#include <cuda_runtime.h>
#include <cuda_fp16.h>
#include <math.h>
#include <stdint.h>

#define NB    8
#define CCH   640
#define HW    1024
#define NH    8
#define DH    80
#define DCTX  512
#define GRP   32
#define CPG   20
#define SKCTX 77

// ---------------- fp32 scratch ----------------
__device__ float  g_xseq [NB*HW*CCH];
__device__ float  g_gnstat[NB*GRP*2];
__device__ float  g_lin1bi[8*CCH];
// ---------------- fp16 scratch ----------------
__device__ __half h_gn  [NB*HW*CCH];
__device__ __half h_t   [NB*HW*CCH];
__device__ __half h_attn[NB*HW*CCH];
__device__ __half h_ctx [NB*SKCTX*DCTX];
__device__ __half h_kv  [NB*SKCTX*2*CCH];
__device__ __half h_ffg [NB*HW*4*CCH];
__device__ __half h_x   [NB*HW*CCH];
__device__ __half h_qkv [NB*HW*3*CCH];
__device__ __half h_vt  [NB*CCH*HW];
__device__ __half h_w   [8847360];       // all weights, fp16, [N,K]

// ---------------- GroupNorm stats (1024 threads) ----------------
__global__ __launch_bounds__(1024)
void gn_stats(const float* __restrict__ x) {
    int ng = blockIdx.x;
    int n = ng / GRP, g = ng % GRP;
    const float4* base = (const float4*)(x + ((size_t)n*CCH + (size_t)g*CPG) * HW);
    float s = 0.f, s2 = 0.f;
    for (int i = threadIdx.x; i < CPG*HW/4; i += 1024) {
        float4 v = base[i];
        s  += v.x + v.y + v.z + v.w;
        s2 += v.x*v.x + v.y*v.y + v.z*v.z + v.w*v.w;
    }
    __shared__ float rs[1024], rq[1024];
    rs[threadIdx.x] = s; rq[threadIdx.x] = s2;
    __syncthreads();
    for (int o = 512; o > 0; o >>= 1) {
        if (threadIdx.x < o) { rs[threadIdx.x] += rs[threadIdx.x+o]; rq[threadIdx.x] += rq[threadIdx.x+o]; }
        __syncthreads();
    }
    if (threadIdx.x == 0) {
        float inv_n = 1.f / (float)(CPG*HW);
        float mu  = rs[0] * inv_n;
        float var = rq[0] * inv_n - mu*mu;
        g_gnstat[ng*2]   = mu;
        g_gnstat[ng*2+1] = rsqrtf(var + 1e-6f);
    }
}

// ---------------- GroupNorm apply + transpose -> fp16 [n,p,c] ----------------
__global__ void gn_apply(const float* __restrict__ x,
                         const float* __restrict__ s, const float* __restrict__ b) {
    __shared__ float tile[32][33];
    int n = blockIdx.z;
    int p0 = blockIdx.x*32, c0 = blockIdx.y*32;
    int tx = threadIdx.x, ty = threadIdx.y;
    #pragma unroll
    for (int i = 0; i < 4; i++) {
        int c = c0 + ty + i*8;
        int ng = n*GRP + c / CPG;
        float mu = g_gnstat[ng*2], is = g_gnstat[ng*2+1];
        float v = x[((size_t)n*CCH + c)*HW + p0 + tx];
        tile[ty + i*8][tx] = (v - mu) * is * s[c] + b[c];
    }
    __syncthreads();
    #pragma unroll
    for (int i = 0; i < 4; i++) {
        int p = p0 + ty + i*8;
        h_gn[((size_t)n*HW + p)*CCH + c0 + tx] = __float2half(tile[tx][ty + i*8]);
    }
}

// ---------------- merged weight transpose+convert ----------------
struct WSeg { const float* src; __half* dst; int K, N, tilesX, tileOff, ileave; };
struct W8 { WSeg w[8]; };
__global__ void wtrans_all(W8 ws) {
    __shared__ float t[32][33];
    int bid = blockIdx.x;
    int si = 0;
    #pragma unroll
    for (int i = 1; i < 8; i++)
        if (bid >= ws.w[i].tileOff) si = i;
    WSeg sg = ws.w[si];
    int local = bid - sg.tileOff;
    int n0 = (local % sg.tilesX) * 32;
    int k0 = (local / sg.tilesX) * 32;
    int tx = threadIdx.x, ty = threadIdx.y;
    #pragma unroll
    for (int i = 0; i < 4; i++)
        t[ty + i*8][tx] = sg.src[(size_t)(k0 + ty + i*8)*sg.N + n0 + tx];
    __syncthreads();
    int half = sg.N >> 1;
    #pragma unroll
    for (int i = 0; i < 4; i++) {
        int r = n0 + ty + i*8;
        int rr = sg.ileave ? ((r < half) ? 2*r : 2*(r - half) + 1) : r;
        sg.dst[(size_t)rr*sg.K + k0 + tx] = __float2half(t[tx][ty + i*8]);
    }
}

// ---------------- merged straight converts ----------------
__global__ void cvt_all(const float* s0, __half* d0, int e0,
                        const float* s1, __half* d1, int e1,
                        const float* s2, __half* d2, int e2) {
    int i = blockIdx.x * 256 + threadIdx.x;
    const float* s; __half* d; int off;
    if (i < e0) { s = s0; d = d0; off = i; }
    else if (i < e0 + e1) { s = s1; d = d1; off = i - e0; }
    else if (i < e0 + e1 + e2) { s = s2; d = d2; off = i - e0 - e1; }
    else return;
    float4 v = ((const float4*)s)[off];
    union { uint2 u; __half2 h[2]; } pk;
    pk.h[0] = __floats2half2_rn(v.x, v.y);
    pk.h[1] = __floats2half2_rn(v.z, v.w);
    ((uint2*)d)[off] = pk.u;
}

// ---------------- lin1 bias interleave ----------------
__global__ void bias_il(const float* __restrict__ b, float* __restrict__ bi) {
    int j = blockIdx.x * 256 + threadIdx.x;
    if (j < 4*CCH) {
        bi[2*j]   = b[j];
        bi[2*j+1] = b[j + 4*CCH];
    }
}

// ---------------- V transpose (fp16) ----------------
__global__ void vtrans(const __half* __restrict__ qkv, __half* __restrict__ vt) {
    __shared__ __half tile[32][33];
    int b = blockIdx.z;
    int p0 = blockIdx.x*32, c0 = blockIdx.y*32;
    int tx = threadIdx.x, ty = threadIdx.y;
    #pragma unroll
    for (int i = 0; i < 4; i++) {
        int p = p0 + ty + i*8;
        tile[ty + i*8][tx] = qkv[((size_t)(b*HW + p))*(3*CCH) + 2*CCH + c0 + tx];
    }
    __syncthreads();
    #pragma unroll
    for (int i = 0; i < 4; i++) {
        int c = c0 + ty + i*8;
        vt[((size_t)b*CCH + c)*HW + p0 + tx] = tile[tx][ty + i*8];
    }
}

// ---------------- LayerNorm fp32 in -> fp16 out ----------------
__global__ __launch_bounds__(160)
void layernorm(const float* __restrict__ in,
               const float* __restrict__ s, const float* __restrict__ b,
               __half* __restrict__ out) {
    int row = blockIdx.x;
    int tid = threadIdx.x;
    const float4* r4 = (const float4*)(in + (size_t)row * CCH);
    float4 v = r4[tid];
    float sum = v.x + v.y + v.z + v.w;
    float sq  = v.x*v.x + v.y*v.y + v.z*v.z + v.w*v.w;
    #pragma unroll
    for (int o = 16; o > 0; o >>= 1) {
        sum += __shfl_xor_sync(~0u, sum, o);
        sq  += __shfl_xor_sync(~0u, sq,  o);
    }
    __shared__ float ws[5], wq[5];
    int w = tid >> 5;
    if ((tid & 31) == 0) { ws[w] = sum; wq[w] = sq; }
    __syncthreads();
    sum = ws[0] + ws[1] + ws[2] + ws[3] + ws[4];
    sq  = wq[0] + wq[1] + wq[2] + wq[3] + wq[4];
    float mu  = sum / (float)CCH;
    float inv = rsqrtf(sq / (float)CCH - mu*mu + 1e-5f);
    float4 sc = ((const float4*)s)[tid];
    float4 bb = ((const float4*)b)[tid];
    union { uint2 u; __half2 h[2]; } pk;
    pk.h[0] = __floats2half2_rn((v.x - mu) * inv * sc.x + bb.x, (v.y - mu) * inv * sc.y + bb.y);
    pk.h[1] = __floats2half2_rn((v.z - mu) * inv * sc.z + bb.z, (v.w - mu) * inv * sc.w + bb.w);
    ((uint2*)(out + (size_t)row * CCH))[tid] = pk.u;
}

// ---------------- mma / cp.async helpers ----------------
__device__ __forceinline__ void mma16h(float c[4], uint32_t a0, uint32_t a1, uint32_t a2, uint32_t a3,
                                       uint32_t b0, uint32_t b1) {
    asm volatile("mma.sync.aligned.m16n8k16.row.col.f32.f16.f16.f32 "
        "{%0,%1,%2,%3}, {%4,%5,%6,%7}, {%8,%9}, {%0,%1,%2,%3};"
        : "+f"(c[0]), "+f"(c[1]), "+f"(c[2]), "+f"(c[3])
        : "r"(a0), "r"(a1), "r"(a2), "r"(a3), "r"(b0), "r"(b1));
}
__device__ __forceinline__ void ldsm4(uint32_t r[4], uint32_t addr) {
    asm volatile("ldmatrix.sync.aligned.m8n8.x4.shared.b16 {%0,%1,%2,%3}, [%4];"
        : "=r"(r[0]), "=r"(r[1]), "=r"(r[2]), "=r"(r[3]) : "r"(addr));
}
__device__ __forceinline__ void cpa16(void* dst, const void* src, bool valid) {
    uint32_t d = (uint32_t)__cvta_generic_to_shared(dst);
    int sz = valid ? 16 : 0;
    asm volatile("cp.async.cg.shared.global [%0], [%1], 16, %2;" :: "r"(d), "l"(src), "r"(sz));
}
#define CP_COMMIT() asm volatile("cp.async.commit_group;")
#define CP_WAIT1()  asm volatile("cp.async.wait_group 1;")
__device__ __forceinline__ uint32_t hpack(float a, float b) {
    __half2 h = __floats2half2_rn(a, b);
    return *(uint32_t*)&h;
}

// ---------------- fp16 GEMM: 128x128x64, 3-stage cp.async, all-ldmatrix, 2 CTA/SM ----------------
#define RS36 36
#define BUFU (128*RS36)
#define NST  3
#define GEMM_SMEM (NST*2*BUFU*4)
template<int MODE>
__global__ __launch_bounds__(256, 2)
void gemm_h(const __half* __restrict__ A, int lda,
            const __half* __restrict__ B,
            const float* __restrict__ bias,
            const float* __restrict__ res,
            float* __restrict__ C, __half* __restrict__ Ch, int ldc,
            int M, int N, int K) {
    extern __shared__ uint32_t sm[];
    uint32_t* As = sm;
    uint32_t* Bs = sm + NST*BUFU;
    uint32_t a_u32 = (uint32_t)__cvta_generic_to_shared(As);
    uint32_t b_u32 = (uint32_t)__cvta_generic_to_shared(Bs);

    int tid = threadIdx.x;
    int lane = tid & 31, warp = tid >> 5;
    int gr = lane >> 2, t4 = lane & 3;
    int wm = (warp >> 2) * 64, wn = (warp & 3) * 32;
    int bm = blockIdx.y * 128, bn = blockIdx.x * 128;

    uint32_t lds_off  = (uint32_t)((lane & 15) * (RS36*4) + ((lane >> 4) << 4));
    uint32_t ldsb_off = (uint32_t)(((lane & 7) + ((lane >> 4) << 3)) * (RS36*4)
                                   + (((lane >> 3) & 1) << 4));

    auto stage = [&](int kt, int buf) {
        #pragma unroll
        for (int i = 0; i < 4; i++) {
            int c = tid + i*256;
            int row = c >> 3, seg = c & 7;
            int gm = bm + row;
            cpa16(As + buf*BUFU + row*RS36 + seg*4,
                  A + ((size_t)(gm < M ? gm : 0))*lda + kt*64 + seg*8, gm < M);
        }
        #pragma unroll
        for (int i = 0; i < 4; i++) {
            int c = tid + i*256;
            int row = c >> 3, seg = c & 7;
            int gn = bn + row;
            cpa16(Bs + buf*BUFU + row*RS36 + seg*4,
                  B + ((size_t)(gn < N ? gn : 0))*K + kt*64 + seg*8, gn < N);
        }
    };

    float acc[4][4][4];
    #pragma unroll
    for (int i = 0; i < 4; i++)
        #pragma unroll
        for (int j = 0; j < 4; j++)
            #pragma unroll
            for (int r = 0; r < 4; r++) acc[i][j][r] = 0.f;

    int nk = K >> 6;
    stage(0, 0); CP_COMMIT();
    stage(1, 1); CP_COMMIT();

    int buf = 0;
    for (int t = 0; t < nk; t++) {
        CP_WAIT1();
        __syncthreads();
        if (t + 2 < nk) stage(t+2, (t+2) % NST);
        CP_COMMIT();

        uint32_t a_base = a_u32 + buf*(BUFU*4) + lds_off;
        uint32_t b_base = b_u32 + buf*(BUFU*4) + ldsb_off;

        #pragma unroll
        for (int ks = 0; ks < 4; ks++) {
            uint32_t af[4][4], bf[4][2];
            #pragma unroll
            for (int mi = 0; mi < 4; mi++)
                ldsm4(af[mi], a_base + (uint32_t)((wm + mi*16)*(RS36*4) + ks*32));
            #pragma unroll
            for (int p = 0; p < 2; p++) {
                uint32_t r[4];
                ldsm4(r, b_base + (uint32_t)((wn + p*16)*(RS36*4) + ks*32));
                bf[2*p][0]   = r[0]; bf[2*p][1]   = r[1];
                bf[2*p+1][0] = r[2]; bf[2*p+1][1] = r[3];
            }
            #pragma unroll
            for (int mi = 0; mi < 4; mi++)
                #pragma unroll
                for (int ni = 0; ni < 4; ni++)
                    mma16h(acc[mi][ni], af[mi][0], af[mi][1], af[mi][2], af[mi][3],
                           bf[ni][0], bf[ni][1]);
        }
        buf = (buf + 1 == NST) ? 0 : buf + 1;
    }

    if (MODE == 2) {
        __syncthreads();
        float* eb = (float*)sm;          // [128 cols][132]
        #pragma unroll
        for (int mi = 0; mi < 4; mi++) {
            #pragma unroll
            for (int ni = 0; ni < 4; ni++) {
                int col_l = wn + ni*8 + t4*2;
                int col0  = bn + col_l;
                #pragma unroll
                for (int half_r = 0; half_r < 2; half_r++) {
                    int row_l = wm + mi*16 + gr + half_r*8;
                    eb[(col_l)*132 + row_l]   = acc[mi][ni][half_r*2 + 0] + bias[col0];
                    eb[(col_l+1)*132 + row_l] = acc[mi][ni][half_r*2 + 1] + bias[col0+1];
                }
            }
        }
        __syncthreads();
        int n = bm >> 10, p0 = bm & 1023;
        for (int i = tid; i < 128*32; i += 256) {
            int c = i >> 5, seg = i & 31;
            size_t off = ((size_t)(n*CCH + bn + c))*HW + p0 + seg*4;
            const float* e = eb + c*132 + seg*4;
            float4 xr = *(const float4*)(res + off);
            *(float4*)(C + off) = make_float4(e[0]+xr.x, e[1]+xr.y, e[2]+xr.z, e[3]+xr.w);
        }
        return;
    }

    #pragma unroll
    for (int mi = 0; mi < 4; mi++) {
        #pragma unroll
        for (int ni = 0; ni < 4; ni++) {
            int col0 = bn + wn + ni*8 + t4*2;
            #pragma unroll
            for (int half_r = 0; half_r < 2; half_r++) {
                int row = bm + wm + mi*16 + gr + half_r*8;
                if (row >= M) continue;
                float v0 = acc[mi][ni][half_r*2 + 0];
                float v1 = acc[mi][ni][half_r*2 + 1];
                if (MODE == 1) {
                    float a = v0 + bias[col0];
                    float g = v1 + bias[col0+1];
                    float ge = 0.5f * g * (1.f + erff(g * 0.70710678118654752f));
                    Ch[(size_t)row*ldc + (col0 >> 1)] = __float2half(a * ge);
                } else {
                    if (bias) { v0 += bias[col0]; v1 += bias[col0+1]; }
                    if (res) {
                        const float* rp = res + (size_t)row*ldc + col0;
                        v0 += rp[0]; v1 += rp[1];
                    }
                    if (C) *(float2*)(C + (size_t)row*ldc + col0) = make_float2(v0, v1);
                    if (Ch) *(__half2*)(Ch + (size_t)row*ldc + col0) = __floats2half2_rn(v0, v1);
                }
            }
        }
    }
}

// ---------------- fused flash self-attention, full fp16 mma ----------------
#define KSR 88
#define VSR 72
__global__ __launch_bounds__(256)
void flash_h(const __half* __restrict__ QKV, const __half* __restrict__ VT,
             __half* __restrict__ O) {
    constexpr int LD = 3*CCH;
    __shared__ __half Ks[2][64*KSR];
    __shared__ __half Vs[2][80*VSR];

    int tid = threadIdx.x, lane = tid & 31, w = tid >> 5;
    int z = blockIdx.y;
    int b = z >> 3, h = z & 7;
    int q0 = blockIdx.x * 128;
    int gr = lane >> 2, t4 = lane & 3;

    const __half* Kb  = QKV + ((size_t)b*HW)*LD + CCH + h*DH;
    const __half* Vtb = VT + ((size_t)b*CCH + h*DH)*HW;

    auto stage = [&](int kt, int buf) {
        #pragma unroll
        for (int i = 0; i < 3; i++) {
            int s = tid + i*256;
            if (s < 640) {
                int r = s / 10, g = s - r*10;
                cpa16(&Ks[buf][r*KSR + g*8], Kb + (size_t)(kt*64 + r)*LD + g*8, true);
            }
        }
        #pragma unroll
        for (int i = 0; i < 3; i++) {
            int s = tid + i*256;
            if (s < 640) {
                int r = s >> 3, g = s & 7;
                cpa16(&Vs[buf][r*VSR + g*8], Vtb + (size_t)r*HW + kt*64 + g*8, true);
            }
        }
    };

    stage(0, 0);
    CP_COMMIT();

    const __half2 qs2 = __float2half2_rn(0.1118033988749895f);
    uint32_t qf[5][4];
    {
        const __half* qp  = QKV + (size_t)(b*HW + q0 + w*16 + gr)*LD + h*DH;
        const __half* qp8 = qp + 8*LD;
        #pragma unroll
        for (int ks = 0; ks < 5; ks++) {
            __half2 v0 = __hmul2(*(const __half2*)(qp  + ks*16 + 2*t4),     qs2);
            __half2 v1 = __hmul2(*(const __half2*)(qp8 + ks*16 + 2*t4),     qs2);
            __half2 v2 = __hmul2(*(const __half2*)(qp  + ks*16 + 8 + 2*t4), qs2);
            __half2 v3 = __hmul2(*(const __half2*)(qp8 + ks*16 + 8 + 2*t4), qs2);
            qf[ks][0] = *(uint32_t*)&v0; qf[ks][1] = *(uint32_t*)&v1;
            qf[ks][2] = *(uint32_t*)&v2; qf[ks][3] = *(uint32_t*)&v3;
        }
    }

    float m0v = -1e30f, m1v = -1e30f, l0 = 0.f, l1 = 0.f;
    float oa[10][4];
    #pragma unroll
    for (int ni = 0; ni < 10; ni++) { oa[ni][0]=oa[ni][1]=oa[ni][2]=oa[ni][3]=0.f; }

    for (int kt = 0; kt < 16; kt++) {
        if (kt + 1 < 16) stage(kt+1, (kt+1) & 1);
        CP_COMMIT();
        CP_WAIT1();
        __syncthreads();
        const __half* Kc = Ks[kt & 1];
        const __half* Vc = Vs[kt & 1];

        float s[8][4];
        #pragma unroll
        for (int ni = 0; ni < 8; ni++) { s[ni][0]=s[ni][1]=s[ni][2]=s[ni][3]=0.f; }
        #pragma unroll
        for (int ks = 0; ks < 5; ks++) {
            #pragma unroll
            for (int ni = 0; ni < 8; ni++) {
                uint32_t b0 = *(const uint32_t*)&Kc[(8*ni + gr)*KSR + ks*16 + 2*t4];
                uint32_t b1 = *(const uint32_t*)&Kc[(8*ni + gr)*KSR + ks*16 + 8 + 2*t4];
                mma16h(s[ni], qf[ks][0], qf[ks][1], qf[ks][2], qf[ks][3], b0, b1);
            }
        }

        float tm0 = -1e30f, tm1 = -1e30f;
        #pragma unroll
        for (int ni = 0; ni < 8; ni++) {
            tm0 = fmaxf(tm0, fmaxf(s[ni][0], s[ni][1]));
            tm1 = fmaxf(tm1, fmaxf(s[ni][2], s[ni][3]));
        }
        tm0 = fmaxf(tm0, __shfl_xor_sync(~0u, tm0, 1));
        tm0 = fmaxf(tm0, __shfl_xor_sync(~0u, tm0, 2));
        tm1 = fmaxf(tm1, __shfl_xor_sync(~0u, tm1, 1));
        tm1 = fmaxf(tm1, __shfl_xor_sync(~0u, tm1, 2));
        float mn0 = fmaxf(m0v, tm0), mn1 = fmaxf(m1v, tm1);
        float al0 = __expf(m0v - mn0), al1 = __expf(m1v - mn1);
        m0v = mn0; m1v = mn1;
        float ts0 = 0.f, ts1 = 0.f;
        #pragma unroll
        for (int ni = 0; ni < 8; ni++) {
            s[ni][0] = __expf(s[ni][0] - mn0);
            s[ni][1] = __expf(s[ni][1] - mn0);
            s[ni][2] = __expf(s[ni][2] - mn1);
            s[ni][3] = __expf(s[ni][3] - mn1);
            ts0 += s[ni][0] + s[ni][1];
            ts1 += s[ni][2] + s[ni][3];
        }
        ts0 += __shfl_xor_sync(~0u, ts0, 1); ts0 += __shfl_xor_sync(~0u, ts0, 2);
        ts1 += __shfl_xor_sync(~0u, ts1, 1); ts1 += __shfl_xor_sync(~0u, ts1, 2);
        l0 = l0*al0 + ts0;
        l1 = l1*al1 + ts1;
        #pragma unroll
        for (int ni = 0; ni < 10; ni++) {
            oa[ni][0] *= al0; oa[ni][1] *= al0;
            oa[ni][2] *= al1; oa[ni][3] *= al1;
        }

        #pragma unroll
        for (int ks = 0; ks < 4; ks++) {
            uint32_t a0 = hpack(s[2*ks][0],   s[2*ks][1]);
            uint32_t a1 = hpack(s[2*ks][2],   s[2*ks][3]);
            uint32_t a2 = hpack(s[2*ks+1][0], s[2*ks+1][1]);
            uint32_t a3 = hpack(s[2*ks+1][2], s[2*ks+1][3]);
            #pragma unroll
            for (int ni = 0; ni < 10; ni++) {
                uint32_t b0 = *(const uint32_t*)&Vc[(8*ni + gr)*VSR + ks*16 + 2*t4];
                uint32_t b1 = *(const uint32_t*)&Vc[(8*ni + gr)*VSR + ks*16 + 8 + 2*t4];
                mma16h(oa[ni], a0, a1, a2, a3, b0, b1);
            }
        }
        __syncthreads();
    }

    float inv0 = 1.f / l0, inv1 = 1.f / l1;
    __half* Ob = O + ((size_t)(b*HW + q0 + w*16))*CCH + h*DH;
    #pragma unroll
    for (int ni = 0; ni < 10; ni++) {
        *(__half2*)(Ob + (size_t)gr*CCH + 8*ni + 2*t4) =
            __floats2half2_rn(oa[ni][0]*inv0, oa[ni][1]*inv0);
        *(__half2*)(Ob + (size_t)(gr+8)*CCH + 8*ni + 2*t4) =
            __floats2half2_rn(oa[ni][2]*inv1, oa[ni][3]*inv1);
    }
}

// ---------------- tiled fp16 cross-attention (SK=77, padded to 80) ----------------
__global__ __launch_bounds__(256)
void xattn_h(const __half* __restrict__ Q, const __half* __restrict__ KV,
             __half* __restrict__ O) {
    __shared__ __half Ks[80*KSR];
    __shared__ __half Vt[80*KSR];

    int tid = threadIdx.x, lane = tid & 31, w = tid >> 5;
    int z = blockIdx.y;
    int b = z >> 3, h = z & 7;
    int q0 = blockIdx.x * 128;
    int gr = lane >> 2, t4 = lane & 3;

    for (int i = tid; i < 80*KSR; i += 256) { Ks[i] = __half(0.f); Vt[i] = __half(0.f); }
    __syncthreads();

    const __half* kc = KV + (size_t)(b*SKCTX)*(2*CCH) + h*DH;
    const __half* vc = kc + CCH;
    for (int idx = tid; idx < SKCTX*40; idx += 256) {
        int key = idx / 40, d2 = idx - key*40;
        __half2 kv = *(const __half2*)(kc + (size_t)key*(2*CCH) + 2*d2);
        __half2 vv = *(const __half2*)(vc + (size_t)key*(2*CCH) + 2*d2);
        *(__half2*)&Ks[key*KSR + 2*d2] = kv;
        Vt[(2*d2)*KSR + key]   = vv.x;
        Vt[(2*d2+1)*KSR + key] = vv.y;
    }
    __syncthreads();

    const __half2 qs2 = __float2half2_rn(0.1118033988749895f);
    uint32_t qf[5][4];
    {
        const __half* qp  = Q + (size_t)(b*HW + q0 + w*16 + gr)*CCH + h*DH;
        const __half* qp8 = qp + 8*CCH;
        #pragma unroll
        for (int ks = 0; ks < 5; ks++) {
            __half2 v0 = __hmul2(*(const __half2*)(qp  + ks*16 + 2*t4),     qs2);
            __half2 v1 = __hmul2(*(const __half2*)(qp8 + ks*16 + 2*t4),     qs2);
            __half2 v2 = __hmul2(*(const __half2*)(qp  + ks*16 + 8 + 2*t4), qs2);
            __half2 v3 = __hmul2(*(const __half2*)(qp8 + ks*16 + 8 + 2*t4), qs2);
            qf[ks][0] = *(uint32_t*)&v0; qf[ks][1] = *(uint32_t*)&v1;
            qf[ks][2] = *(uint32_t*)&v2; qf[ks][3] = *(uint32_t*)&v3;
        }
    }

    float s[10][4];
    #pragma unroll
    for (int ni = 0; ni < 10; ni++) { s[ni][0]=s[ni][1]=s[ni][2]=s[ni][3]=0.f; }
    #pragma unroll
    for (int ks = 0; ks < 5; ks++) {
        #pragma unroll
        for (int ni = 0; ni < 10; ni++) {
            uint32_t b0 = *(const uint32_t*)&Ks[(8*ni + gr)*KSR + ks*16 + 2*t4];
            uint32_t b1 = *(const uint32_t*)&Ks[(8*ni + gr)*KSR + ks*16 + 8 + 2*t4];
            mma16h(s[ni], qf[ks][0], qf[ks][1], qf[ks][2], qf[ks][3], b0, b1);
        }
    }
    if (t4 == 3) { s[9][0] = -1e30f; s[9][2] = -1e30f; }
    if (t4 >= 2) { s[9][1] = -1e30f; s[9][3] = -1e30f; }

    float m0 = -1e30f, m1 = -1e30f;
    #pragma unroll
    for (int ni = 0; ni < 10; ni++) {
        m0 = fmaxf(m0, fmaxf(s[ni][0], s[ni][1]));
        m1 = fmaxf(m1, fmaxf(s[ni][2], s[ni][3]));
    }
    m0 = fmaxf(m0, __shfl_xor_sync(~0u, m0, 1));
    m0 = fmaxf(m0, __shfl_xor_sync(~0u, m0, 2));
    m1 = fmaxf(m1, __shfl_xor_sync(~0u, m1, 1));
    m1 = fmaxf(m1, __shfl_xor_sync(~0u, m1, 2));
    float l0 = 0.f, l1 = 0.f;
    #pragma unroll
    for (int ni = 0; ni < 10; ni++) {
        s[ni][0] = __expf(s[ni][0] - m0);
        s[ni][1] = __expf(s[ni][1] - m0);
        s[ni][2] = __expf(s[ni][2] - m1);
        s[ni][3] = __expf(s[ni][3] - m1);
        l0 += s[ni][0] + s[ni][1];
        l1 += s[ni][2] + s[ni][3];
    }
    l0 += __shfl_xor_sync(~0u, l0, 1); l0 += __shfl_xor_sync(~0u, l0, 2);
    l1 += __shfl_xor_sync(~0u, l1, 1); l1 += __shfl_xor_sync(~0u, l1, 2);

    float oa[10][4];
    #pragma unroll
    for (int ni = 0; ni < 10; ni++) { oa[ni][0]=oa[ni][1]=oa[ni][2]=oa[ni][3]=0.f; }
    #pragma unroll
    for (int ks = 0; ks < 5; ks++) {
        uint32_t a0 = hpack(s[2*ks][0],   s[2*ks][1]);
        uint32_t a1 = hpack(s[2*ks][2],   s[2*ks][3]);
        uint32_t a2 = hpack(s[2*ks+1][0], s[2*ks+1][1]);
        uint32_t a3 = hpack(s[2*ks+1][2], s[2*ks+1][3]);
        #pragma unroll
        for (int ni = 0; ni < 10; ni++) {
            uint32_t b0 = *(const uint32_t*)&Vt[(8*ni + gr)*KSR + ks*16 + 2*t4];
            uint32_t b1 = *(const uint32_t*)&Vt[(8*ni + gr)*KSR + ks*16 + 8 + 2*t4];
            mma16h(oa[ni], a0, a1, a2, a3, b0, b1);
        }
    }

    float inv0 = 1.f / l0, inv1 = 1.f / l1;
    __half* Ob = O + ((size_t)(b*HW + q0 + w*16))*CCH + h*DH;
    #pragma unroll
    for (int ni = 0; ni < 10; ni++) {
        *(__half2*)(Ob + (size_t)gr*CCH + 8*ni + 2*t4) =
            __floats2half2_rn(oa[ni][0]*inv0, oa[ni][1]*inv0);
        *(__half2*)(Ob + (size_t)(gr+8)*CCH + 8*ni + 2*t4) =
            __floats2half2_rn(oa[ni][2]*inv1, oa[ni][3]*inv1);
    }
}

// ---------------- host launch ----------------
extern "C" void kernel_launch(void* const* d_in, const int* in_sizes, int n_in,
                              void* d_out, int out_size) {
    const float* x        = (const float*)d_in[0];
    const float* context  = (const float*)d_in[1];
    const float* gn_s     = (const float*)d_in[2];
    const float* gn_b     = (const float*)d_in[3];
    const float* conv1_w  = (const float*)d_in[4];
    const float* conv1_b  = (const float*)d_in[5];
    const float* ln1_s    = (const float*)d_in[6];
    const float* ln1_b    = (const float*)d_in[7];
    const float* sa_in_w  = (const float*)d_in[8];
    const float* sa_out_w = (const float*)d_in[9];
    const float* sa_out_b = (const float*)d_in[10];
    const float* ln2_s    = (const float*)d_in[11];
    const float* ln2_b    = (const float*)d_in[12];
    const float* ca_q_w   = (const float*)d_in[13];
    const float* ca_k_w   = (const float*)d_in[14];
    const float* ca_v_w   = (const float*)d_in[15];
    const float* ca_out_w = (const float*)d_in[16];
    const float* ca_out_b = (const float*)d_in[17];
    const float* ln3_s    = (const float*)d_in[18];
    const float* ln3_b    = (const float*)d_in[19];
    const float* lin1_w   = (const float*)d_in[20];
    const float* lin1_b   = (const float*)d_in[21];
    const float* lin2_w   = (const float*)d_in[22];
    const float* lin2_b   = (const float*)d_in[23];
    const float* co_w     = (const float*)d_in[24];
    const float* co_b     = (const float*)d_in[25];
    float* out = (float*)d_out;

    float *xseq, *lin1bi;
    __half *hgn, *ht, *hattn, *hctx, *hkv, *hffg, *hx, *hqkv, *hvt, *hw;
    cudaGetSymbolAddress((void**)&xseq, g_xseq);
    cudaGetSymbolAddress((void**)&lin1bi, g_lin1bi);
    cudaGetSymbolAddress((void**)&hgn,  h_gn);
    cudaGetSymbolAddress((void**)&ht,   h_t);
    cudaGetSymbolAddress((void**)&hattn,h_attn);
    cudaGetSymbolAddress((void**)&hctx, h_ctx);
    cudaGetSymbolAddress((void**)&hkv,  h_kv);
    cudaGetSymbolAddress((void**)&hffg, h_ffg);
    cudaGetSymbolAddress((void**)&hx,   h_x);
    cudaGetSymbolAddress((void**)&hqkv, h_qkv);
    cudaGetSymbolAddress((void**)&hvt,  h_vt);
    cudaGetSymbolAddress((void**)&hw,   h_w);

    __half* sa_in_wT  = hw;
    __half* sa_out_wT = sa_in_wT  + 1920*640;
    __half* ca_q_wT   = sa_out_wT + 640*640;
    __half* ca_k_wT   = ca_q_wT   + 640*640;
    __half* ca_v_wT   = ca_k_wT   + 640*512;
    __half* ca_out_wT = ca_v_wT   + 640*512;
    __half* lin1_wT   = ca_out_wT + 640*640;
    __half* lin2_wT   = lin1_wT   + 5120*640;
    __half* conv1_wh  = lin2_wT   + 640*2560;
    __half* co_wh     = conv1_wh  + 640*640;
    (void)ca_v_wT;

    cudaFuncSetAttribute(gemm_h<0>, cudaFuncAttributeMaxDynamicSharedMemorySize, GEMM_SMEM);
    cudaFuncSetAttribute(gemm_h<1>, cudaFuncAttributeMaxDynamicSharedMemorySize, GEMM_SMEM);
    cudaFuncSetAttribute(gemm_h<2>, cudaFuncAttributeMaxDynamicSharedMemorySize, GEMM_SMEM);

    const int M = NB * HW;      // 8192
    const int MC = NB * SKCTX;  // 616
    dim3 tblk(32, 8);
    dim3 tgrid(HW/32, CCH/32, NB);
    auto ggrid = [](int N_, int M_) { return dim3(N_/128, (M_+127)/128); };

    // 0. weight prep
    {
        W8 ws;
        auto mk = [](const float* s, __half* d, int K, int N, int off, int il) {
            WSeg w; w.src = s; w.dst = d; w.K = K; w.N = N;
            w.tilesX = N/32; w.tileOff = off; w.ileave = il; return w;
        };
        int off = 0;
        ws.w[0] = mk(sa_in_w,  sa_in_wT,  CCH, 3*CCH, off, 0); off += (3*CCH/32)*(CCH/32);
        ws.w[1] = mk(sa_out_w, sa_out_wT, CCH, CCH,   off, 0); off += (CCH/32)*(CCH/32);
        ws.w[2] = mk(ca_q_w,   ca_q_wT,   CCH, CCH,   off, 0); off += (CCH/32)*(CCH/32);
        ws.w[3] = mk(ca_k_w,   ca_k_wT,   DCTX, CCH,  off, 0); off += (CCH/32)*(DCTX/32);
        ws.w[4] = mk(ca_v_w,   ca_v_wT,   DCTX, CCH,  off, 0); off += (CCH/32)*(DCTX/32);
        ws.w[5] = mk(ca_out_w, ca_out_wT, CCH, CCH,   off, 0); off += (CCH/32)*(CCH/32);
        ws.w[6] = mk(lin1_w,   lin1_wT,   CCH, 8*CCH, off, 1); off += (8*CCH/32)*(CCH/32);
        ws.w[7] = mk(lin2_w,   lin2_wT,   4*CCH, CCH, off, 0); off += (CCH/32)*(4*CCH/32);
        wtrans_all<<<off, tblk>>>(ws);
    }
    {
        int e0 = CCH*CCH/4, e1 = CCH*CCH/4, e2 = MC*DCTX/4;
        cvt_all<<<(e0+e1+e2 + 255)/256, 256>>>(conv1_w, conv1_wh, e0,
                                               co_w, co_wh, e1,
                                               context, hctx, e2);
    }
    bias_il<<<(4*CCH + 255)/256, 256>>>(lin1_b, lin1bi);

    // 1. GroupNorm + transpose
    gn_stats<<<NB*GRP, 1024>>>(x);
    gn_apply<<<tgrid, tblk>>>(x, gn_s, gn_b);

    // 2. conv1
    gemm_h<0><<<ggrid(CCH, M), 256, GEMM_SMEM>>>(hgn, CCH, conv1_wh, conv1_b, nullptr,
                                                 xseq, nullptr, CCH, M, CCH, CCH);

    // 3. self-attention
    layernorm<<<M, 160>>>(xseq, ln1_s, ln1_b, ht);
    gemm_h<0><<<ggrid(3*CCH, M), 256, GEMM_SMEM>>>(ht, CCH, sa_in_wT, nullptr, nullptr,
                                                   nullptr, hqkv, 3*CCH, M, 3*CCH, CCH);
    vtrans<<<dim3(HW/32, CCH/32, NB), tblk>>>(hqkv, hvt);
    flash_h<<<dim3(HW/128, NB*NH), 256>>>(hqkv, hvt, hattn);
    gemm_h<0><<<ggrid(CCH, M), 256, GEMM_SMEM>>>(hattn, CCH, sa_out_wT, sa_out_b, xseq,
                                                 xseq, nullptr, CCH, M, CCH, CCH);

    // 4. cross-attention (k+v in one GEMM, N=1280)
    layernorm<<<M, 160>>>(xseq, ln2_s, ln2_b, ht);
    gemm_h<0><<<ggrid(CCH, M), 256, GEMM_SMEM>>>(ht, CCH, ca_q_wT, nullptr, nullptr,
                                                 nullptr, hqkv, CCH, M, CCH, CCH);
    gemm_h<0><<<ggrid(2*CCH, MC), 256, GEMM_SMEM>>>(hctx, DCTX, ca_k_wT, nullptr, nullptr,
                                                    nullptr, hkv, 2*CCH, MC, 2*CCH, DCTX);
    xattn_h<<<dim3(HW/128, NB*NH), 256>>>(hqkv, hkv, hattn);
    gemm_h<0><<<ggrid(CCH, M), 256, GEMM_SMEM>>>(hattn, CCH, ca_out_wT, ca_out_b, xseq,
                                                 xseq, nullptr, CCH, M, CCH, CCH);

    // 5. GeGLU FFN (fused geglu)
    layernorm<<<M, 160>>>(xseq, ln3_s, ln3_b, ht);
    gemm_h<1><<<ggrid(8*CCH, M), 256, GEMM_SMEM>>>(ht, CCH, lin1_wT, lin1bi, nullptr,
                                                   nullptr, hffg, 4*CCH, M, 8*CCH, CCH);
    gemm_h<0><<<ggrid(CCH, M), 256, GEMM_SMEM>>>(hffg, 4*CCH, lin2_wT, lin2_b, xseq,
                                                 xseq, hx, CCH, M, CCH, 4*CCH);

    // 6. final conv + long residual, fused transposed epilogue
    gemm_h<2><<<ggrid(CCH, M), 256, GEMM_SMEM>>>(hx, CCH, co_wh, co_b, x,
                                                 out, nullptr, CCH, M, CCH, CCH);
}

// round 12
// speedup vs baseline: 35.0623x; 1.0208x over previous
#include <cuda_runtime.h>
#include <cuda_fp16.h>
#include <math.h>
#include <stdint.h>

#define NB    8
#define CCH   640
#define HW    1024
#define NH    8
#define DH    80
#define DCTX  512
#define GRP   32
#define CPG   20
#define SKCTX 77

// ---------------- fp32 scratch ----------------
__device__ float  g_xseq [NB*HW*CCH];
__device__ float  g_gnstat[NB*GRP*2];
__device__ float  g_lin1bi[8*CCH];
// ---------------- fp16 scratch ----------------
__device__ __half h_gn  [NB*HW*CCH];
__device__ __half h_t   [NB*HW*CCH];
__device__ __half h_attn[NB*HW*CCH];
__device__ __half h_ctx [NB*SKCTX*DCTX];
__device__ __half h_kv  [NB*SKCTX*2*CCH];
__device__ __half h_ffg [NB*HW*4*CCH];
__device__ __half h_x   [NB*HW*CCH];
__device__ __half h_qkv [NB*HW*3*CCH];
__device__ __half h_vt  [NB*CCH*HW];
__device__ __half h_w   [8847360];       // all weights, fp16, [N,K]

// ---------------- GroupNorm stats ----------------
__global__ __launch_bounds__(1024)
void gn_stats(const float* __restrict__ x) {
    int ng = blockIdx.x;
    int n = ng / GRP, g = ng % GRP;
    const float4* base = (const float4*)(x + ((size_t)n*CCH + (size_t)g*CPG) * HW);
    float s = 0.f, s2 = 0.f;
    for (int i = threadIdx.x; i < CPG*HW/4; i += 1024) {
        float4 v = base[i];
        s  += v.x + v.y + v.z + v.w;
        s2 += v.x*v.x + v.y*v.y + v.z*v.z + v.w*v.w;
    }
    __shared__ float rs[1024], rq[1024];
    rs[threadIdx.x] = s; rq[threadIdx.x] = s2;
    __syncthreads();
    for (int o = 512; o > 0; o >>= 1) {
        if (threadIdx.x < o) { rs[threadIdx.x] += rs[threadIdx.x+o]; rq[threadIdx.x] += rq[threadIdx.x+o]; }
        __syncthreads();
    }
    if (threadIdx.x == 0) {
        float inv_n = 1.f / (float)(CPG*HW);
        float mu  = rs[0] * inv_n;
        float var = rq[0] * inv_n - mu*mu;
        g_gnstat[ng*2]   = mu;
        g_gnstat[ng*2+1] = rsqrtf(var + 1e-6f);
    }
}

// ---------------- GroupNorm apply + transpose -> fp16 [n,p,c] ----------------
__global__ void gn_apply(const float* __restrict__ x,
                         const float* __restrict__ s, const float* __restrict__ b) {
    __shared__ float tile[32][33];
    int n = blockIdx.z;
    int p0 = blockIdx.x*32, c0 = blockIdx.y*32;
    int tx = threadIdx.x, ty = threadIdx.y;
    #pragma unroll
    for (int i = 0; i < 4; i++) {
        int c = c0 + ty + i*8;
        int ng = n*GRP + c / CPG;
        float mu = g_gnstat[ng*2], is = g_gnstat[ng*2+1];
        float v = x[((size_t)n*CCH + c)*HW + p0 + tx];
        tile[ty + i*8][tx] = (v - mu) * is * s[c] + b[c];
    }
    __syncthreads();
    #pragma unroll
    for (int i = 0; i < 4; i++) {
        int p = p0 + ty + i*8;
        h_gn[((size_t)n*HW + p)*CCH + c0 + tx] = __float2half(tile[tx][ty + i*8]);
    }
}

// ---------------- merged weight transpose+convert ----------------
struct WSeg { const float* src; __half* dst; int K, N, tilesX, tileOff, ileave; };
struct W8 { WSeg w[8]; };
__global__ void wtrans_all(W8 ws) {
    __shared__ float t[32][33];
    int bid = blockIdx.x;
    int si = 0;
    #pragma unroll
    for (int i = 1; i < 8; i++)
        if (bid >= ws.w[i].tileOff) si = i;
    WSeg sg = ws.w[si];
    int local = bid - sg.tileOff;
    int n0 = (local % sg.tilesX) * 32;
    int k0 = (local / sg.tilesX) * 32;
    int tx = threadIdx.x, ty = threadIdx.y;
    #pragma unroll
    for (int i = 0; i < 4; i++)
        t[ty + i*8][tx] = sg.src[(size_t)(k0 + ty + i*8)*sg.N + n0 + tx];
    __syncthreads();
    int half = sg.N >> 1;
    #pragma unroll
    for (int i = 0; i < 4; i++) {
        int r = n0 + ty + i*8;
        int rr = sg.ileave ? ((r < half) ? 2*r : 2*(r - half) + 1) : r;
        sg.dst[(size_t)rr*sg.K + k0 + tx] = __float2half(t[tx][ty + i*8]);
    }
}

// ---------------- merged converts + lin1 bias interleave ----------------
__global__ void cvt_all(const float* s0, __half* d0, int e0,
                        const float* s1, __half* d1, int e1,
                        const float* s2, __half* d2, int e2,
                        const float* b,  float* bi,  int e3) {
    int i = blockIdx.x * 256 + threadIdx.x;
    if (i >= e0 + e1 + e2) {
        int off = i - e0 - e1 - e2;
        if (off < e3) {           // off indexes groups of 4 bias entries
            int j = off * 4;
            float4 a = *(const float4*)(b + j);
            float4 g = *(const float4*)(b + j + 4*CCH);
            float4 lo = make_float4(a.x, g.x, a.y, g.y);
            float4 hi = make_float4(a.z, g.z, a.w, g.w);
            *(float4*)(bi + 2*j)     = lo;
            *(float4*)(bi + 2*j + 4) = hi;
        }
        return;
    }
    const float* s; __half* d; int off;
    if (i < e0) { s = s0; d = d0; off = i; }
    else if (i < e0 + e1) { s = s1; d = d1; off = i - e0; }
    else { s = s2; d = d2; off = i - e0 - e1; }
    float4 v = ((const float4*)s)[off];
    union { uint2 u; __half2 h[2]; } pk;
    pk.h[0] = __floats2half2_rn(v.x, v.y);
    pk.h[1] = __floats2half2_rn(v.z, v.w);
    ((uint2*)d)[off] = pk.u;
}

// ---------------- LayerNorm fp32 in -> fp16 out ----------------
__global__ __launch_bounds__(160)
void layernorm(const float* __restrict__ in,
               const float* __restrict__ s, const float* __restrict__ b,
               __half* __restrict__ out) {
    int row = blockIdx.x;
    int tid = threadIdx.x;
    const float4* r4 = (const float4*)(in + (size_t)row * CCH);
    float4 v = r4[tid];
    float sum = v.x + v.y + v.z + v.w;
    float sq  = v.x*v.x + v.y*v.y + v.z*v.z + v.w*v.w;
    #pragma unroll
    for (int o = 16; o > 0; o >>= 1) {
        sum += __shfl_xor_sync(~0u, sum, o);
        sq  += __shfl_xor_sync(~0u, sq,  o);
    }
    __shared__ float ws[5], wq[5];
    int w = tid >> 5;
    if ((tid & 31) == 0) { ws[w] = sum; wq[w] = sq; }
    __syncthreads();
    sum = ws[0] + ws[1] + ws[2] + ws[3] + ws[4];
    sq  = wq[0] + wq[1] + wq[2] + wq[3] + wq[4];
    float mu  = sum / (float)CCH;
    float inv = rsqrtf(sq / (float)CCH - mu*mu + 1e-5f);
    float4 sc = ((const float4*)s)[tid];
    float4 bb = ((const float4*)b)[tid];
    union { uint2 u; __half2 h[2]; } pk;
    pk.h[0] = __floats2half2_rn((v.x - mu) * inv * sc.x + bb.x, (v.y - mu) * inv * sc.y + bb.y);
    pk.h[1] = __floats2half2_rn((v.z - mu) * inv * sc.z + bb.z, (v.w - mu) * inv * sc.w + bb.w);
    ((uint2*)(out + (size_t)row * CCH))[tid] = pk.u;
}

// ---------------- mma / cp.async helpers ----------------
__device__ __forceinline__ void mma16h(float c[4], uint32_t a0, uint32_t a1, uint32_t a2, uint32_t a3,
                                       uint32_t b0, uint32_t b1) {
    asm volatile("mma.sync.aligned.m16n8k16.row.col.f32.f16.f16.f32 "
        "{%0,%1,%2,%3}, {%4,%5,%6,%7}, {%8,%9}, {%0,%1,%2,%3};"
        : "+f"(c[0]), "+f"(c[1]), "+f"(c[2]), "+f"(c[3])
        : "r"(a0), "r"(a1), "r"(a2), "r"(a3), "r"(b0), "r"(b1));
}
__device__ __forceinline__ void ldsm4(uint32_t r[4], uint32_t addr) {
    asm volatile("ldmatrix.sync.aligned.m8n8.x4.shared.b16 {%0,%1,%2,%3}, [%4];"
        : "=r"(r[0]), "=r"(r[1]), "=r"(r[2]), "=r"(r[3]) : "r"(addr));
}
__device__ __forceinline__ void cpa16(void* dst, const void* src, bool valid) {
    uint32_t d = (uint32_t)__cvta_generic_to_shared(dst);
    int sz = valid ? 16 : 0;
    asm volatile("cp.async.cg.shared.global [%0], [%1], 16, %2;" :: "r"(d), "l"(src), "r"(sz));
}
#define CP_COMMIT() asm volatile("cp.async.commit_group;")
#define CP_WAIT1()  asm volatile("cp.async.wait_group 1;")
__device__ __forceinline__ uint32_t hpack(float a, float b) {
    __half2 h = __floats2half2_rn(a, b);
    return *(uint32_t*)&h;
}

// ---------------- fp16 GEMM: 128x128x64, 3-stage cp.async, all-ldmatrix, 2 CTA/SM ----------------
// MODE 0: normal  MODE 1: geglu epilogue  MODE 2: NCHW transpose+residual out
// MODE 3: fp16 out + transposed V side-store (C param = __half* vt) for tiles bn >= 2*CCH
#define RS36 36
#define BUFU (128*RS36)
#define NST  3
#define GEMM_SMEM (NST*2*BUFU*4)
template<int MODE>
__global__ __launch_bounds__(256, 2)
void gemm_h(const __half* __restrict__ A, int lda,
            const __half* __restrict__ B,
            const float* __restrict__ bias,
            const float* __restrict__ res,
            float* __restrict__ C, __half* __restrict__ Ch, int ldc,
            int M, int N, int K) {
    extern __shared__ uint32_t sm[];
    uint32_t* As = sm;
    uint32_t* Bs = sm + NST*BUFU;
    uint32_t a_u32 = (uint32_t)__cvta_generic_to_shared(As);
    uint32_t b_u32 = (uint32_t)__cvta_generic_to_shared(Bs);

    int tid = threadIdx.x;
    int lane = tid & 31, warp = tid >> 5;
    int gr = lane >> 2, t4 = lane & 3;
    int wm = (warp >> 2) * 64, wn = (warp & 3) * 32;
    int bm = blockIdx.y * 128, bn = blockIdx.x * 128;

    uint32_t lds_off  = (uint32_t)((lane & 15) * (RS36*4) + ((lane >> 4) << 4));
    uint32_t ldsb_off = (uint32_t)(((lane & 7) + ((lane >> 4) << 3)) * (RS36*4)
                                   + (((lane >> 3) & 1) << 4));

    auto stage = [&](int kt, int buf) {
        #pragma unroll
        for (int i = 0; i < 4; i++) {
            int c = tid + i*256;
            int row = c >> 3, seg = c & 7;
            int gm = bm + row;
            cpa16(As + buf*BUFU + row*RS36 + seg*4,
                  A + ((size_t)(gm < M ? gm : 0))*lda + kt*64 + seg*8, gm < M);
        }
        #pragma unroll
        for (int i = 0; i < 4; i++) {
            int c = tid + i*256;
            int row = c >> 3, seg = c & 7;
            int gn = bn + row;
            cpa16(Bs + buf*BUFU + row*RS36 + seg*4,
                  B + ((size_t)(gn < N ? gn : 0))*K + kt*64 + seg*8, gn < N);
        }
    };

    float acc[4][4][4];
    #pragma unroll
    for (int i = 0; i < 4; i++)
        #pragma unroll
        for (int j = 0; j < 4; j++)
            #pragma unroll
            for (int r = 0; r < 4; r++) acc[i][j][r] = 0.f;

    int nk = K >> 6;
    stage(0, 0); CP_COMMIT();
    stage(1, 1); CP_COMMIT();

    int buf = 0;
    for (int t = 0; t < nk; t++) {
        CP_WAIT1();
        __syncthreads();
        if (t + 2 < nk) stage(t+2, (t+2) % NST);
        CP_COMMIT();

        uint32_t a_base = a_u32 + buf*(BUFU*4) + lds_off;
        uint32_t b_base = b_u32 + buf*(BUFU*4) + ldsb_off;

        #pragma unroll
        for (int ks = 0; ks < 4; ks++) {
            uint32_t af[4][4], bf[4][2];
            #pragma unroll
            for (int mi = 0; mi < 4; mi++)
                ldsm4(af[mi], a_base + (uint32_t)((wm + mi*16)*(RS36*4) + ks*32));
            #pragma unroll
            for (int p = 0; p < 2; p++) {
                uint32_t r[4];
                ldsm4(r, b_base + (uint32_t)((wn + p*16)*(RS36*4) + ks*32));
                bf[2*p][0]   = r[0]; bf[2*p][1]   = r[1];
                bf[2*p+1][0] = r[2]; bf[2*p+1][1] = r[3];
            }
            #pragma unroll
            for (int mi = 0; mi < 4; mi++)
                #pragma unroll
                for (int ni = 0; ni < 4; ni++)
                    mma16h(acc[mi][ni], af[mi][0], af[mi][1], af[mi][2], af[mi][3],
                           bf[ni][0], bf[ni][1]);
        }
        buf = (buf + 1 == NST) ? 0 : buf + 1;
    }

    if (MODE == 2) {
        __syncthreads();
        float* eb = (float*)sm;          // [128 cols][132]
        #pragma unroll
        for (int mi = 0; mi < 4; mi++) {
            #pragma unroll
            for (int ni = 0; ni < 4; ni++) {
                int col_l = wn + ni*8 + t4*2;
                int col0  = bn + col_l;
                #pragma unroll
                for (int half_r = 0; half_r < 2; half_r++) {
                    int row_l = wm + mi*16 + gr + half_r*8;
                    eb[(col_l)*132 + row_l]   = acc[mi][ni][half_r*2 + 0] + bias[col0];
                    eb[(col_l+1)*132 + row_l] = acc[mi][ni][half_r*2 + 1] + bias[col0+1];
                }
            }
        }
        __syncthreads();
        int n = bm >> 10, p0 = bm & 1023;
        for (int i = tid; i < 128*32; i += 256) {
            int c = i >> 5, seg = i & 31;
            size_t off = ((size_t)(n*CCH + bn + c))*HW + p0 + seg*4;
            const float* e = eb + c*132 + seg*4;
            float4 xr = *(const float4*)(res + off);
            *(float4*)(C + off) = make_float4(e[0]+xr.x, e[1]+xr.y, e[2]+xr.z, e[3]+xr.w);
        }
        return;
    }

    #pragma unroll
    for (int mi = 0; mi < 4; mi++) {
        #pragma unroll
        for (int ni = 0; ni < 4; ni++) {
            int col0 = bn + wn + ni*8 + t4*2;
            #pragma unroll
            for (int half_r = 0; half_r < 2; half_r++) {
                int row = bm + wm + mi*16 + gr + half_r*8;
                if (row >= M) continue;
                float v0 = acc[mi][ni][half_r*2 + 0];
                float v1 = acc[mi][ni][half_r*2 + 1];
                if (MODE == 1) {
                    float a = v0 + bias[col0];
                    float g = v1 + bias[col0+1];
                    float ge = 0.5f * g * (1.f + erff(g * 0.70710678118654752f));
                    Ch[(size_t)row*ldc + (col0 >> 1)] = __float2half(a * ge);
                } else {
                    if (bias) { v0 += bias[col0]; v1 += bias[col0+1]; }
                    if (res) {
                        const float* rp = res + (size_t)row*ldc + col0;
                        v0 += rp[0]; v1 += rp[1];
                    }
                    if (MODE == 0 && C) *(float2*)(C + (size_t)row*ldc + col0) = make_float2(v0, v1);
                    if (Ch) *(__half2*)(Ch + (size_t)row*ldc + col0) = __floats2half2_rn(v0, v1);
                }
            }
        }
    }

    if (MODE == 3 && bn >= 2*CCH) {
        // transposed V side-store: eb[col][row] (halves), then coalesced write to vt
        __syncthreads();
        __half* eb = (__half*)sm;        // [128][136]
        #pragma unroll
        for (int mi = 0; mi < 4; mi++) {
            #pragma unroll
            for (int ni = 0; ni < 4; ni++) {
                int col_l = wn + ni*8 + t4*2;
                #pragma unroll
                for (int half_r = 0; half_r < 2; half_r++) {
                    int row_l = wm + mi*16 + gr + half_r*8;
                    eb[(col_l)*136 + row_l]   = __float2half(acc[mi][ni][half_r*2 + 0]);
                    eb[(col_l+1)*136 + row_l] = __float2half(acc[mi][ni][half_r*2 + 1]);
                }
            }
        }
        __syncthreads();
        __half* vt = (__half*)C;
        int b = bm >> 10, p0 = bm & 1023;
        int c0 = bn - 2*CCH;
        for (int i = tid; i < 128*16; i += 256) {
            int c = i >> 4, seg = i & 15;
            *(uint4*)(vt + ((size_t)(b*CCH + c0 + c))*HW + p0 + seg*8) =
                *(const uint4*)(eb + c*136 + seg*8);
        }
    }
}

// ---------------- fused flash self-attention, full fp16 mma, 2 CTA/SM ----------------
#define KSR 88
#define VSR 72
__global__ __launch_bounds__(256, 2)
void flash_h(const __half* __restrict__ QKV, const __half* __restrict__ VT,
             __half* __restrict__ O) {
    constexpr int LD = 3*CCH;
    __shared__ __half Ks[2][64*KSR];
    __shared__ __half Vs[2][80*VSR];

    int tid = threadIdx.x, lane = tid & 31, w = tid >> 5;
    int z = blockIdx.y;
    int b = z >> 3, h = z & 7;
    int q0 = blockIdx.x * 128;
    int gr = lane >> 2, t4 = lane & 3;

    const __half* Kb  = QKV + ((size_t)b*HW)*LD + CCH + h*DH;
    const __half* Vtb = VT + ((size_t)b*CCH + h*DH)*HW;

    auto stage = [&](int kt, int buf) {
        #pragma unroll
        for (int i = 0; i < 3; i++) {
            int s = tid + i*256;
            if (s < 640) {
                int r = s / 10, g = s - r*10;
                cpa16(&Ks[buf][r*KSR + g*8], Kb + (size_t)(kt*64 + r)*LD + g*8, true);
            }
        }
        #pragma unroll
        for (int i = 0; i < 3; i++) {
            int s = tid + i*256;
            if (s < 640) {
                int r = s >> 3, g = s & 7;
                cpa16(&Vs[buf][r*VSR + g*8], Vtb + (size_t)r*HW + kt*64 + g*8, true);
            }
        }
    };

    stage(0, 0);
    CP_COMMIT();

    const __half2 qs2 = __float2half2_rn(0.1118033988749895f);
    uint32_t qf[5][4];
    {
        const __half* qp  = QKV + (size_t)(b*HW + q0 + w*16 + gr)*LD + h*DH;
        const __half* qp8 = qp + 8*LD;
        #pragma unroll
        for (int ks = 0; ks < 5; ks++) {
            __half2 v0 = __hmul2(*(const __half2*)(qp  + ks*16 + 2*t4),     qs2);
            __half2 v1 = __hmul2(*(const __half2*)(qp8 + ks*16 + 2*t4),     qs2);
            __half2 v2 = __hmul2(*(const __half2*)(qp  + ks*16 + 8 + 2*t4), qs2);
            __half2 v3 = __hmul2(*(const __half2*)(qp8 + ks*16 + 8 + 2*t4), qs2);
            qf[ks][0] = *(uint32_t*)&v0; qf[ks][1] = *(uint32_t*)&v1;
            qf[ks][2] = *(uint32_t*)&v2; qf[ks][3] = *(uint32_t*)&v3;
        }
    }

    float m0v = -1e30f, m1v = -1e30f, l0 = 0.f, l1 = 0.f;
    float oa[10][4];
    #pragma unroll
    for (int ni = 0; ni < 10; ni++) { oa[ni][0]=oa[ni][1]=oa[ni][2]=oa[ni][3]=0.f; }

    for (int kt = 0; kt < 16; kt++) {
        if (kt + 1 < 16) stage(kt+1, (kt+1) & 1);
        CP_COMMIT();
        CP_WAIT1();
        __syncthreads();
        const __half* Kc = Ks[kt & 1];
        const __half* Vc = Vs[kt & 1];

        float s[8][4];
        #pragma unroll
        for (int ni = 0; ni < 8; ni++) { s[ni][0]=s[ni][1]=s[ni][2]=s[ni][3]=0.f; }
        #pragma unroll
        for (int ks = 0; ks < 5; ks++) {
            #pragma unroll
            for (int ni = 0; ni < 8; ni++) {
                uint32_t b0 = *(const uint32_t*)&Kc[(8*ni + gr)*KSR + ks*16 + 2*t4];
                uint32_t b1 = *(const uint32_t*)&Kc[(8*ni + gr)*KSR + ks*16 + 8 + 2*t4];
                mma16h(s[ni], qf[ks][0], qf[ks][1], qf[ks][2], qf[ks][3], b0, b1);
            }
        }

        float tm0 = -1e30f, tm1 = -1e30f;
        #pragma unroll
        for (int ni = 0; ni < 8; ni++) {
            tm0 = fmaxf(tm0, fmaxf(s[ni][0], s[ni][1]));
            tm1 = fmaxf(tm1, fmaxf(s[ni][2], s[ni][3]));
        }
        tm0 = fmaxf(tm0, __shfl_xor_sync(~0u, tm0, 1));
        tm0 = fmaxf(tm0, __shfl_xor_sync(~0u, tm0, 2));
        tm1 = fmaxf(tm1, __shfl_xor_sync(~0u, tm1, 1));
        tm1 = fmaxf(tm1, __shfl_xor_sync(~0u, tm1, 2));
        float mn0 = fmaxf(m0v, tm0), mn1 = fmaxf(m1v, tm1);
        float al0 = __expf(m0v - mn0), al1 = __expf(m1v - mn1);
        m0v = mn0; m1v = mn1;
        float ts0 = 0.f, ts1 = 0.f;
        #pragma unroll
        for (int ni = 0; ni < 8; ni++) {
            s[ni][0] = __expf(s[ni][0] - mn0);
            s[ni][1] = __expf(s[ni][1] - mn0);
            s[ni][2] = __expf(s[ni][2] - mn1);
            s[ni][3] = __expf(s[ni][3] - mn1);
            ts0 += s[ni][0] + s[ni][1];
            ts1 += s[ni][2] + s[ni][3];
        }
        ts0 += __shfl_xor_sync(~0u, ts0, 1); ts0 += __shfl_xor_sync(~0u, ts0, 2);
        ts1 += __shfl_xor_sync(~0u, ts1, 1); ts1 += __shfl_xor_sync(~0u, ts1, 2);
        l0 = l0*al0 + ts0;
        l1 = l1*al1 + ts1;
        #pragma unroll
        for (int ni = 0; ni < 10; ni++) {
            oa[ni][0] *= al0; oa[ni][1] *= al0;
            oa[ni][2] *= al1; oa[ni][3] *= al1;
        }

        #pragma unroll
        for (int ks = 0; ks < 4; ks++) {
            uint32_t a0 = hpack(s[2*ks][0],   s[2*ks][1]);
            uint32_t a1 = hpack(s[2*ks][2],   s[2*ks][3]);
            uint32_t a2 = hpack(s[2*ks+1][0], s[2*ks+1][1]);
            uint32_t a3 = hpack(s[2*ks+1][2], s[2*ks+1][3]);
            #pragma unroll
            for (int ni = 0; ni < 10; ni++) {
                uint32_t b0 = *(const uint32_t*)&Vc[(8*ni + gr)*VSR + ks*16 + 2*t4];
                uint32_t b1 = *(const uint32_t*)&Vc[(8*ni + gr)*VSR + ks*16 + 8 + 2*t4];
                mma16h(oa[ni], a0, a1, a2, a3, b0, b1);
            }
        }
        __syncthreads();
    }

    float inv0 = 1.f / l0, inv1 = 1.f / l1;
    __half* Ob = O + ((size_t)(b*HW + q0 + w*16))*CCH + h*DH;
    #pragma unroll
    for (int ni = 0; ni < 10; ni++) {
        *(__half2*)(Ob + (size_t)gr*CCH + 8*ni + 2*t4) =
            __floats2half2_rn(oa[ni][0]*inv0, oa[ni][1]*inv0);
        *(__half2*)(Ob + (size_t)(gr+8)*CCH + 8*ni + 2*t4) =
            __floats2half2_rn(oa[ni][2]*inv1, oa[ni][3]*inv1);
    }
}

// ---------------- tiled fp16 cross-attention (SK=77 padded to 80), 2 CTA/SM ----------------
__global__ __launch_bounds__(256, 2)
void xattn_h(const __half* __restrict__ Q, const __half* __restrict__ KV,
             __half* __restrict__ O) {
    __shared__ __half Ks[80*KSR];
    __shared__ __half Vt[80*KSR];

    int tid = threadIdx.x, lane = tid & 31, w = tid >> 5;
    int z = blockIdx.y;
    int b = z >> 3, h = z & 7;
    int q0 = blockIdx.x * 128;
    int gr = lane >> 2, t4 = lane & 3;

    for (int i = tid; i < 80*KSR; i += 256) { Ks[i] = __half(0.f); Vt[i] = __half(0.f); }
    __syncthreads();

    const __half* kc = KV + (size_t)(b*SKCTX)*(2*CCH) + h*DH;
    const __half* vc = kc + CCH;
    for (int idx = tid; idx < SKCTX*40; idx += 256) {
        int key = idx / 40, d2 = idx - key*40;
        __half2 kv = *(const __half2*)(kc + (size_t)key*(2*CCH) + 2*d2);
        __half2 vv = *(const __half2*)(vc + (size_t)key*(2*CCH) + 2*d2);
        *(__half2*)&Ks[key*KSR + 2*d2] = kv;
        Vt[(2*d2)*KSR + key]   = vv.x;
        Vt[(2*d2+1)*KSR + key] = vv.y;
    }
    __syncthreads();

    const __half2 qs2 = __float2half2_rn(0.1118033988749895f);
    uint32_t qf[5][4];
    {
        const __half* qp  = Q + (size_t)(b*HW + q0 + w*16 + gr)*CCH + h*DH;
        const __half* qp8 = qp + 8*CCH;
        #pragma unroll
        for (int ks = 0; ks < 5; ks++) {
            __half2 v0 = __hmul2(*(const __half2*)(qp  + ks*16 + 2*t4),     qs2);
            __half2 v1 = __hmul2(*(const __half2*)(qp8 + ks*16 + 2*t4),     qs2);
            __half2 v2 = __hmul2(*(const __half2*)(qp  + ks*16 + 8 + 2*t4), qs2);
            __half2 v3 = __hmul2(*(const __half2*)(qp8 + ks*16 + 8 + 2*t4), qs2);
            qf[ks][0] = *(uint32_t*)&v0; qf[ks][1] = *(uint32_t*)&v1;
            qf[ks][2] = *(uint32_t*)&v2; qf[ks][3] = *(uint32_t*)&v3;
        }
    }

    float s[10][4];
    #pragma unroll
    for (int ni = 0; ni < 10; ni++) { s[ni][0]=s[ni][1]=s[ni][2]=s[ni][3]=0.f; }
    #pragma unroll
    for (int ks = 0; ks < 5; ks++) {
        #pragma unroll
        for (int ni = 0; ni < 10; ni++) {
            uint32_t b0 = *(const uint32_t*)&Ks[(8*ni + gr)*KSR + ks*16 + 2*t4];
            uint32_t b1 = *(const uint32_t*)&Ks[(8*ni + gr)*KSR + ks*16 + 8 + 2*t4];
            mma16h(s[ni], qf[ks][0], qf[ks][1], qf[ks][2], qf[ks][3], b0, b1);
        }
    }
    if (t4 == 3) { s[9][0] = -1e30f; s[9][2] = -1e30f; }
    if (t4 >= 2) { s[9][1] = -1e30f; s[9][3] = -1e30f; }

    float m0 = -1e30f, m1 = -1e30f;
    #pragma unroll
    for (int ni = 0; ni < 10; ni++) {
        m0 = fmaxf(m0, fmaxf(s[ni][0], s[ni][1]));
        m1 = fmaxf(m1, fmaxf(s[ni][2], s[ni][3]));
    }
    m0 = fmaxf(m0, __shfl_xor_sync(~0u, m0, 1));
    m0 = fmaxf(m0, __shfl_xor_sync(~0u, m0, 2));
    m1 = fmaxf(m1, __shfl_xor_sync(~0u, m1, 1));
    m1 = fmaxf(m1, __shfl_xor_sync(~0u, m1, 2));
    float l0 = 0.f, l1 = 0.f;
    #pragma unroll
    for (int ni = 0; ni < 10; ni++) {
        s[ni][0] = __expf(s[ni][0] - m0);
        s[ni][1] = __expf(s[ni][1] - m0);
        s[ni][2] = __expf(s[ni][2] - m1);
        s[ni][3] = __expf(s[ni][3] - m1);
        l0 += s[ni][0] + s[ni][1];
        l1 += s[ni][2] + s[ni][3];
    }
    l0 += __shfl_xor_sync(~0u, l0, 1); l0 += __shfl_xor_sync(~0u, l0, 2);
    l1 += __shfl_xor_sync(~0u, l1, 1); l1 += __shfl_xor_sync(~0u, l1, 2);

    float oa[10][4];
    #pragma unroll
    for (int ni = 0; ni < 10; ni++) { oa[ni][0]=oa[ni][1]=oa[ni][2]=oa[ni][3]=0.f; }
    #pragma unroll
    for (int ks = 0; ks < 5; ks++) {
        uint32_t a0 = hpack(s[2*ks][0],   s[2*ks][1]);
        uint32_t a1 = hpack(s[2*ks][2],   s[2*ks][3]);
        uint32_t a2 = hpack(s[2*ks+1][0], s[2*ks+1][1]);
        uint32_t a3 = hpack(s[2*ks+1][2], s[2*ks+1][3]);
        #pragma unroll
        for (int ni = 0; ni < 10; ni++) {
            uint32_t b0 = *(const uint32_t*)&Vt[(8*ni + gr)*KSR + ks*16 + 2*t4];
            uint32_t b1 = *(const uint32_t*)&Vt[(8*ni + gr)*KSR + ks*16 + 8 + 2*t4];
            mma16h(oa[ni], a0, a1, a2, a3, b0, b1);
        }
    }

    float inv0 = 1.f / l0, inv1 = 1.f / l1;
    __half* Ob = O + ((size_t)(b*HW + q0 + w*16))*CCH + h*DH;
    #pragma unroll
    for (int ni = 0; ni < 10; ni++) {
        *(__half2*)(Ob + (size_t)gr*CCH + 8*ni + 2*t4) =
            __floats2half2_rn(oa[ni][0]*inv0, oa[ni][1]*inv0);
        *(__half2*)(Ob + (size_t)(gr+8)*CCH + 8*ni + 2*t4) =
            __floats2half2_rn(oa[ni][2]*inv1, oa[ni][3]*inv1);
    }
}

// ---------------- host launch ----------------
extern "C" void kernel_launch(void* const* d_in, const int* in_sizes, int n_in,
                              void* d_out, int out_size) {
    const float* x        = (const float*)d_in[0];
    const float* context  = (const float*)d_in[1];
    const float* gn_s     = (const float*)d_in[2];
    const float* gn_b     = (const float*)d_in[3];
    const float* conv1_w  = (const float*)d_in[4];
    const float* conv1_b  = (const float*)d_in[5];
    const float* ln1_s    = (const float*)d_in[6];
    const float* ln1_b    = (const float*)d_in[7];
    const float* sa_in_w  = (const float*)d_in[8];
    const float* sa_out_w = (const float*)d_in[9];
    const float* sa_out_b = (const float*)d_in[10];
    const float* ln2_s    = (const float*)d_in[11];
    const float* ln2_b    = (const float*)d_in[12];
    const float* ca_q_w   = (const float*)d_in[13];
    const float* ca_k_w   = (const float*)d_in[14];
    const float* ca_v_w   = (const float*)d_in[15];
    const float* ca_out_w = (const float*)d_in[16];
    const float* ca_out_b = (const float*)d_in[17];
    const float* ln3_s    = (const float*)d_in[18];
    const float* ln3_b    = (const float*)d_in[19];
    const float* lin1_w   = (const float*)d_in[20];
    const float* lin1_b   = (const float*)d_in[21];
    const float* lin2_w   = (const float*)d_in[22];
    const float* lin2_b   = (const float*)d_in[23];
    const float* co_w     = (const float*)d_in[24];
    const float* co_b     = (const float*)d_in[25];
    float* out = (float*)d_out;

    float *xseq, *lin1bi;
    __half *hgn, *ht, *hattn, *hctx, *hkv, *hffg, *hx, *hqkv, *hvt, *hw;
    cudaGetSymbolAddress((void**)&xseq, g_xseq);
    cudaGetSymbolAddress((void**)&lin1bi, g_lin1bi);
    cudaGetSymbolAddress((void**)&hgn,  h_gn);
    cudaGetSymbolAddress((void**)&ht,   h_t);
    cudaGetSymbolAddress((void**)&hattn,h_attn);
    cudaGetSymbolAddress((void**)&hctx, h_ctx);
    cudaGetSymbolAddress((void**)&hkv,  h_kv);
    cudaGetSymbolAddress((void**)&hffg, h_ffg);
    cudaGetSymbolAddress((void**)&hx,   h_x);
    cudaGetSymbolAddress((void**)&hqkv, h_qkv);
    cudaGetSymbolAddress((void**)&hvt,  h_vt);
    cudaGetSymbolAddress((void**)&hw,   h_w);

    __half* sa_in_wT  = hw;
    __half* sa_out_wT = sa_in_wT  + 1920*640;
    __half* ca_q_wT   = sa_out_wT + 640*640;
    __half* ca_k_wT   = ca_q_wT   + 640*640;
    __half* ca_v_wT   = ca_k_wT   + 640*512;
    __half* ca_out_wT = ca_v_wT   + 640*512;
    __half* lin1_wT   = ca_out_wT + 640*640;
    __half* lin2_wT   = lin1_wT   + 5120*640;
    __half* conv1_wh  = lin2_wT   + 640*2560;
    __half* co_wh     = conv1_wh  + 640*640;
    (void)ca_v_wT;

    cudaFuncSetAttribute(gemm_h<0>, cudaFuncAttributeMaxDynamicSharedMemorySize, GEMM_SMEM);
    cudaFuncSetAttribute(gemm_h<1>, cudaFuncAttributeMaxDynamicSharedMemorySize, GEMM_SMEM);
    cudaFuncSetAttribute(gemm_h<2>, cudaFuncAttributeMaxDynamicSharedMemorySize, GEMM_SMEM);
    cudaFuncSetAttribute(gemm_h<3>, cudaFuncAttributeMaxDynamicSharedMemorySize, GEMM_SMEM);

    const int M = NB * HW;      // 8192
    const int MC = NB * SKCTX;  // 616
    dim3 tblk(32, 8);
    dim3 tgrid(HW/32, CCH/32, NB);
    auto ggrid = [](int N_, int M_) { return dim3(N_/128, (M_+127)/128); };

    // 0. weight prep (2 launches)
    {
        W8 ws;
        auto mk = [](const float* s, __half* d, int K, int N, int off, int il) {
            WSeg w; w.src = s; w.dst = d; w.K = K; w.N = N;
            w.tilesX = N/32; w.tileOff = off; w.ileave = il; return w;
        };
        int off = 0;
        ws.w[0] = mk(sa_in_w,  sa_in_wT,  CCH, 3*CCH, off, 0); off += (3*CCH/32)*(CCH/32);
        ws.w[1] = mk(sa_out_w, sa_out_wT, CCH, CCH,   off, 0); off += (CCH/32)*(CCH/32);
        ws.w[2] = mk(ca_q_w,   ca_q_wT,   CCH, CCH,   off, 0); off += (CCH/32)*(CCH/32);
        ws.w[3] = mk(ca_k_w,   ca_k_wT,   DCTX, CCH,  off, 0); off += (CCH/32)*(DCTX/32);
        ws.w[4] = mk(ca_v_w,   ca_v_wT,   DCTX, CCH,  off, 0); off += (CCH/32)*(DCTX/32);
        ws.w[5] = mk(ca_out_w, ca_out_wT, CCH, CCH,   off, 0); off += (CCH/32)*(CCH/32);
        ws.w[6] = mk(lin1_w,   lin1_wT,   CCH, 8*CCH, off, 1); off += (8*CCH/32)*(CCH/32);
        ws.w[7] = mk(lin2_w,   lin2_wT,   4*CCH, CCH, off, 0); off += (CCH/32)*(4*CCH/32);
        wtrans_all<<<off, tblk>>>(ws);
    }
    {
        int e0 = CCH*CCH/4, e1 = CCH*CCH/4, e2 = MC*DCTX/4, e3 = CCH;  // e3: 4*CCH/4 groups
        cvt_all<<<(e0+e1+e2+e3 + 255)/256, 256>>>(conv1_w, conv1_wh, e0,
                                                  co_w, co_wh, e1,
                                                  context, hctx, e2,
                                                  lin1_b, lin1bi, e3);
    }

    // 1. GroupNorm + transpose
    gn_stats<<<NB*GRP, 1024>>>(x);
    gn_apply<<<tgrid, tblk>>>(x, gn_s, gn_b);

    // 2. conv1
    gemm_h<0><<<ggrid(CCH, M), 256, GEMM_SMEM>>>(hgn, CCH, conv1_wh, conv1_b, nullptr,
                                                 xseq, nullptr, CCH, M, CCH, CCH);

    // 3. self-attention (V transpose fused into qkv GEMM epilogue)
    layernorm<<<M, 160>>>(xseq, ln1_s, ln1_b, ht);
    gemm_h<3><<<ggrid(3*CCH, M), 256, GEMM_SMEM>>>(ht, CCH, sa_in_wT, nullptr, nullptr,
                                                   (float*)hvt, hqkv, 3*CCH, M, 3*CCH, CCH);
    flash_h<<<dim3(HW/128, NB*NH), 256>>>(hqkv, hvt, hattn);
    gemm_h<0><<<ggrid(CCH, M), 256, GEMM_SMEM>>>(hattn, CCH, sa_out_wT, sa_out_b, xseq,
                                                 xseq, nullptr, CCH, M, CCH, CCH);

    // 4. cross-attention
    layernorm<<<M, 160>>>(xseq, ln2_s, ln2_b, ht);
    gemm_h<0><<<ggrid(CCH, M), 256, GEMM_SMEM>>>(ht, CCH, ca_q_wT, nullptr, nullptr,
                                                 nullptr, hqkv, CCH, M, CCH, CCH);
    gemm_h<0><<<ggrid(2*CCH, MC), 256, GEMM_SMEM>>>(hctx, DCTX, ca_k_wT, nullptr, nullptr,
                                                    nullptr, hkv, 2*CCH, MC, 2*CCH, DCTX);
    xattn_h<<<dim3(HW/128, NB*NH), 256>>>(hqkv, hkv, hattn);
    gemm_h<0><<<ggrid(CCH, M), 256, GEMM_SMEM>>>(hattn, CCH, ca_out_wT, ca_out_b, xseq,
                                                 xseq, nullptr, CCH, M, CCH, CCH);

    // 5. GeGLU FFN
    layernorm<<<M, 160>>>(xseq, ln3_s, ln3_b, ht);
    gemm_h<1><<<ggrid(8*CCH, M), 256, GEMM_SMEM>>>(ht, CCH, lin1_wT, lin1bi, nullptr,
                                                   nullptr, hffg, 4*CCH, M, 8*CCH, CCH);
    gemm_h<0><<<ggrid(CCH, M), 256, GEMM_SMEM>>>(hffg, 4*CCH, lin2_wT, lin2_b, xseq,
                                                 xseq, hx, CCH, M, CCH, 4*CCH);

    // 6. final conv + long residual
    gemm_h<2><<<ggrid(CCH, M), 256, GEMM_SMEM>>>(hx, CCH, co_wh, co_b, x,
                                                 out, nullptr, CCH, M, CCH, CCH);
}

// round 13
// speedup vs baseline: 36.6146x; 1.0443x over previous
#include <cuda_runtime.h>
#include <cuda_fp16.h>
#include <math.h>
#include <stdint.h>

#define NB    8
#define CCH   640
#define HW    1024
#define NH    8
#define DH    80
#define DCTX  512
#define GRP   32
#define CPG   20
#define SKCTX 77

// ---------------- fp32 scratch ----------------
__device__ float  g_xseq [NB*HW*CCH];
__device__ float  g_gnstat[NB*GRP*2];
__device__ float  g_lin1bi[8*CCH];
// ---------------- fp16 scratch ----------------
__device__ __half h_gn  [NB*HW*CCH];
__device__ __half h_t   [NB*HW*CCH];
__device__ __half h_attn[NB*HW*CCH];
__device__ __half h_ctx [NB*SKCTX*DCTX];
__device__ __half h_kv  [NB*SKCTX*2*CCH];
__device__ __half h_ffg [NB*HW*4*CCH];
__device__ __half h_x   [NB*HW*CCH];
__device__ __half h_qkv [NB*HW*3*CCH];
__device__ __half h_vt  [NB*CCH*HW];
__device__ __half h_w   [8847360];       // all weights, fp16, [N,K]

// ---------------- GroupNorm stats ----------------
__global__ __launch_bounds__(1024)
void gn_stats(const float* __restrict__ x) {
    int ng = blockIdx.x;
    int n = ng / GRP, g = ng % GRP;
    const float4* base = (const float4*)(x + ((size_t)n*CCH + (size_t)g*CPG) * HW);
    float s = 0.f, s2 = 0.f;
    for (int i = threadIdx.x; i < CPG*HW/4; i += 1024) {
        float4 v = base[i];
        s  += v.x + v.y + v.z + v.w;
        s2 += v.x*v.x + v.y*v.y + v.z*v.z + v.w*v.w;
    }
    __shared__ float rs[1024], rq[1024];
    rs[threadIdx.x] = s; rq[threadIdx.x] = s2;
    __syncthreads();
    for (int o = 512; o > 0; o >>= 1) {
        if (threadIdx.x < o) { rs[threadIdx.x] += rs[threadIdx.x+o]; rq[threadIdx.x] += rq[threadIdx.x+o]; }
        __syncthreads();
    }
    if (threadIdx.x == 0) {
        float inv_n = 1.f / (float)(CPG*HW);
        float mu  = rs[0] * inv_n;
        float var = rq[0] * inv_n - mu*mu;
        g_gnstat[ng*2]   = mu;
        g_gnstat[ng*2+1] = rsqrtf(var + 1e-6f);
    }
}

// ---------------- GroupNorm apply + transpose -> fp16 [n,p,c] ----------------
__global__ void gn_apply(const float* __restrict__ x,
                         const float* __restrict__ s, const float* __restrict__ b) {
    __shared__ float tile[32][33];
    int n = blockIdx.z;
    int p0 = blockIdx.x*32, c0 = blockIdx.y*32;
    int tx = threadIdx.x, ty = threadIdx.y;
    #pragma unroll
    for (int i = 0; i < 4; i++) {
        int c = c0 + ty + i*8;
        int ng = n*GRP + c / CPG;
        float mu = g_gnstat[ng*2], is = g_gnstat[ng*2+1];
        float v = x[((size_t)n*CCH + c)*HW + p0 + tx];
        tile[ty + i*8][tx] = (v - mu) * is * s[c] + b[c];
    }
    __syncthreads();
    #pragma unroll
    for (int i = 0; i < 4; i++) {
        int p = p0 + ty + i*8;
        h_gn[((size_t)n*HW + p)*CCH + c0 + tx] = __float2half(tile[tx][ty + i*8]);
    }
}

// ---------------- merged weight transpose+convert ----------------
struct WSeg { const float* src; __half* dst; int K, N, tilesX, tileOff, ileave; };
struct W8 { WSeg w[8]; };
__global__ void wtrans_all(W8 ws) {
    __shared__ float t[32][33];
    int bid = blockIdx.x;
    int si = 0;
    #pragma unroll
    for (int i = 1; i < 8; i++)
        if (bid >= ws.w[i].tileOff) si = i;
    WSeg sg = ws.w[si];
    int local = bid - sg.tileOff;
    int n0 = (local % sg.tilesX) * 32;
    int k0 = (local / sg.tilesX) * 32;
    int tx = threadIdx.x, ty = threadIdx.y;
    #pragma unroll
    for (int i = 0; i < 4; i++)
        t[ty + i*8][tx] = sg.src[(size_t)(k0 + ty + i*8)*sg.N + n0 + tx];
    __syncthreads();
    int half = sg.N >> 1;
    #pragma unroll
    for (int i = 0; i < 4; i++) {
        int r = n0 + ty + i*8;
        int rr = sg.ileave ? ((r < half) ? 2*r : 2*(r - half) + 1) : r;
        sg.dst[(size_t)rr*sg.K + k0 + tx] = __float2half(t[tx][ty + i*8]);
    }
}

// ---------------- merged converts + lin1 bias interleave ----------------
__global__ void cvt_all(const float* s0, __half* d0, int e0,
                        const float* s1, __half* d1, int e1,
                        const float* s2, __half* d2, int e2,
                        const float* b,  float* bi,  int e3) {
    int i = blockIdx.x * 256 + threadIdx.x;
    if (i >= e0 + e1 + e2) {
        int off = i - e0 - e1 - e2;
        if (off < e3) {
            int j = off * 4;
            float4 a = *(const float4*)(b + j);
            float4 g = *(const float4*)(b + j + 4*CCH);
            *(float4*)(bi + 2*j)     = make_float4(a.x, g.x, a.y, g.y);
            *(float4*)(bi + 2*j + 4) = make_float4(a.z, g.z, a.w, g.w);
        }
        return;
    }
    const float* s; __half* d; int off;
    if (i < e0) { s = s0; d = d0; off = i; }
    else if (i < e0 + e1) { s = s1; d = d1; off = i - e0; }
    else { s = s2; d = d2; off = i - e0 - e1; }
    float4 v = ((const float4*)s)[off];
    union { uint2 u; __half2 h[2]; } pk;
    pk.h[0] = __floats2half2_rn(v.x, v.y);
    pk.h[1] = __floats2half2_rn(v.z, v.w);
    ((uint2*)d)[off] = pk.u;
}

// ---------------- LayerNorm fp32 in -> fp16 out ----------------
__global__ __launch_bounds__(160)
void layernorm(const float* __restrict__ in,
               const float* __restrict__ s, const float* __restrict__ b,
               __half* __restrict__ out) {
    int row = blockIdx.x;
    int tid = threadIdx.x;
    const float4* r4 = (const float4*)(in + (size_t)row * CCH);
    float4 v = r4[tid];
    float sum = v.x + v.y + v.z + v.w;
    float sq  = v.x*v.x + v.y*v.y + v.z*v.z + v.w*v.w;
    #pragma unroll
    for (int o = 16; o > 0; o >>= 1) {
        sum += __shfl_xor_sync(~0u, sum, o);
        sq  += __shfl_xor_sync(~0u, sq,  o);
    }
    __shared__ float ws[5], wq[5];
    int w = tid >> 5;
    if ((tid & 31) == 0) { ws[w] = sum; wq[w] = sq; }
    __syncthreads();
    sum = ws[0] + ws[1] + ws[2] + ws[3] + ws[4];
    sq  = wq[0] + wq[1] + wq[2] + wq[3] + wq[4];
    float mu  = sum / (float)CCH;
    float inv = rsqrtf(sq / (float)CCH - mu*mu + 1e-5f);
    float4 sc = ((const float4*)s)[tid];
    float4 bb = ((const float4*)b)[tid];
    union { uint2 u; __half2 h[2]; } pk;
    pk.h[0] = __floats2half2_rn((v.x - mu) * inv * sc.x + bb.x, (v.y - mu) * inv * sc.y + bb.y);
    pk.h[1] = __floats2half2_rn((v.z - mu) * inv * sc.z + bb.z, (v.w - mu) * inv * sc.w + bb.w);
    ((uint2*)(out + (size_t)row * CCH))[tid] = pk.u;
}

// ---------------- mma / cp.async helpers ----------------
__device__ __forceinline__ void mma16h(float c[4], uint32_t a0, uint32_t a1, uint32_t a2, uint32_t a3,
                                       uint32_t b0, uint32_t b1) {
    asm volatile("mma.sync.aligned.m16n8k16.row.col.f32.f16.f16.f32 "
        "{%0,%1,%2,%3}, {%4,%5,%6,%7}, {%8,%9}, {%0,%1,%2,%3};"
        : "+f"(c[0]), "+f"(c[1]), "+f"(c[2]), "+f"(c[3])
        : "r"(a0), "r"(a1), "r"(a2), "r"(a3), "r"(b0), "r"(b1));
}
__device__ __forceinline__ void ldsm4(uint32_t r[4], uint32_t addr) {
    asm volatile("ldmatrix.sync.aligned.m8n8.x4.shared.b16 {%0,%1,%2,%3}, [%4];"
        : "=r"(r[0]), "=r"(r[1]), "=r"(r[2]), "=r"(r[3]) : "r"(addr));
}
__device__ __forceinline__ void cpa16(void* dst, const void* src, bool valid) {
    uint32_t d = (uint32_t)__cvta_generic_to_shared(dst);
    int sz = valid ? 16 : 0;
    asm volatile("cp.async.cg.shared.global [%0], [%1], 16, %2;" :: "r"(d), "l"(src), "r"(sz));
}
#define CP_COMMIT() asm volatile("cp.async.commit_group;")
#define CP_WAIT1()  asm volatile("cp.async.wait_group 1;")
__device__ __forceinline__ uint32_t hpack(float a, float b) {
    __half2 h = __floats2half2_rn(a, b);
    return *(uint32_t*)&h;
}

// ---------------- fp16 GEMM core: 128x128x64, 3-stage cp.async, all-ldmatrix ----------------
// MODE 0: normal  MODE 1: geglu epilogue  MODE 2: NCHW transpose+residual out
// MODE 3: fp16 out + transposed V side-store for tiles bn >= 2*CCH
#define RS36 36
#define BUFU (128*RS36)
#define NST  3
#define GEMM_SMEM (NST*2*BUFU*4)
template<int MODE>
__device__ __forceinline__
void gemm_core(uint32_t* sm, int bm, int bn,
               const __half* __restrict__ A, int lda,
               const __half* __restrict__ B,
               const float* __restrict__ bias,
               const float* __restrict__ res,
               float* __restrict__ C, __half* __restrict__ Ch, int ldc,
               int M, int N, int K) {
    uint32_t* As = sm;
    uint32_t* Bs = sm + NST*BUFU;
    uint32_t a_u32 = (uint32_t)__cvta_generic_to_shared(As);
    uint32_t b_u32 = (uint32_t)__cvta_generic_to_shared(Bs);

    int tid = threadIdx.x;
    int lane = tid & 31, warp = tid >> 5;
    int gr = lane >> 2, t4 = lane & 3;
    int wm = (warp >> 2) * 64, wn = (warp & 3) * 32;

    uint32_t lds_off  = (uint32_t)((lane & 15) * (RS36*4) + ((lane >> 4) << 4));
    uint32_t ldsb_off = (uint32_t)(((lane & 7) + ((lane >> 4) << 3)) * (RS36*4)
                                   + (((lane >> 3) & 1) << 4));

    auto stage = [&](int kt, int buf) {
        #pragma unroll
        for (int i = 0; i < 4; i++) {
            int c = tid + i*256;
            int row = c >> 3, seg = c & 7;
            int gm = bm + row;
            cpa16(As + buf*BUFU + row*RS36 + seg*4,
                  A + ((size_t)(gm < M ? gm : 0))*lda + kt*64 + seg*8, gm < M);
        }
        #pragma unroll
        for (int i = 0; i < 4; i++) {
            int c = tid + i*256;
            int row = c >> 3, seg = c & 7;
            int gn = bn + row;
            cpa16(Bs + buf*BUFU + row*RS36 + seg*4,
                  B + ((size_t)(gn < N ? gn : 0))*K + kt*64 + seg*8, gn < N);
        }
    };

    float acc[4][4][4];
    #pragma unroll
    for (int i = 0; i < 4; i++)
        #pragma unroll
        for (int j = 0; j < 4; j++)
            #pragma unroll
            for (int r = 0; r < 4; r++) acc[i][j][r] = 0.f;

    int nk = K >> 6;
    stage(0, 0); CP_COMMIT();
    stage(1, 1); CP_COMMIT();

    int buf = 0;
    for (int t = 0; t < nk; t++) {
        CP_WAIT1();
        __syncthreads();
        if (t + 2 < nk) stage(t+2, (t+2) % NST);
        CP_COMMIT();

        uint32_t a_base = a_u32 + buf*(BUFU*4) + lds_off;
        uint32_t b_base = b_u32 + buf*(BUFU*4) + ldsb_off;

        #pragma unroll
        for (int ks = 0; ks < 4; ks++) {
            uint32_t af[4][4], bf[4][2];
            #pragma unroll
            for (int mi = 0; mi < 4; mi++)
                ldsm4(af[mi], a_base + (uint32_t)((wm + mi*16)*(RS36*4) + ks*32));
            #pragma unroll
            for (int p = 0; p < 2; p++) {
                uint32_t r[4];
                ldsm4(r, b_base + (uint32_t)((wn + p*16)*(RS36*4) + ks*32));
                bf[2*p][0]   = r[0]; bf[2*p][1]   = r[1];
                bf[2*p+1][0] = r[2]; bf[2*p+1][1] = r[3];
            }
            #pragma unroll
            for (int mi = 0; mi < 4; mi++)
                #pragma unroll
                for (int ni = 0; ni < 4; ni++)
                    mma16h(acc[mi][ni], af[mi][0], af[mi][1], af[mi][2], af[mi][3],
                           bf[ni][0], bf[ni][1]);
        }
        buf = (buf + 1 == NST) ? 0 : buf + 1;
    }

    if (MODE == 2) {
        __syncthreads();
        float* eb = (float*)sm;          // [128 cols][132]
        #pragma unroll
        for (int mi = 0; mi < 4; mi++) {
            #pragma unroll
            for (int ni = 0; ni < 4; ni++) {
                int col_l = wn + ni*8 + t4*2;
                int col0  = bn + col_l;
                #pragma unroll
                for (int half_r = 0; half_r < 2; half_r++) {
                    int row_l = wm + mi*16 + gr + half_r*8;
                    eb[(col_l)*132 + row_l]   = acc[mi][ni][half_r*2 + 0] + bias[col0];
                    eb[(col_l+1)*132 + row_l] = acc[mi][ni][half_r*2 + 1] + bias[col0+1];
                }
            }
        }
        __syncthreads();
        int n = bm >> 10, p0 = bm & 1023;
        for (int i = tid; i < 128*32; i += 256) {
            int c = i >> 5, seg = i & 31;
            size_t off = ((size_t)(n*CCH + bn + c))*HW + p0 + seg*4;
            const float* e = eb + c*132 + seg*4;
            float4 xr = *(const float4*)(res + off);
            *(float4*)(C + off) = make_float4(e[0]+xr.x, e[1]+xr.y, e[2]+xr.z, e[3]+xr.w);
        }
        return;
    }

    #pragma unroll
    for (int mi = 0; mi < 4; mi++) {
        #pragma unroll
        for (int ni = 0; ni < 4; ni++) {
            int col0 = bn + wn + ni*8 + t4*2;
            #pragma unroll
            for (int half_r = 0; half_r < 2; half_r++) {
                int row = bm + wm + mi*16 + gr + half_r*8;
                if (row >= M) continue;
                float v0 = acc[mi][ni][half_r*2 + 0];
                float v1 = acc[mi][ni][half_r*2 + 1];
                if (MODE == 1) {
                    float a = v0 + bias[col0];
                    float g = v1 + bias[col0+1];
                    float ge = 0.5f * g * (1.f + erff(g * 0.70710678118654752f));
                    Ch[(size_t)row*ldc + (col0 >> 1)] = __float2half(a * ge);
                } else {
                    if (bias) { v0 += bias[col0]; v1 += bias[col0+1]; }
                    if (res) {
                        const float* rp = res + (size_t)row*ldc + col0;
                        v0 += rp[0]; v1 += rp[1];
                    }
                    if (MODE == 0 && C) *(float2*)(C + (size_t)row*ldc + col0) = make_float2(v0, v1);
                    if (Ch) *(__half2*)(Ch + (size_t)row*ldc + col0) = __floats2half2_rn(v0, v1);
                }
            }
        }
    }

    if (MODE == 3 && bn >= 2*CCH) {
        __syncthreads();
        __half* eb = (__half*)sm;        // [128][136]
        #pragma unroll
        for (int mi = 0; mi < 4; mi++) {
            #pragma unroll
            for (int ni = 0; ni < 4; ni++) {
                int col_l = wn + ni*8 + t4*2;
                #pragma unroll
                for (int half_r = 0; half_r < 2; half_r++) {
                    int row_l = wm + mi*16 + gr + half_r*8;
                    eb[(col_l)*136 + row_l]   = __float2half(acc[mi][ni][half_r*2 + 0]);
                    eb[(col_l+1)*136 + row_l] = __float2half(acc[mi][ni][half_r*2 + 1]);
                }
            }
        }
        __syncthreads();
        __half* vt = (__half*)C;
        int b = bm >> 10, p0 = bm & 1023;
        int c0 = bn - 2*CCH;
        for (int i = tid; i < 128*16; i += 256) {
            int c = i >> 4, seg = i & 15;
            *(uint4*)(vt + ((size_t)(b*CCH + c0 + c))*HW + p0 + seg*8) =
                *(const uint4*)(eb + c*136 + seg*8);
        }
    }
}

template<int MODE>
__global__ __launch_bounds__(256, 2)
void gemm_h(const __half* __restrict__ A, int lda,
            const __half* __restrict__ B,
            const float* __restrict__ bias,
            const float* __restrict__ res,
            float* __restrict__ C, __half* __restrict__ Ch, int ldc,
            int M, int N, int K) {
    extern __shared__ uint32_t sm[];
    gemm_core<MODE>(sm, blockIdx.y*128, blockIdx.x*128,
                    A, lda, B, bias, res, C, Ch, ldc, M, N, K);
}

// dual GEMM: CTAs [0,split) -> GEMM0 (grid nx0 x *), rest -> GEMM1 (grid nx1 x *)
__global__ __launch_bounds__(256, 2)
void gemm_dual(const __half* A0, int lda0, const __half* B0, __half* Ch0, int ldc0,
               int M0, int N0, int K0, int nx0, int split,
               const __half* A1, int lda1, const __half* B1, __half* Ch1, int ldc1,
               int M1, int N1, int K1, int nx1) {
    extern __shared__ uint32_t sm[];
    int bid = blockIdx.x;
    if (bid < split) {
        gemm_core<0>(sm, (bid/nx0)*128, (bid%nx0)*128,
                     A0, lda0, B0, nullptr, nullptr, nullptr, Ch0, ldc0, M0, N0, K0);
    } else {
        int l = bid - split;
        gemm_core<0>(sm, (l/nx1)*128, (l%nx1)*128,
                     A1, lda1, B1, nullptr, nullptr, nullptr, Ch1, ldc1, M1, N1, K1);
    }
}

// ---------------- fused flash self-attention, full fp16 mma, 2 CTA/SM ----------------
#define KSR 88
#define VSR 72
__global__ __launch_bounds__(256, 2)
void flash_h(const __half* __restrict__ QKV, const __half* __restrict__ VT,
             __half* __restrict__ O) {
    constexpr int LD = 3*CCH;
    __shared__ __half Ks[2][64*KSR];
    __shared__ __half Vs[2][80*VSR];

    int tid = threadIdx.x, lane = tid & 31, w = tid >> 5;
    int z = blockIdx.y;
    int b = z >> 3, h = z & 7;
    int q0 = blockIdx.x * 128;
    int gr = lane >> 2, t4 = lane & 3;

    const __half* Kb  = QKV + ((size_t)b*HW)*LD + CCH + h*DH;
    const __half* Vtb = VT + ((size_t)b*CCH + h*DH)*HW;

    auto stage = [&](int kt, int buf) {
        #pragma unroll
        for (int i = 0; i < 3; i++) {
            int s = tid + i*256;
            if (s < 640) {
                int r = s / 10, g = s - r*10;
                cpa16(&Ks[buf][r*KSR + g*8], Kb + (size_t)(kt*64 + r)*LD + g*8, true);
            }
        }
        #pragma unroll
        for (int i = 0; i < 3; i++) {
            int s = tid + i*256;
            if (s < 640) {
                int r = s >> 3, g = s & 7;
                cpa16(&Vs[buf][r*VSR + g*8], Vtb + (size_t)r*HW + kt*64 + g*8, true);
            }
        }
    };

    stage(0, 0);
    CP_COMMIT();

    const __half2 qs2 = __float2half2_rn(0.1118033988749895f);
    uint32_t qf[5][4];
    {
        const __half* qp  = QKV + (size_t)(b*HW + q0 + w*16 + gr)*LD + h*DH;
        const __half* qp8 = qp + 8*LD;
        #pragma unroll
        for (int ks = 0; ks < 5; ks++) {
            __half2 v0 = __hmul2(*(const __half2*)(qp  + ks*16 + 2*t4),     qs2);
            __half2 v1 = __hmul2(*(const __half2*)(qp8 + ks*16 + 2*t4),     qs2);
            __half2 v2 = __hmul2(*(const __half2*)(qp  + ks*16 + 8 + 2*t4), qs2);
            __half2 v3 = __hmul2(*(const __half2*)(qp8 + ks*16 + 8 + 2*t4), qs2);
            qf[ks][0] = *(uint32_t*)&v0; qf[ks][1] = *(uint32_t*)&v1;
            qf[ks][2] = *(uint32_t*)&v2; qf[ks][3] = *(uint32_t*)&v3;
        }
    }

    float m0v = -1e30f, m1v = -1e30f, l0 = 0.f, l1 = 0.f;
    float oa[10][4];
    #pragma unroll
    for (int ni = 0; ni < 10; ni++) { oa[ni][0]=oa[ni][1]=oa[ni][2]=oa[ni][3]=0.f; }

    for (int kt = 0; kt < 16; kt++) {
        if (kt + 1 < 16) stage(kt+1, (kt+1) & 1);
        CP_COMMIT();
        CP_WAIT1();
        __syncthreads();
        const __half* Kc = Ks[kt & 1];
        const __half* Vc = Vs[kt & 1];

        float s[8][4];
        #pragma unroll
        for (int ni = 0; ni < 8; ni++) { s[ni][0]=s[ni][1]=s[ni][2]=s[ni][3]=0.f; }
        #pragma unroll
        for (int ks = 0; ks < 5; ks++) {
            #pragma unroll
            for (int ni = 0; ni < 8; ni++) {
                uint32_t b0 = *(const uint32_t*)&Kc[(8*ni + gr)*KSR + ks*16 + 2*t4];
                uint32_t b1 = *(const uint32_t*)&Kc[(8*ni + gr)*KSR + ks*16 + 8 + 2*t4];
                mma16h(s[ni], qf[ks][0], qf[ks][1], qf[ks][2], qf[ks][3], b0, b1);
            }
        }

        float tm0 = -1e30f, tm1 = -1e30f;
        #pragma unroll
        for (int ni = 0; ni < 8; ni++) {
            tm0 = fmaxf(tm0, fmaxf(s[ni][0], s[ni][1]));
            tm1 = fmaxf(tm1, fmaxf(s[ni][2], s[ni][3]));
        }
        tm0 = fmaxf(tm0, __shfl_xor_sync(~0u, tm0, 1));
        tm0 = fmaxf(tm0, __shfl_xor_sync(~0u, tm0, 2));
        tm1 = fmaxf(tm1, __shfl_xor_sync(~0u, tm1, 1));
        tm1 = fmaxf(tm1, __shfl_xor_sync(~0u, tm1, 2));
        float mn0 = fmaxf(m0v, tm0), mn1 = fmaxf(m1v, tm1);
        float al0 = __expf(m0v - mn0), al1 = __expf(m1v - mn1);
        m0v = mn0; m1v = mn1;
        float ts0 = 0.f, ts1 = 0.f;
        #pragma unroll
        for (int ni = 0; ni < 8; ni++) {
            s[ni][0] = __expf(s[ni][0] - mn0);
            s[ni][1] = __expf(s[ni][1] - mn0);
            s[ni][2] = __expf(s[ni][2] - mn1);
            s[ni][3] = __expf(s[ni][3] - mn1);
            ts0 += s[ni][0] + s[ni][1];
            ts1 += s[ni][2] + s[ni][3];
        }
        ts0 += __shfl_xor_sync(~0u, ts0, 1); ts0 += __shfl_xor_sync(~0u, ts0, 2);
        ts1 += __shfl_xor_sync(~0u, ts1, 1); ts1 += __shfl_xor_sync(~0u, ts1, 2);
        l0 = l0*al0 + ts0;
        l1 = l1*al1 + ts1;
        #pragma unroll
        for (int ni = 0; ni < 10; ni++) {
            oa[ni][0] *= al0; oa[ni][1] *= al0;
            oa[ni][2] *= al1; oa[ni][3] *= al1;
        }

        #pragma unroll
        for (int ks = 0; ks < 4; ks++) {
            uint32_t a0 = hpack(s[2*ks][0],   s[2*ks][1]);
            uint32_t a1 = hpack(s[2*ks][2],   s[2*ks][3]);
            uint32_t a2 = hpack(s[2*ks+1][0], s[2*ks+1][1]);
            uint32_t a3 = hpack(s[2*ks+1][2], s[2*ks+1][3]);
            #pragma unroll
            for (int ni = 0; ni < 10; ni++) {
                uint32_t b0 = *(const uint32_t*)&Vc[(8*ni + gr)*VSR + ks*16 + 2*t4];
                uint32_t b1 = *(const uint32_t*)&Vc[(8*ni + gr)*VSR + ks*16 + 8 + 2*t4];
                mma16h(oa[ni], a0, a1, a2, a3, b0, b1);
            }
        }
        __syncthreads();
    }

    float inv0 = 1.f / l0, inv1 = 1.f / l1;
    __half* Ob = O + ((size_t)(b*HW + q0 + w*16))*CCH + h*DH;
    #pragma unroll
    for (int ni = 0; ni < 10; ni++) {
        *(__half2*)(Ob + (size_t)gr*CCH + 8*ni + 2*t4) =
            __floats2half2_rn(oa[ni][0]*inv0, oa[ni][1]*inv0);
        *(__half2*)(Ob + (size_t)(gr+8)*CCH + 8*ni + 2*t4) =
            __floats2half2_rn(oa[ni][2]*inv1, oa[ni][3]*inv1);
    }
}

// ---------------- tiled fp16 cross-attention (SK=77 padded to 80), 2 CTA/SM ----------------
__global__ __launch_bounds__(256, 2)
void xattn_h(const __half* __restrict__ Q, const __half* __restrict__ KV,
             __half* __restrict__ O) {
    __shared__ __half Ks[80*KSR];
    __shared__ __half Vt[80*KSR];

    int tid = threadIdx.x, lane = tid & 31, w = tid >> 5;
    int z = blockIdx.y;
    int b = z >> 3, h = z & 7;
    int q0 = blockIdx.x * 128;
    int gr = lane >> 2, t4 = lane & 3;

    for (int i = tid; i < 80*KSR; i += 256) { Ks[i] = __half(0.f); Vt[i] = __half(0.f); }
    __syncthreads();

    const __half* kc = KV + (size_t)(b*SKCTX)*(2*CCH) + h*DH;
    const __half* vc = kc + CCH;
    for (int idx = tid; idx < SKCTX*40; idx += 256) {
        int key = idx / 40, d2 = idx - key*40;
        __half2 kv = *(const __half2*)(kc + (size_t)key*(2*CCH) + 2*d2);
        __half2 vv = *(const __half2*)(vc + (size_t)key*(2*CCH) + 2*d2);
        *(__half2*)&Ks[key*KSR + 2*d2] = kv;
        Vt[(2*d2)*KSR + key]   = vv.x;
        Vt[(2*d2+1)*KSR + key] = vv.y;
    }
    __syncthreads();

    const __half2 qs2 = __float2half2_rn(0.1118033988749895f);
    uint32_t qf[5][4];
    {
        const __half* qp  = Q + (size_t)(b*HW + q0 + w*16 + gr)*CCH + h*DH;
        const __half* qp8 = qp + 8*CCH;
        #pragma unroll
        for (int ks = 0; ks < 5; ks++) {
            __half2 v0 = __hmul2(*(const __half2*)(qp  + ks*16 + 2*t4),     qs2);
            __half2 v1 = __hmul2(*(const __half2*)(qp8 + ks*16 + 2*t4),     qs2);
            __half2 v2 = __hmul2(*(const __half2*)(qp  + ks*16 + 8 + 2*t4), qs2);
            __half2 v3 = __hmul2(*(const __half2*)(qp8 + ks*16 + 8 + 2*t4), qs2);
            qf[ks][0] = *(uint32_t*)&v0; qf[ks][1] = *(uint32_t*)&v1;
            qf[ks][2] = *(uint32_t*)&v2; qf[ks][3] = *(uint32_t*)&v3;
        }
    }

    float s[10][4];
    #pragma unroll
    for (int ni = 0; ni < 10; ni++) { s[ni][0]=s[ni][1]=s[ni][2]=s[ni][3]=0.f; }
    #pragma unroll
    for (int ks = 0; ks < 5; ks++) {
        #pragma unroll
        for (int ni = 0; ni < 10; ni++) {
            uint32_t b0 = *(const uint32_t*)&Ks[(8*ni + gr)*KSR + ks*16 + 2*t4];
            uint32_t b1 = *(const uint32_t*)&Ks[(8*ni + gr)*KSR + ks*16 + 8 + 2*t4];
            mma16h(s[ni], qf[ks][0], qf[ks][1], qf[ks][2], qf[ks][3], b0, b1);
        }
    }
    if (t4 == 3) { s[9][0] = -1e30f; s[9][2] = -1e30f; }
    if (t4 >= 2) { s[9][1] = -1e30f; s[9][3] = -1e30f; }

    float m0 = -1e30f, m1 = -1e30f;
    #pragma unroll
    for (int ni = 0; ni < 10; ni++) {
        m0 = fmaxf(m0, fmaxf(s[ni][0], s[ni][1]));
        m1 = fmaxf(m1, fmaxf(s[ni][2], s[ni][3]));
    }
    m0 = fmaxf(m0, __shfl_xor_sync(~0u, m0, 1));
    m0 = fmaxf(m0, __shfl_xor_sync(~0u, m0, 2));
    m1 = fmaxf(m1, __shfl_xor_sync(~0u, m1, 1));
    m1 = fmaxf(m1, __shfl_xor_sync(~0u, m1, 2));
    float l0 = 0.f, l1 = 0.f;
    #pragma unroll
    for (int ni = 0; ni < 10; ni++) {
        s[ni][0] = __expf(s[ni][0] - m0);
        s[ni][1] = __expf(s[ni][1] - m0);
        s[ni][2] = __expf(s[ni][2] - m1);
        s[ni][3] = __expf(s[ni][3] - m1);
        l0 += s[ni][0] + s[ni][1];
        l1 += s[ni][2] + s[ni][3];
    }
    l0 += __shfl_xor_sync(~0u, l0, 1); l0 += __shfl_xor_sync(~0u, l0, 2);
    l1 += __shfl_xor_sync(~0u, l1, 1); l1 += __shfl_xor_sync(~0u, l1, 2);

    float oa[10][4];
    #pragma unroll
    for (int ni = 0; ni < 10; ni++) { oa[ni][0]=oa[ni][1]=oa[ni][2]=oa[ni][3]=0.f; }
    #pragma unroll
    for (int ks = 0; ks < 5; ks++) {
        uint32_t a0 = hpack(s[2*ks][0],   s[2*ks][1]);
        uint32_t a1 = hpack(s[2*ks][2],   s[2*ks][3]);
        uint32_t a2 = hpack(s[2*ks+1][0], s[2*ks+1][1]);
        uint32_t a3 = hpack(s[2*ks+1][2], s[2*ks+1][3]);
        #pragma unroll
        for (int ni = 0; ni < 10; ni++) {
            uint32_t b0 = *(const uint32_t*)&Vt[(8*ni + gr)*KSR + ks*16 + 2*t4];
            uint32_t b1 = *(const uint32_t*)&Vt[(8*ni + gr)*KSR + ks*16 + 8 + 2*t4];
            mma16h(oa[ni], a0, a1, a2, a3, b0, b1);
        }
    }

    float inv0 = 1.f / l0, inv1 = 1.f / l1;
    __half* Ob = O + ((size_t)(b*HW + q0 + w*16))*CCH + h*DH;
    #pragma unroll
    for (int ni = 0; ni < 10; ni++) {
        *(__half2*)(Ob + (size_t)gr*CCH + 8*ni + 2*t4) =
            __floats2half2_rn(oa[ni][0]*inv0, oa[ni][1]*inv0);
        *(__half2*)(Ob + (size_t)(gr+8)*CCH + 8*ni + 2*t4) =
            __floats2half2_rn(oa[ni][2]*inv1, oa[ni][3]*inv1);
    }
}

// ---------------- host launch ----------------
extern "C" void kernel_launch(void* const* d_in, const int* in_sizes, int n_in,
                              void* d_out, int out_size) {
    const float* x        = (const float*)d_in[0];
    const float* context  = (const float*)d_in[1];
    const float* gn_s     = (const float*)d_in[2];
    const float* gn_b     = (const float*)d_in[3];
    const float* conv1_w  = (const float*)d_in[4];
    const float* conv1_b  = (const float*)d_in[5];
    const float* ln1_s    = (const float*)d_in[6];
    const float* ln1_b    = (const float*)d_in[7];
    const float* sa_in_w  = (const float*)d_in[8];
    const float* sa_out_w = (const float*)d_in[9];
    const float* sa_out_b = (const float*)d_in[10];
    const float* ln2_s    = (const float*)d_in[11];
    const float* ln2_b    = (const float*)d_in[12];
    const float* ca_q_w   = (const float*)d_in[13];
    const float* ca_k_w   = (const float*)d_in[14];
    const float* ca_v_w   = (const float*)d_in[15];
    const float* ca_out_w = (const float*)d_in[16];
    const float* ca_out_b = (const float*)d_in[17];
    const float* ln3_s    = (const float*)d_in[18];
    const float* ln3_b    = (const float*)d_in[19];
    const float* lin1_w   = (const float*)d_in[20];
    const float* lin1_b   = (const float*)d_in[21];
    const float* lin2_w   = (const float*)d_in[22];
    const float* lin2_b   = (const float*)d_in[23];
    const float* co_w     = (const float*)d_in[24];
    const float* co_b     = (const float*)d_in[25];
    float* out = (float*)d_out;

    float *xseq, *lin1bi;
    __half *hgn, *ht, *hattn, *hctx, *hkv, *hffg, *hx, *hqkv, *hvt, *hw;
    cudaGetSymbolAddress((void**)&xseq, g_xseq);
    cudaGetSymbolAddress((void**)&lin1bi, g_lin1bi);
    cudaGetSymbolAddress((void**)&hgn,  h_gn);
    cudaGetSymbolAddress((void**)&ht,   h_t);
    cudaGetSymbolAddress((void**)&hattn,h_attn);
    cudaGetSymbolAddress((void**)&hctx, h_ctx);
    cudaGetSymbolAddress((void**)&hkv,  h_kv);
    cudaGetSymbolAddress((void**)&hffg, h_ffg);
    cudaGetSymbolAddress((void**)&hx,   h_x);
    cudaGetSymbolAddress((void**)&hqkv, h_qkv);
    cudaGetSymbolAddress((void**)&hvt,  h_vt);
    cudaGetSymbolAddress((void**)&hw,   h_w);

    __half* sa_in_wT  = hw;
    __half* sa_out_wT = sa_in_wT  + 1920*640;
    __half* ca_q_wT   = sa_out_wT + 640*640;
    __half* ca_k_wT   = ca_q_wT   + 640*640;
    __half* ca_v_wT   = ca_k_wT   + 640*512;
    __half* ca_out_wT = ca_v_wT   + 640*512;
    __half* lin1_wT   = ca_out_wT + 640*640;
    __half* lin2_wT   = lin1_wT   + 5120*640;
    __half* conv1_wh  = lin2_wT   + 640*2560;
    __half* co_wh     = conv1_wh  + 640*640;
    (void)ca_v_wT;

    cudaFuncSetAttribute(gemm_h<0>, cudaFuncAttributeMaxDynamicSharedMemorySize, GEMM_SMEM);
    cudaFuncSetAttribute(gemm_h<1>, cudaFuncAttributeMaxDynamicSharedMemorySize, GEMM_SMEM);
    cudaFuncSetAttribute(gemm_h<2>, cudaFuncAttributeMaxDynamicSharedMemorySize, GEMM_SMEM);
    cudaFuncSetAttribute(gemm_h<3>, cudaFuncAttributeMaxDynamicSharedMemorySize, GEMM_SMEM);
    cudaFuncSetAttribute(gemm_dual, cudaFuncAttributeMaxDynamicSharedMemorySize, GEMM_SMEM);

    const int M = NB * HW;      // 8192
    const int MC = NB * SKCTX;  // 616
    dim3 tblk(32, 8);
    dim3 tgrid(HW/32, CCH/32, NB);
    auto ggrid = [](int N_, int M_) { return dim3(N_/128, (M_+127)/128); };

    // 0. weight prep
    {
        W8 ws;
        auto mk = [](const float* s, __half* d, int K, int N, int off, int il) {
            WSeg w; w.src = s; w.dst = d; w.K = K; w.N = N;
            w.tilesX = N/32; w.tileOff = off; w.ileave = il; return w;
        };
        int off = 0;
        ws.w[0] = mk(sa_in_w,  sa_in_wT,  CCH, 3*CCH, off, 0); off += (3*CCH/32)*(CCH/32);
        ws.w[1] = mk(sa_out_w, sa_out_wT, CCH, CCH,   off, 0); off += (CCH/32)*(CCH/32);
        ws.w[2] = mk(ca_q_w,   ca_q_wT,   CCH, CCH,   off, 0); off += (CCH/32)*(CCH/32);
        ws.w[3] = mk(ca_k_w,   ca_k_wT,   DCTX, CCH,  off, 0); off += (CCH/32)*(DCTX/32);
        ws.w[4] = mk(ca_v_w,   ca_v_wT,   DCTX, CCH,  off, 0); off += (CCH/32)*(DCTX/32);
        ws.w[5] = mk(ca_out_w, ca_out_wT, CCH, CCH,   off, 0); off += (CCH/32)*(CCH/32);
        ws.w[6] = mk(lin1_w,   lin1_wT,   CCH, 8*CCH, off, 1); off += (8*CCH/32)*(CCH/32);
        ws.w[7] = mk(lin2_w,   lin2_wT,   4*CCH, CCH, off, 0); off += (CCH/32)*(4*CCH/32);
        wtrans_all<<<off, tblk>>>(ws);
    }
    {
        int e0 = CCH*CCH/4, e1 = CCH*CCH/4, e2 = MC*DCTX/4, e3 = CCH;
        cvt_all<<<(e0+e1+e2+e3 + 255)/256, 256>>>(conv1_w, conv1_wh, e0,
                                                  co_w, co_wh, e1,
                                                  context, hctx, e2,
                                                  lin1_b, lin1bi, e3);
    }

    // 1. GroupNorm + transpose
    gn_stats<<<NB*GRP, 1024>>>(x);
    gn_apply<<<tgrid, tblk>>>(x, gn_s, gn_b);

    // 2. conv1
    gemm_h<0><<<ggrid(CCH, M), 256, GEMM_SMEM>>>(hgn, CCH, conv1_wh, conv1_b, nullptr,
                                                 xseq, nullptr, CCH, M, CCH, CCH);

    // 3. self-attention
    layernorm<<<M, 160>>>(xseq, ln1_s, ln1_b, ht);
    gemm_h<3><<<ggrid(3*CCH, M), 256, GEMM_SMEM>>>(ht, CCH, sa_in_wT, nullptr, nullptr,
                                                   (float*)hvt, hqkv, 3*CCH, M, 3*CCH, CCH);
    flash_h<<<dim3(HW/128, NB*NH), 256>>>(hqkv, hvt, hattn);
    gemm_h<0><<<ggrid(CCH, M), 256, GEMM_SMEM>>>(hattn, CCH, sa_out_wT, sa_out_b, xseq,
                                                 xseq, nullptr, CCH, M, CCH, CCH);

    // 4. cross-attention: q-proj (320 CTAs) + kv-proj (50 CTAs) fused into one launch
    layernorm<<<M, 160>>>(xseq, ln2_s, ln2_b, ht);
    {
        int nq = (CCH/128) * (M/128);                       // 5*64 = 320
        int nkv = (2*CCH/128) * ((MC + 127)/128);           // 10*5 = 50
        gemm_dual<<<nq + nkv, 256, GEMM_SMEM>>>(
            ht, CCH, ca_q_wT, hqkv, CCH, M, CCH, CCH, CCH/128, nq,
            hctx, DCTX, ca_k_wT, hkv, 2*CCH, MC, 2*CCH, DCTX, 2*CCH/128);
    }
    xattn_h<<<dim3(HW/128, NB*NH), 256>>>(hqkv, hkv, hattn);
    gemm_h<0><<<ggrid(CCH, M), 256, GEMM_SMEM>>>(hattn, CCH, ca_out_wT, ca_out_b, xseq,
                                                 xseq, nullptr, CCH, M, CCH, CCH);

    // 5. GeGLU FFN (lin2: fp32 xseq is dead after this point — fp16 out only)
    layernorm<<<M, 160>>>(xseq, ln3_s, ln3_b, ht);
    gemm_h<1><<<ggrid(8*CCH, M), 256, GEMM_SMEM>>>(ht, CCH, lin1_wT, lin1bi, nullptr,
                                                   nullptr, hffg, 4*CCH, M, 8*CCH, CCH);
    gemm_h<0><<<ggrid(CCH, M), 256, GEMM_SMEM>>>(hffg, 4*CCH, lin2_wT, lin2_b, xseq,
                                                 nullptr, hx, CCH, M, CCH, 4*CCH);

    // 6. final conv + long residual
    gemm_h<2><<<ggrid(CCH, M), 256, GEMM_SMEM>>>(hx, CCH, co_wh, co_b, x,
                                                 out, nullptr, CCH, M, CCH, CCH);
}